// round 13
// baseline (speedup 1.0000x reference)
#include <cuda_runtime.h>
#include <cuda_bf16.h>
#include <math.h>
#include <stdint.h>

#define BB   8
#define NN   4096
#define SS   1024
#define KNBR 16
#define CIN  128
#define COUT 256
#define MROWS (BB*SS*KNBR)   /* 131072 */
#define BSR   (BB*SS)        /* 8192  */
#define NPTS  (BB*NN)        /* 32768 */

typedef __nv_bfloat16 bf16;

// ---------------- static device scratch (no allocs allowed) ----------------
__device__ float g_pos [(size_t)MROWS*COUT];
__device__ float g_att [(size_t)MROWS*COUT];
__device__ bf16  g_a1h [(size_t)MROWS*COUT];
__device__ bf16  g_a1l [(size_t)MROWS*COUT];
__device__ bf16  g_x1h [(size_t)MROWS*COUT];   // h1 then h2
__device__ bf16  g_x1l [(size_t)MROWS*COUT];
__device__ bf16  g_ph  [(size_t)NPTS*CIN];
__device__ bf16  g_pl  [(size_t)NPTS*CIN];
__device__ float g_kall[(size_t)NPTS*COUT];
__device__ float g_vall[(size_t)NPTS*COUT];
__device__ float g_q   [(size_t)BSR*COUT];
__device__ bf16  g_r0h [(size_t)BSR*COUT];
__device__ bf16  g_r0l [(size_t)BSR*COUT];
__device__ float g_res1[(size_t)BSR*COUT];
__device__ int   g_fps [BSR];
__device__ int   g_knn [MROWS];
__device__ int   g_prog[BB];
__device__ int   g_kprog[BB];
__device__ int   g_cvtcnt;
__device__ float g_psum[64*COUT];
__device__ float g_psq [64*COUT];
__device__ float g_scale[COUT];
__device__ float g_shift[COUT];
// pre-split weights
__device__ bf16  g_wkh[CIN*COUT],  g_wkl[CIN*COUT];
__device__ bf16  g_wvh[CIN*COUT],  g_wvl[CIN*COUT];
__device__ bf16  g_wqh[CIN*COUT],  g_wql[CIN*COUT];
__device__ bf16  g_dw2h[COUT*COUT], g_dw2l[COUT*COUT];
__device__ bf16  g_gw1h[COUT*COUT], g_gw1l[COUT*COUT];
__device__ bf16  g_gw2h[COUT*COUT], g_gw2l[COUT*COUT];
__device__ bf16  g_lwh[COUT*COUT],  g_lwl[COUT*COUT];

// -------------------- bf16 split helper ------------------------------------
__device__ __forceinline__ void split2(float x0, float x1, uint32_t& hi, uint32_t& lo)
{
    bf16 h0 = __float2bfloat16(x0);
    bf16 h1 = __float2bfloat16(x1);
    float r0 = __fsub_rn(x0, __bfloat162float(h0));
    float r1 = __fsub_rn(x1, __bfloat162float(h1));
    bf16 l0 = __float2bfloat16(r0);
    bf16 l1 = __float2bfloat16(r1);
    hi = (uint32_t)__bfloat16_as_ushort(h0) | ((uint32_t)__bfloat16_as_ushort(h1) << 16);
    lo = (uint32_t)__bfloat16_as_ushort(l0) | ((uint32_t)__bfloat16_as_ushort(l1) << 16);
}

__device__ __forceinline__ int ld_acquire(const int* p)
{
    int v;
    asm volatile("ld.acquire.gpu.global.b32 %0, [%1];" : "=r"(v) : "l"(p));
    return v;
}

// ---------------- wide fp32 -> bf16 hi/lo conversion (8 elems/thread) -------
__device__ __forceinline__ void cvt_block_wide(const float* __restrict__ src,
                                               bf16* __restrict__ hi, bf16* __restrict__ lo,
                                               int local_bid, int tid)
{
    int e = (local_bid * 256 + tid) * 8;
    float4 a = *(const float4*)(src + e);
    float4 c = *(const float4*)(src + e + 4);
    uint32_t h0,l0,h1,l1,h2,l2,h3,l3;
    split2(a.x, a.y, h0, l0); split2(a.z, a.w, h1, l1);
    split2(c.x, c.y, h2, l2); split2(c.z, c.w, h3, l3);
    uint4 H; H.x = h0; H.y = h1; H.z = h2; H.w = h3;
    uint4 L; L.x = l0; L.y = l1; L.z = l2; L.w = l3;
    *(uint4*)&hi[e] = H;
    *(uint4*)&lo[e] = L;
}

__global__ void reset_prog_kernel()
{
    int t = threadIdx.x;
    if (t < BB) g_prog[t] = 0;
    if (t >= 32 && t < 32 + BB) g_kprog[t - 32] = 0;
    if (t == 63) g_cvtcnt = 0;
}

// ------------------------- mma helpers --------------------------------------
__device__ __forceinline__ void cp16(void* s, const void* g)
{
    unsigned sa = (unsigned)__cvta_generic_to_shared(s);
    asm volatile("cp.async.ca.shared.global [%0], [%1], 16;\n" :: "r"(sa), "l"(g));
}
#define CP_COMMIT() asm volatile("cp.async.commit_group;\n")

__device__ __forceinline__ void ldsm_x4(uint32_t* r, const void* p)
{
    uint32_t a = (uint32_t)__cvta_generic_to_shared(p);
    asm volatile("ldmatrix.sync.aligned.m8n8.x4.shared.b16 {%0,%1,%2,%3}, [%4];"
                 : "=r"(r[0]), "=r"(r[1]), "=r"(r[2]), "=r"(r[3]) : "r"(a));
}

__device__ __forceinline__ void ldsm_x4_t(uint32_t* r, const void* p)
{
    uint32_t a = (uint32_t)__cvta_generic_to_shared(p);
    asm volatile("ldmatrix.sync.aligned.m8n8.x4.trans.shared.b16 {%0,%1,%2,%3}, [%4];"
                 : "=r"(r[0]), "=r"(r[1]), "=r"(r[2]), "=r"(r[3]) : "r"(a));
}

__device__ __forceinline__ void mma16816(float* c, const uint32_t* a, const uint32_t* b)
{
    asm volatile("mma.sync.aligned.m16n8k16.row.col.f32.bf16.bf16.f32 "
                 "{%0,%1,%2,%3}, {%4,%5,%6,%7}, {%8,%9}, {%0,%1,%2,%3};"
                 : "+f"(c[0]), "+f"(c[1]), "+f"(c[2]), "+f"(c[3])
                 : "r"(a[0]), "r"(a[1]), "r"(a[2]), "r"(a[3]),
                   "r"(b[0]), "r"(b[1]));
}

// ----------------------- shared GEMM mainloop macro -------------------------
// Block tile 256x64, 8 warps as 4(wm) x 2(wn), warp tile 64x32, 3-stage ring.
#define KCH    16
#define NSTG   3
#define ASTR2  24
#define BSTR2  72
#define AS_BYTES  (NSTG*2*256*ASTR2*2)            /* 73728 */
#define BS_BYTES  (NSTG*2*KCH*BSTR2*2)            /* 13824 */
#define TG_SMEM   (AS_BYTES + BS_BYTES + 1024)    /* 88576 */

#define GEMM_MAINLOOP(AHI, ALO, ROWMAP, WHI, WLO)                               \
    extern __shared__ char smraw[];                                            \
    typedef bf16 (*AsT)[2][256][ASTR2];                                        \
    typedef bf16 (*BsT)[2][KCH][BSTR2];                                        \
    AsT As = (AsT)smraw;                                                       \
    BsT Bs = (BsT)(smraw + AS_BYTES);                                          \
    int* rmap = (int*)(smraw + AS_BYTES + BS_BYTES);                           \
    rmap[tid] = (ROWMAP) ? __ldcg((ROWMAP) + m0 + tid) : (m0 + tid);           \
    __syncthreads();                                                           \
    const bf16* aSrcH = (AHI) + (size_t)rmap[tid] * Kd;                        \
    const bf16* aSrcL = (ALO) + (size_t)rmap[tid] * Kd;                        \
    const int bpl = tid >> 7;                                                  \
    const int bk  = (tid >> 3) & 15;                                           \
    const int bch = (tid & 7) * 8;                                             \
    const bf16* bSrc = (bpl ? (WLO) : (WHI)) + (size_t)bk * COUT + n0 + bch;   \
    const int lane = tid & 31;                                                 \
    const int wm = (tid >> 5) >> 1;                                            \
    const int wn = (tid >> 5) & 1;                                             \
    const int aFrow = wm * 64 + (lane & 15);                                   \
    const int aFk   = (lane >> 4) * 8;                                         \
    const int bFk   = (lane & 7) + ((lane >> 3) & 1) * 8;                      \
    const int bFn   = (lane >> 4) * 8;                                         \
    float acc[4][4][4];                                                        \
    _Pragma("unroll")                                                          \
    for (int i = 0; i < 4; i++)                                                \
        _Pragma("unroll")                                                      \
        for (int j = 0; j < 4; j++)                                            \
            _Pragma("unroll")                                                  \
            for (int l = 0; l < 4; l++) acc[i][j][l] = 0.0f;                   \
    const int nk = Kd >> 4;                                                    \
    _Pragma("unroll")                                                          \
    for (int s = 0; s < NSTG - 1; s++) {                                       \
        if (s < nk) {                                                          \
            int k0 = s * KCH;                                                  \
            cp16(&As[s][0][tid][0], aSrcH + k0);                               \
            cp16(&As[s][0][tid][8], aSrcH + k0 + 8);                           \
            cp16(&As[s][1][tid][0], aSrcL + k0);                               \
            cp16(&As[s][1][tid][8], aSrcL + k0 + 8);                           \
            cp16(&Bs[s][bpl][bk][bch], bSrc + (size_t)k0 * COUT);              \
        }                                                                      \
        CP_COMMIT();                                                           \
    }                                                                          \
    int cur = 0;                                                               \
    for (int t = 0; t < nk; t++) {                                             \
        if (t + NSTG - 1 < nk) {                                               \
            asm volatile("cp.async.wait_group 1;\n" ::: "memory");             \
        } else {                                                               \
            asm volatile("cp.async.wait_group 0;\n" ::: "memory");             \
        }                                                                      \
        __syncthreads();                                                       \
        if (t + NSTG - 1 < nk) {                                               \
            int stg = cur + NSTG - 1; if (stg >= NSTG) stg -= NSTG;            \
            const int k0  = (t + NSTG - 1) * KCH;                              \
            cp16(&As[stg][0][tid][0], aSrcH + k0);                             \
            cp16(&As[stg][0][tid][8], aSrcH + k0 + 8);                         \
            cp16(&As[stg][1][tid][0], aSrcL + k0);                             \
            cp16(&As[stg][1][tid][8], aSrcL + k0 + 8);                         \
            cp16(&Bs[stg][bpl][bk][bch], bSrc + (size_t)k0 * COUT);            \
            CP_COMMIT();                                                       \
        }                                                                      \
        uint32_t bh[4][2], bl[4][2];                                           \
        _Pragma("unroll")                                                      \
        for (int g = 0; g < 2; g++) {                                          \
            uint32_t tmp[4];                                                   \
            ldsm_x4_t(tmp, &Bs[cur][0][bFk][wn*32 + g*16 + bFn]);              \
            bh[g*2][0]   = tmp[0]; bh[g*2][1]   = tmp[1];                      \
            bh[g*2+1][0] = tmp[2]; bh[g*2+1][1] = tmp[3];                      \
            ldsm_x4_t(tmp, &Bs[cur][1][bFk][wn*32 + g*16 + bFn]);              \
            bl[g*2][0]   = tmp[0]; bl[g*2][1]   = tmp[1];                      \
            bl[g*2+1][0] = tmp[2]; bl[g*2+1][1] = tmp[3];                      \
        }                                                                      \
        _Pragma("unroll")                                                      \
        for (int mt = 0; mt < 4; mt++) {                                       \
            uint32_t ah[4], al[4];                                             \
            ldsm_x4(ah, &As[cur][0][aFrow + mt*16][aFk]);                      \
            ldsm_x4(al, &As[cur][1][aFrow + mt*16][aFk]);                      \
            _Pragma("unroll")                                                  \
            for (int nt = 0; nt < 4; nt++) {                                   \
                mma16816(acc[mt][nt], ah, bh[nt]);                             \
                mma16816(acc[mt][nt], al, bh[nt]);                             \
                mma16816(acc[mt][nt], ah, bl[nt]);                             \
            }                                                                  \
        }                                                                      \
        cur++; if (cur == NSTG) cur = 0;                                       \
    }

// ------ FUSED kernel block ranges -------------------------------------------
#define CVT_PTS_B    (NPTS*CIN/2048)          /* 2048 */
#define CVT_WSM_B    (CIN*COUT/2048)          /* 16   */
#define CVT_WBG_B    (COUT*COUT/2048)         /* 32   */
#define CVT_PRE_TOT  (CVT_PTS_B + 2*CVT_WSM_B)            /* 2080 */
#define KV_BLOCKS    (8 * (NPTS/256))                     /* 1024 */
#define CVT_POST_TOT (CVT_WSM_B + 4*CVT_WBG_B)            /* 144  */
#define KNN_BLOCKS   (BSR/8)                              /* 1024 */
#define Q_BLOCKS     (4 * (BSR/256))                      /* 128  */
#define H1_BLOCKS    (MROWS/128)                          /* 1024 */

#define B_CVTPRE   8
#define B_KV       (B_CVTPRE + CVT_PRE_TOT)
#define B_CVTPOST  (B_KV + KV_BLOCKS)
#define B_KNN      (B_CVTPOST + CVT_POST_TOT)
#define B_Q        (B_KNN + KNN_BLOCKS)
#define B_H1       (B_Q + Q_BLOCKS)
#define FUSED_GRID (B_H1 + H1_BLOCKS)

__global__ __launch_bounds__(256, 2) void fused_all(
    const float* __restrict__ xyz, float* __restrict__ newxyz,
    const float* __restrict__ points,
    const float* __restrict__ wk, const float* __restrict__ wv,
    const float* __restrict__ wq, const float* __restrict__ dw2,
    const float* __restrict__ gw1, const float* __restrict__ gw2,
    const float* __restrict__ lw,
    const float* __restrict__ dw1, const float* __restrict__ db1)
{
    const int bid = blockIdx.x;
    const int tid = threadIdx.x;

    if (bid < 8) {
        // ------------------------- FPS -------------------------------------
        extern __shared__ char smtop[];
        float* sx = (float*)smtop;
        float* sy = sx + NN;
        float* sz = sy + NN;
        unsigned long long* swk = (unsigned long long*)(smtop + 3*NN*4); // [2][8]

        int b = bid;
        int lane = tid & 31, wid = tid >> 5;
        const float* base = xyz + (size_t)b * NN * 3;

        for (int i = tid; i < NN; i += 256) {
            sx[i] = base[i*3+0];
            sy[i] = base[i*3+1];
            sz[i] = base[i*3+2];
        }
        __syncthreads();

        float px[16], py[16], pz[16], dist[16];
#pragma unroll
        for (int j = 0; j < 16; j++) {
            int i = tid * 16 + j;
            px[j] = sx[i]; py[j] = sy[i]; pz[j] = sz[i];
            dist[j] = 1e10f;
        }

        int far = 0;
        for (int s = 0; s < SS; s++) {
            float cx = sx[far], cy = sy[far], cz = sz[far];
            if (tid == 0) {
                g_fps[b*SS + s] = b*NN + far;
                newxyz[((size_t)b*SS + s)*3 + 0] = cx;
                newxyz[((size_t)b*SS + s)*3 + 1] = cy;
                newxyz[((size_t)b*SS + s)*3 + 2] = cz;
                if ((s & 31) == 31) {
                    __threadfence();
                    atomicExch(&g_prog[b], s + 1);
                }
            }
#pragma unroll
            for (int j = 0; j < 16; j++) {
                float dx = __fsub_rn(px[j], cx);
                float dy = __fsub_rn(py[j], cy);
                float dz = __fsub_rn(pz[j], cz);
                float d  = __fadd_rn(__fadd_rn(__fmul_rn(dx,dx), __fmul_rn(dy,dy)),
                                     __fmul_rn(dz,dz));
                dist[j] = fminf(dist[j], d);
            }
            float m8[8];
#pragma unroll
            for (int j = 0; j < 8; j++) m8[j] = fmaxf(dist[j], dist[j+8]);
#pragma unroll
            for (int j = 0; j < 4; j++) m8[j] = fmaxf(m8[j], m8[j+4]);
            float bv = fmaxf(fmaxf(m8[0], m8[1]), fmaxf(m8[2], m8[3]));
            unsigned match = 0;
#pragma unroll
            for (int j = 0; j < 16; j++) match |= (dist[j] == bv) ? (1u << j) : 0u;
            int bi = tid*16 + (__ffs(match) - 1);

            unsigned key  = __float_as_uint(bv);
            unsigned wmax = __reduce_max_sync(0xffffffffu, key);
            unsigned ball = __ballot_sync(0xffffffffu, key == wmax);
            int src  = __ffs(ball) - 1;
            int wbi  = __shfl_sync(0xffffffffu, bi, src);
            if (lane == 0)
                swk[(s & 1)*8 + wid] = ((unsigned long long)wmax << 32)
                                     | (unsigned)(NN - 1 - wbi);
            __syncthreads();
            unsigned long long best = swk[(s & 1)*8 + 0];
#pragma unroll
            for (int w = 1; w < 8; w++) {
                unsigned long long c = swk[(s & 1)*8 + w];
                if (c > best) best = c;
            }
            far = NN - 1 - (int)(best & 0xffffffffu);
        }
        return;
    }

    if (bid < B_KV) {
        // ------------- pre-cvts (points, wk, wv) + release counter ----------
        int cb = bid - B_CVTPRE;
        if (cb < CVT_PTS_B)               cvt_block_wide(points, g_ph, g_pl, cb, tid);
        else if (cb < CVT_PTS_B + CVT_WSM_B)
            cvt_block_wide(wk, g_wkh, g_wkl, cb - CVT_PTS_B, tid);
        else
            cvt_block_wide(wv, g_wvh, g_wvl, cb - CVT_PTS_B - CVT_WSM_B, tid);
        __syncthreads();
        if (tid == 0) { __threadfence(); atomicAdd(&g_cvtcnt, 1); }
        return;
    }

    if (bid < B_CVTPOST) {
        // -------------------- merged k/v GEMM (polls cvtcnt) ----------------
        if (tid == 0) { while (ld_acquire(&g_cvtcnt) < CVT_PRE_TOT) { } }
        const int idx = bid - B_KV;
        const int bx  = idx & 7;           // 0..3 -> wk, 4..7 -> wv
        const int m0  = (idx >> 3) * 256;
        const int n0  = (bx & 3) * 64;
        const bf16* WhiS = (bx < 4) ? g_wkh : g_wvh;
        const bf16* WloS = (bx < 4) ? g_wkl : g_wvl;
        float* CS = (bx < 4) ? g_kall : g_vall;
        const int Kd = CIN;
        const int* rowmap = nullptr;

        GEMM_MAINLOOP(g_ph, g_pl, rowmap, WhiS, WloS)

        const int quad = lane >> 2, tq = lane & 3;
#pragma unroll
        for (int mt = 0; mt < 4; mt++) {
            int r0 = m0 + wm*64 + mt*16 + quad;
            int r1 = r0 + 8;
#pragma unroll
            for (int nt = 0; nt < 4; nt++) {
                int col = n0 + wn*32 + nt*8 + tq*2;
                *(float2*)(CS + (size_t)r0*COUT + col) =
                    make_float2(acc[mt][nt][0], acc[mt][nt][1]);
                *(float2*)(CS + (size_t)r1*COUT + col) =
                    make_float2(acc[mt][nt][2], acc[mt][nt][3]);
            }
        }
        return;
    }

    if (bid < B_KNN) {
        // ------------------------ post weight cvts ---------------------------
        int cb = bid - B_CVTPOST;
        if (cb < CVT_WSM_B) { cvt_block_wide(wq, g_wqh, g_wql, cb, tid); return; }
        cb -= CVT_WSM_B;
        if (cb < CVT_WBG_B) { cvt_block_wide(dw2, g_dw2h, g_dw2l, cb, tid); return; }
        cb -= CVT_WBG_B;
        if (cb < CVT_WBG_B) { cvt_block_wide(gw1, g_gw1h, g_gw1l, cb, tid); return; }
        cb -= CVT_WBG_B;
        if (cb < CVT_WBG_B) { cvt_block_wide(gw2, g_gw2h, g_gw2l, cb, tid); return; }
        cb -= CVT_WBG_B;
        cvt_block_wide(lw, g_lwh, g_lwl, cb, tid);
        return;
    }

    if (bid < B_Q) {
        // ------------- KNN (polls FPS progress, commits kprog) ---------------
        extern __shared__ char smk[];
        float (*smd)[512] = (float(*)[512])smk;
        int   (*smi)[512] = (int(*)[512])(smk + 8*512*4);

        const int kb   = bid - B_KNN;
        const int lane = tid & 31;
        const int wloc = tid >> 5;
        const int b    = kb & 7;
        const int s0   = (kb >> 3) * 8;
        const int s    = s0 + wloc;
        const int warp = b * SS + s;
        const float* base = xyz + (size_t)b * NN * 3;

        if (lane == 0) {
            while (ld_acquire(&g_prog[b]) <= s) { }
        }
        __syncwarp();

        float nx = __ldcg(newxyz + (size_t)warp*3 + 0);
        float ny = __ldcg(newxyz + (size_t)warp*3 + 1);
        float nz = __ldcg(newxyz + (size_t)warp*3 + 2);
        float ns = fmaf(nz, nz, fmaf(ny, ny, __fmul_rn(nx, nx)));

        float v[16]; int id[16];
#pragma unroll
        for (int t = 0; t < 16; t++) { v[t] = 3.4e38f; id[t] = 0x7fffffff; }

        for (int j = lane; j < NN; j += 32) {
            float x = base[j*3+0], y = base[j*3+1], z = base[j*3+2];
            float dot = fmaf(z, nz, fmaf(y, ny, __fmul_rn(x, nx)));
            float nq  = fmaf(z, z,  fmaf(y, y,  __fmul_rn(x, x)));
            float d   = __fadd_rn(__fsub_rn(ns, __fmul_rn(2.0f, dot)), nq);
            if (d < v[15]) {
                v[15] = d; id[15] = j;
#pragma unroll
                for (int t = 15; t > 0; t--) {
                    if (v[t] < v[t-1] || (v[t] == v[t-1] && id[t] < id[t-1])) {
                        float tv = v[t]; v[t] = v[t-1]; v[t-1] = tv;
                        int   ti = id[t]; id[t] = id[t-1]; id[t-1] = ti;
                    } else break;
                }
            }
        }

#pragma unroll
        for (int t = 0; t < 16; t++) {
            smd[wloc][lane*16 + t] = v[t];
            smi[wloc][lane*16 + t] = id[t];
        }
        __syncwarp();

        int p = 0;
        for (int t = 0; t < 16; t++) {
            float cv = (p < 16) ? smd[wloc][lane*16 + p] : 3.4e38f;
            int   ci = (p < 16) ? smi[wloc][lane*16 + p] : 0x7fffffff;
            float mv = cv; int mi = ci;
#pragma unroll
            for (int off = 16; off; off >>= 1) {
                float ov = __shfl_xor_sync(0xffffffffu, mv, off);
                int   oi = __shfl_xor_sync(0xffffffffu, mi, off);
                if (ov < mv || (ov == mv && oi < mi)) { mv = ov; mi = oi; }
            }
            if (cv == mv && ci == mi) p++;
            if (lane == 0) g_knn[(size_t)warp*16 + t] = b*NN + mi;
            __syncwarp();
        }

        // in-order commit of per-batch KNN progress
        __syncthreads();
        if (tid == 0) {
            while (ld_acquire(&g_kprog[b]) != s0) { }
            __threadfence();
            atomicExch(&g_kprog[b], s0 + 8);
        }
        return;
    }

    if (bid < B_H1) {
        // -------------- q GEMM = gather(points, fps) @ wq (polls prog) -------
        const int idx = bid - B_Q;
        const int n0  = (idx & 3) * 64;
        const int m0  = (idx >> 2) * 256;
        const int b   = m0 >> 10;
        const int s_need = (m0 & 1023) + 256;
        if (tid == 0) { while (ld_acquire(&g_prog[b]) < s_need) { } }
        const int Kd = CIN;
        const int* fps_ptr = g_fps;

        GEMM_MAINLOOP(g_ph, g_pl, fps_ptr, g_wqh, g_wql)

        const int quad = lane >> 2, tq = lane & 3;
#pragma unroll
        for (int mt = 0; mt < 4; mt++) {
            int r0 = m0 + wm*64 + mt*16 + quad;
            int r1 = r0 + 8;
#pragma unroll
            for (int nt = 0; nt < 4; nt++) {
                int col = n0 + wn*32 + nt*8 + tq*2;
                *(float2*)(g_q + (size_t)r0*COUT + col) =
                    make_float2(acc[mt][nt][0], acc[mt][nt][1]);
                *(float2*)(g_q + (size_t)r1*COUT + col) =
                    make_float2(acc[mt][nt][2], acc[mt][nt][3]);
            }
        }
        return;
    }

    // ----------------- h1 pos-enc layer 1 (polls kprog) ----------------------
    {
        const int hb = bid - B_H1;           // 0..1023, rows [hb*128, +128)
        const int b  = hb >> 7;
        const int s_need = ((hb * 8) & 1023) + 8;
        if (tid == 0) { while (ld_acquire(&g_kprog[b]) < s_need) { } }
        __syncthreads();

        const int col    = (tid & 127) * 2;
        const int rowsel = tid >> 7;
        const float w0a = dw1[col],        w0b = dw1[col+1];
        const float w1a = dw1[COUT+col],   w1b = dw1[COUT+col+1];
        const float w2a = dw1[2*COUT+col], w2b = dw1[2*COUT+col+1];
        const float b0  = db1[col],        b1  = db1[col+1];

        for (int rr = 0; rr < 64; rr++) {
            int r  = hb*128 + rr*2 + rowsel;
            int g  = __ldcg(&g_knn[r]);
            int bs = r >> 4;
            float cx = __ldcg(&xyz[(size_t)g*3+0]) - __ldcg(&newxyz[(size_t)bs*3+0]);
            float cy = __ldcg(&xyz[(size_t)g*3+1]) - __ldcg(&newxyz[(size_t)bs*3+1]);
            float cz = __ldcg(&xyz[(size_t)g*3+2]) - __ldcg(&newxyz[(size_t)bs*3+2]);
            float h0 = b0, h1v = b1;
            h0  = fmaf(cx, w0a, h0);  h0  = fmaf(cy, w1a, h0);  h0  = fmaf(cz, w2a, h0);
            h1v = fmaf(cx, w0b, h1v); h1v = fmaf(cy, w1b, h1v); h1v = fmaf(cz, w2b, h1v);
            h0  = fmaxf(h0, 0.0f);
            h1v = fmaxf(h1v, 0.0f);
            uint32_t h, l;
            split2(h0, h1v, h, l);
            *(uint32_t*)&g_x1h[(size_t)r*COUT + col] = h;
            *(uint32_t*)&g_x1l[(size_t)r*COUT + col] = l;
        }
    }
}

// --------- generic GEMM (fp32 out / bf16-split out / fused a1 dual write) ---
__global__ __launch_bounds__(256, 2) void tgemm_bf(
    const bf16* __restrict__ Ahi, const bf16* __restrict__ Alo,
    const int* __restrict__ rowmap,
    const bf16* __restrict__ Whi, const bf16* __restrict__ Wlo,
    const float* __restrict__ bias, int Kd, int relu,
    float* __restrict__ C, bf16* __restrict__ Chi, bf16* __restrict__ Clo,
    const float* __restrict__ qv, const float* __restrict__ kall,
    const int* __restrict__ knn,
    bf16* __restrict__ A1hi, bf16* __restrict__ A1lo)
{
    const int tid = threadIdx.x;
    const int m0  = blockIdx.y * 256;
    const int n0  = blockIdx.x * 64;

    GEMM_MAINLOOP(Ahi, Alo, rowmap, Whi, Wlo)

    const int quad = lane >> 2, tq = lane & 3;
#pragma unroll
    for (int mt = 0; mt < 4; mt++) {
        int r0 = m0 + wm*64 + mt*16 + quad;
        int r1 = r0 + 8;
        const float *q0 = nullptr, *k0p = nullptr, *q1 = nullptr, *k1p = nullptr;
        if (A1hi) {
            q0 = qv + (size_t)(r0 >> 4) * COUT;  k0p = kall + (size_t)knn[r0] * COUT;
            q1 = qv + (size_t)(r1 >> 4) * COUT;  k1p = kall + (size_t)knn[r1] * COUT;
        }
#pragma unroll
        for (int nt = 0; nt < 4; nt++) {
            int col = n0 + wn*32 + nt*8 + tq*2;
            float o0 = acc[mt][nt][0], o1 = acc[mt][nt][1];
            float o2 = acc[mt][nt][2], o3 = acc[mt][nt][3];
            if (bias) { float bb0 = bias[col], bb1 = bias[col+1];
                        o0 += bb0; o1 += bb1; o2 += bb0; o3 += bb1; }
            if (relu) { o0 = fmaxf(o0,0.f); o1 = fmaxf(o1,0.f);
                        o2 = fmaxf(o2,0.f); o3 = fmaxf(o3,0.f); }
            if (C) {
                *(float2*)(C + (size_t)r0*COUT + col) = make_float2(o0, o1);
                *(float2*)(C + (size_t)r1*COUT + col) = make_float2(o2, o3);
            }
            if (Chi) {
                uint32_t h, l;
                split2(o0, o1, h, l);
                *(uint32_t*)&Chi[(size_t)r0*COUT + col] = h;
                *(uint32_t*)&Clo[(size_t)r0*COUT + col] = l;
                split2(o2, o3, h, l);
                *(uint32_t*)&Chi[(size_t)r1*COUT + col] = h;
                *(uint32_t*)&Clo[(size_t)r1*COUT + col] = l;
            }
            if (A1hi) {
                float w0 = __fadd_rn(__fsub_rn(q0[col],   k0p[col]),   o0);
                float w1 = __fadd_rn(__fsub_rn(q0[col+1], k0p[col+1]), o1);
                float w2 = __fadd_rn(__fsub_rn(q1[col],   k1p[col]),   o2);
                float w3 = __fadd_rn(__fsub_rn(q1[col+1], k1p[col+1]), o3);
                uint32_t h, l;
                split2(w0, w1, h, l);
                *(uint32_t*)&A1hi[(size_t)r0*COUT + col] = h;
                *(uint32_t*)&A1lo[(size_t)r0*COUT + col] = l;
                split2(w2, w3, h, l);
                *(uint32_t*)&A1hi[(size_t)r1*COUT + col] = h;
                *(uint32_t*)&A1lo[(size_t)r1*COUT + col] = l;
            }
        }
    }
}

// --------------- softmax over K axis + weighted sum (v gathered) -----------
__global__ __launch_bounds__(128) void softmax_reduce_kernel()
{
    int bs = blockIdx.x;
    int c  = threadIdx.x * 2;
    __shared__ int kn[16];
    if (threadIdx.x < 16) kn[threadIdx.x] = g_knn[bs*16 + threadIdx.x];
    __syncthreads();

    size_t base = (size_t)bs * KNBR * COUT + c;
    float a0[16], a1[16];
    float mx0 = -3.4e38f, mx1 = -3.4e38f;
#pragma unroll
    for (int i = 0; i < 16; i++) {
        a0[i] = g_att[base + (size_t)i*COUT]     * 0.0625f;
        a1[i] = g_att[base + (size_t)i*COUT + 1] * 0.0625f;
        mx0 = fmaxf(mx0, a0[i]);
        mx1 = fmaxf(mx1, a1[i]);
    }
    float s0 = 0.0f, s1 = 0.0f;
#pragma unroll
    for (int i = 0; i < 16; i++) {
        a0[i] = expf(a0[i] - mx0); s0 += a0[i];
        a1[i] = expf(a1[i] - mx1); s1 += a1[i];
    }
    float i0 = 1.0f / s0, i1 = 1.0f / s1;
    float acc0 = 0.0f, acc1 = 0.0f;
#pragma unroll
    for (int i = 0; i < 16; i++) {
        size_t vb = (size_t)kn[i]*COUT + c;
        float vp0 = g_vall[vb]     + g_pos[base + (size_t)i*COUT];
        float vp1 = g_vall[vb + 1] + g_pos[base + (size_t)i*COUT + 1];
        acc0 = fmaf(a0[i]*i0, vp0, acc0);
        acc1 = fmaf(a1[i]*i1, vp1, acc1);
    }
    uint32_t h, l;
    split2(acc0, acc1, h, l);
    *(uint32_t*)&g_r0h[(size_t)bs*COUT + c] = h;
    *(uint32_t*)&g_r0l[(size_t)bs*COUT + c] = l;
}

// ---------------------------- BatchNorm ------------------------------------
__global__ void bn_partial_kernel()
{
    int blk = blockIdx.x;
    int c   = threadIdx.x;
    float s = 0.0f, q = 0.0f;
    for (int r = blk*128; r < blk*128 + 128; r++) {
        float x = g_res1[(size_t)r*COUT + c];
        s += x; q = fmaf(x, x, q);
    }
    g_psum[blk*COUT + c] = s;
    g_psq [blk*COUT + c] = q;
}

__global__ void bn_final_kernel(const float* __restrict__ bng, const float* __restrict__ bnb)
{
    int c = threadIdx.x;
    float s = 0.0f, q = 0.0f;
    for (int i = 0; i < 64; i++) { s += g_psum[i*COUT + c]; q += g_psq[i*COUT + c]; }
    float mean = s * (1.0f/(float)BSR);
    float var  = fmaxf(q * (1.0f/(float)BSR) - mean*mean, 0.0f);
    float sc   = bng[c] * rsqrtf(var + 1e-5f);
    g_scale[c] = sc;
    g_shift[c] = bnb[c] - mean * sc;
}

__global__ void bn_apply_kernel(float* __restrict__ out)
{
    size_t e = (size_t)blockIdx.x * blockDim.x + threadIdx.x;
    int c = (int)(e & 255);
    out[e] = fmaxf(fmaf(g_res1[e], g_scale[c], g_shift[c]), 0.0f);
}

// ------------------------------ launch --------------------------------------
extern "C" void kernel_launch(void* const* d_in, const int* in_sizes, int n_in,
                              void* d_out, int out_size)
{
    const float* xyz    = (const float*)d_in[0];
    const float* points = (const float*)d_in[1];
    const float* wq     = (const float*)d_in[2];
    const float* wk     = (const float*)d_in[3];
    const float* wv     = (const float*)d_in[4];
    const float* dw1    = (const float*)d_in[5];
    const float* db1    = (const float*)d_in[6];
    const float* dw2    = (const float*)d_in[7];
    const float* db2    = (const float*)d_in[8];
    const float* gw1    = (const float*)d_in[9];
    const float* gb1    = (const float*)d_in[10];
    const float* gw2    = (const float*)d_in[11];
    const float* gb2    = (const float*)d_in[12];
    const float* lw     = (const float*)d_in[13];
    const float* lb     = (const float*)d_in[14];
    const float* bng    = (const float*)d_in[15];
    const float* bnb    = (const float*)d_in[16];

    float* out     = (float*)d_out;
    float* newxyz  = out;
    float* res_out = out + (size_t)BSR*3;

    static bool attr_set = false;
    if (!attr_set) {
        cudaFuncSetAttribute(tgemm_bf,  cudaFuncAttributeMaxDynamicSharedMemorySize, TG_SMEM);
        cudaFuncSetAttribute(fused_all, cudaFuncAttributeMaxDynamicSharedMemorySize, TG_SMEM);
        attr_set = true;
    }

#define SYM(p, s) void* p; cudaGetSymbolAddress(&p, s)
    SYM(ppos, g_pos);  SYM(patt, g_att);
    SYM(pa1h, g_a1h);  SYM(pa1l, g_a1l);
    SYM(px1h, g_x1h);  SYM(px1l, g_x1l);
    SYM(pph,  g_ph);   SYM(ppl,  g_pl);
    SYM(pk,   g_kall); SYM(pv,   g_vall);
    SYM(pq,   g_q);
    SYM(pr0h, g_r0h);  SYM(pr0l, g_r0l);
    SYM(pr1,  g_res1);
    SYM(pknn, g_knn);
    SYM(pdw2h, g_dw2h); SYM(pdw2l, g_dw2l);
    SYM(pgw1h, g_gw1h); SYM(pgw1l, g_gw1l);
    SYM(pgw2h, g_gw2h); SYM(pgw2l, g_gw2l);
    SYM(plwh, g_lwh);   SYM(plwl, g_lwl);
#undef SYM

    // 1: reset progress counters (graph-replay safe)
    reset_prog_kernel<<<1, 64>>>();
    // 2: FPS || pre-cvts || kv GEMM || post-cvts || KNN || q GEMM || h1
    fused_all<<<FUSED_GRID, 256, TG_SMEM>>>(xyz, newxyz, points, wk, wv,
                                            wq, dw2, gw1, gw2, lw, dw1, db1);
    // 3: pos = h1 @ dw2 + db2 (fp32) + fused a1 = q - k_gather + pos (bf16 split)
    tgemm_bf<<<dim3(4, MROWS/256), 256, TG_SMEM>>>(
        (const bf16*)px1h, (const bf16*)px1l, nullptr,
        (const bf16*)pdw2h, (const bf16*)pdw2l, db2, COUT, 0,
        (float*)ppos, nullptr, nullptr,
        (const float*)pq, (const float*)pk, (const int*)pknn,
        (bf16*)pa1h, (bf16*)pa1l);
    // 4: h2 = relu(a1 @ gw1 + gb1) -> x1 (bf16 split)
    tgemm_bf<<<dim3(4, MROWS/256), 256, TG_SMEM>>>(
        (const bf16*)pa1h, (const bf16*)pa1l, nullptr,
        (const bf16*)pgw1h, (const bf16*)pgw1l, gb1, COUT, 1,
        nullptr, (bf16*)px1h, (bf16*)px1l,
        nullptr, nullptr, nullptr, nullptr, nullptr);
    // 5: att = h2 @ gw2 + gb2 -> fp32
    tgemm_bf<<<dim3(4, MROWS/256), 256, TG_SMEM>>>(
        (const bf16*)px1h, (const bf16*)px1l, nullptr,
        (const bf16*)pgw2h, (const bf16*)pgw2l, gb2, COUT, 0,
        (float*)patt, nullptr, nullptr,
        nullptr, nullptr, nullptr, nullptr, nullptr);
    // 6: softmax over K + weighted sum -> r0 (bf16 split)
    softmax_reduce_kernel<<<BSR, 128>>>();
    // 7: res1 = res0 @ lw + lb
    tgemm_bf<<<dim3(4, BSR/256), 256, TG_SMEM>>>(
        (const bf16*)pr0h, (const bf16*)pr0l, nullptr,
        (const bf16*)plwh, (const bf16*)plwl, lb, COUT, 0,
        (float*)pr1, nullptr, nullptr,
        nullptr, nullptr, nullptr, nullptr, nullptr);
    // 8: BatchNorm (training stats) + ReLU -> output
    bn_partial_kernel<<<64, 256>>>();
    bn_final_kernel<<<1, 256>>>(bng, bnb);
    bn_apply_kernel<<<(BSR*COUT)/1024, 1024>>>(res_out);
}

// round 14
// speedup vs baseline: 1.1112x; 1.1112x over previous
#include <cuda_runtime.h>
#include <cuda_bf16.h>
#include <math.h>
#include <stdint.h>

#define BB   8
#define NN   4096
#define SS   1024
#define KNBR 16
#define CIN  128
#define COUT 256
#define MROWS (BB*SS*KNBR)   /* 131072 */
#define BSR   (BB*SS)        /* 8192  */
#define NPTS  (BB*NN)        /* 32768 */

typedef __nv_bfloat16 bf16;

// ---------------- static device scratch (no allocs allowed) ----------------
__device__ float g_pos [(size_t)MROWS*COUT];
__device__ bf16  g_a1h [(size_t)MROWS*COUT];
__device__ bf16  g_a1l [(size_t)MROWS*COUT];
__device__ bf16  g_x1h [(size_t)MROWS*COUT];   // h1 then h2
__device__ bf16  g_x1l [(size_t)MROWS*COUT];
__device__ bf16  g_ph  [(size_t)NPTS*CIN];
__device__ bf16  g_pl  [(size_t)NPTS*CIN];
__device__ float g_kall[(size_t)NPTS*COUT];
__device__ float g_vall[(size_t)NPTS*COUT];
__device__ float g_q   [(size_t)BSR*COUT];
__device__ bf16  g_r0h [(size_t)BSR*COUT];
__device__ bf16  g_r0l [(size_t)BSR*COUT];
__device__ float g_res1[(size_t)BSR*COUT];
__device__ int   g_fps [BSR];
__device__ int   g_knn [MROWS];
__device__ int   g_prog[BB];
__device__ int   g_kprog[BB];
__device__ int   g_cvtcnt;
__device__ float g_psum[64*COUT];
__device__ float g_psq [64*COUT];
__device__ float g_scale[COUT];
__device__ float g_shift[COUT];
// pre-split weights
__device__ bf16  g_wkh[CIN*COUT],  g_wkl[CIN*COUT];
__device__ bf16  g_wvh[CIN*COUT],  g_wvl[CIN*COUT];
__device__ bf16  g_wqh[CIN*COUT],  g_wql[CIN*COUT];
__device__ bf16  g_dw2h[COUT*COUT], g_dw2l[COUT*COUT];
__device__ bf16  g_gw1h[COUT*COUT], g_gw1l[COUT*COUT];
__device__ bf16  g_gw2h[COUT*COUT], g_gw2l[COUT*COUT];
__device__ bf16  g_lwh[COUT*COUT],  g_lwl[COUT*COUT];

// -------------------- bf16 split helper ------------------------------------
__device__ __forceinline__ void split2(float x0, float x1, uint32_t& hi, uint32_t& lo)
{
    bf16 h0 = __float2bfloat16(x0);
    bf16 h1 = __float2bfloat16(x1);
    float r0 = __fsub_rn(x0, __bfloat162float(h0));
    float r1 = __fsub_rn(x1, __bfloat162float(h1));
    bf16 l0 = __float2bfloat16(r0);
    bf16 l1 = __float2bfloat16(r1);
    hi = (uint32_t)__bfloat16_as_ushort(h0) | ((uint32_t)__bfloat16_as_ushort(h1) << 16);
    lo = (uint32_t)__bfloat16_as_ushort(l0) | ((uint32_t)__bfloat16_as_ushort(l1) << 16);
}

__device__ __forceinline__ int ld_acquire(const int* p)
{
    int v;
    asm volatile("ld.acquire.gpu.global.b32 %0, [%1];" : "=r"(v) : "l"(p));
    return v;
}

// ---------------- wide fp32 -> bf16 hi/lo conversion (8 elems/thread) -------
__device__ __forceinline__ void cvt_block_wide(const float* __restrict__ src,
                                               bf16* __restrict__ hi, bf16* __restrict__ lo,
                                               int local_bid, int tid)
{
    int e = (local_bid * 256 + tid) * 8;
    float4 a = *(const float4*)(src + e);
    float4 c = *(const float4*)(src + e + 4);
    uint32_t h0,l0,h1,l1,h2,l2,h3,l3;
    split2(a.x, a.y, h0, l0); split2(a.z, a.w, h1, l1);
    split2(c.x, c.y, h2, l2); split2(c.z, c.w, h3, l3);
    uint4 H; H.x = h0; H.y = h1; H.z = h2; H.w = h3;
    uint4 L; L.x = l0; L.y = l1; L.z = l2; L.w = l3;
    *(uint4*)&hi[e] = H;
    *(uint4*)&lo[e] = L;
}

__global__ void reset_prog_kernel()
{
    int t = threadIdx.x;
    if (t < BB) g_prog[t] = 0;
    if (t >= 32 && t < 32 + BB) g_kprog[t - 32] = 0;
    if (t == 63) g_cvtcnt = 0;
}

// ------------------------- mma helpers --------------------------------------
__device__ __forceinline__ void cp16(void* s, const void* g)
{
    unsigned sa = (unsigned)__cvta_generic_to_shared(s);
    asm volatile("cp.async.ca.shared.global [%0], [%1], 16;\n" :: "r"(sa), "l"(g));
}
#define CP_COMMIT() asm volatile("cp.async.commit_group;\n")

__device__ __forceinline__ void ldsm_x4(uint32_t* r, const void* p)
{
    uint32_t a = (uint32_t)__cvta_generic_to_shared(p);
    asm volatile("ldmatrix.sync.aligned.m8n8.x4.shared.b16 {%0,%1,%2,%3}, [%4];"
                 : "=r"(r[0]), "=r"(r[1]), "=r"(r[2]), "=r"(r[3]) : "r"(a));
}

__device__ __forceinline__ void ldsm_x4_t(uint32_t* r, const void* p)
{
    uint32_t a = (uint32_t)__cvta_generic_to_shared(p);
    asm volatile("ldmatrix.sync.aligned.m8n8.x4.trans.shared.b16 {%0,%1,%2,%3}, [%4];"
                 : "=r"(r[0]), "=r"(r[1]), "=r"(r[2]), "=r"(r[3]) : "r"(a));
}

__device__ __forceinline__ void mma16816(float* c, const uint32_t* a, const uint32_t* b)
{
    asm volatile("mma.sync.aligned.m16n8k16.row.col.f32.bf16.bf16.f32 "
                 "{%0,%1,%2,%3}, {%4,%5,%6,%7}, {%8,%9}, {%0,%1,%2,%3};"
                 : "+f"(c[0]), "+f"(c[1]), "+f"(c[2]), "+f"(c[3])
                 : "r"(a[0]), "r"(a[1]), "r"(a[2]), "r"(a[3]),
                   "r"(b[0]), "r"(b[1]));
}

// ----------------------- shared GEMM mainloop macro (R12: 128x64, 4-stage) --
#define KCH    16
#define NSTG   4
#define ASTR2  24
#define BSTR2  72
#define AS_BYTES  (NSTG*2*128*ASTR2*2)
#define BS_BYTES  (NSTG*2*KCH*BSTR2*2)
#define TG_SMEM   (AS_BYTES + BS_BYTES + 512)

#define GEMM_MAINLOOP(AHI, ALO, ROWMAP, WHI, WLO)                               \
    extern __shared__ char smraw[];                                            \
    typedef bf16 (*AsT)[2][128][ASTR2];                                        \
    typedef bf16 (*BsT)[2][KCH][BSTR2];                                        \
    AsT As = (AsT)smraw;                                                       \
    BsT Bs = (BsT)(smraw + AS_BYTES);                                          \
    int* rmap = (int*)(smraw + AS_BYTES + BS_BYTES);                           \
    if (tid < 128) rmap[tid] = (ROWMAP) ? __ldcg((ROWMAP) + m0 + tid) : (m0 + tid); \
    __syncthreads();                                                           \
    const int arow = tid >> 1;                                                 \
    const int ach  = (tid & 1) * 8;                                            \
    const bf16* aSrcH = (AHI) + (size_t)rmap[arow] * Kd + ach;                 \
    const bf16* aSrcL = (ALO) + (size_t)rmap[arow] * Kd + ach;                 \
    const int bpl = tid >> 7;                                                  \
    const int bk  = (tid >> 3) & 15;                                           \
    const int bch = (tid & 7) * 8;                                             \
    const bf16* bSrc = (bpl ? (WLO) : (WHI)) + (size_t)bk * COUT + n0 + bch;   \
    const int lane = tid & 31;                                                 \
    const int wm = (tid >> 5) >> 1;                                            \
    const int wn = (tid >> 5) & 1;                                             \
    const int aFrow = wm * 32 + (lane & 15);                                   \
    const int aFk   = (lane >> 4) * 8;                                         \
    const int bFk   = (lane & 7) + ((lane >> 3) & 1) * 8;                      \
    const int bFn   = (lane >> 4) * 8;                                         \
    float acc[2][4][4];                                                        \
    _Pragma("unroll")                                                          \
    for (int i = 0; i < 2; i++)                                                \
        _Pragma("unroll")                                                      \
        for (int j = 0; j < 4; j++)                                            \
            _Pragma("unroll")                                                  \
            for (int l = 0; l < 4; l++) acc[i][j][l] = 0.0f;                   \
    const int nk = Kd >> 4;                                                    \
    _Pragma("unroll")                                                          \
    for (int s = 0; s < NSTG - 1; s++) {                                       \
        if (s < nk) {                                                          \
            int k0 = s * KCH;                                                  \
            cp16(&As[s][0][arow][ach], aSrcH + k0);                            \
            cp16(&As[s][1][arow][ach], aSrcL + k0);                            \
            cp16(&Bs[s][bpl][bk][bch], bSrc + (size_t)k0 * COUT);              \
        }                                                                      \
        CP_COMMIT();                                                           \
    }                                                                          \
    for (int t = 0; t < nk; t++) {                                             \
        const int cur = t & (NSTG - 1);                                        \
        if (t + NSTG - 1 < nk) {                                               \
            asm volatile("cp.async.wait_group 2;\n" ::: "memory");             \
        } else {                                                               \
            asm volatile("cp.async.wait_group 0;\n" ::: "memory");             \
        }                                                                      \
        __syncthreads();                                                       \
        if (t + NSTG - 1 < nk) {                                               \
            const int stg = (t + NSTG - 1) & (NSTG - 1);                       \
            const int k0  = (t + NSTG - 1) * KCH;                              \
            cp16(&As[stg][0][arow][ach], aSrcH + k0);                          \
            cp16(&As[stg][1][arow][ach], aSrcL + k0);                          \
            cp16(&Bs[stg][bpl][bk][bch], bSrc + (size_t)k0 * COUT);            \
            CP_COMMIT();                                                       \
        }                                                                      \
        uint32_t ah[2][4], al[2][4], bh[4][2], bl[4][2];                       \
        _Pragma("unroll")                                                      \
        for (int mt = 0; mt < 2; mt++) {                                       \
            ldsm_x4(ah[mt], &As[cur][0][aFrow + mt*16][aFk]);                  \
            ldsm_x4(al[mt], &As[cur][1][aFrow + mt*16][aFk]);                  \
        }                                                                      \
        _Pragma("unroll")                                                      \
        for (int g = 0; g < 2; g++) {                                          \
            uint32_t tmp[4];                                                   \
            ldsm_x4_t(tmp, &Bs[cur][0][bFk][wn*32 + g*16 + bFn]);              \
            bh[g*2][0]   = tmp[0]; bh[g*2][1]   = tmp[1];                      \
            bh[g*2+1][0] = tmp[2]; bh[g*2+1][1] = tmp[3];                      \
            ldsm_x4_t(tmp, &Bs[cur][1][bFk][wn*32 + g*16 + bFn]);              \
            bl[g*2][0]   = tmp[0]; bl[g*2][1]   = tmp[1];                      \
            bl[g*2+1][0] = tmp[2]; bl[g*2+1][1] = tmp[3];                      \
        }                                                                      \
        _Pragma("unroll")                                                      \
        for (int mt = 0; mt < 2; mt++)                                         \
            _Pragma("unroll")                                                  \
            for (int nt = 0; nt < 4; nt++) {                                   \
                mma16816(acc[mt][nt], ah[mt], bh[nt]);                         \
                mma16816(acc[mt][nt], al[mt], bh[nt]);                         \
                mma16816(acc[mt][nt], ah[mt], bl[nt]);                         \
            }                                                                  \
    }

// ------ FUSED kernel block ranges -------------------------------------------
#define CVT_PTS_B    (NPTS*CIN/2048)          /* 2048 */
#define CVT_WSM_B    (CIN*COUT/2048)          /* 16   */
#define CVT_WBG_B    (COUT*COUT/2048)         /* 32   */
#define CVT_PRE_TOT  (CVT_PTS_B + 2*CVT_WSM_B)            /* 2080 */
#define KV_BLOCKS    (8 * (NPTS/128))                     /* 2048 */
#define CVT_POST_TOT (CVT_WSM_B + 4*CVT_WBG_B)            /* 144  */
#define KNN_BLOCKS   (BSR/8)                              /* 1024 */
#define Q_BLOCKS     (4 * (BSR/128))                      /* 256  */
#define H1_BLOCKS    (MROWS/128)                          /* 1024 */

#define B_CVTPRE   8
#define B_KV       (B_CVTPRE + CVT_PRE_TOT)
#define B_CVTPOST  (B_KV + KV_BLOCKS)
#define B_KNN      (B_CVTPOST + CVT_POST_TOT)
#define B_Q        (B_KNN + KNN_BLOCKS)
#define B_H1       (B_Q + Q_BLOCKS)
#define FUSED_GRID (B_H1 + H1_BLOCKS)

__global__ __launch_bounds__(256, 2) void fused_all(
    const float* __restrict__ xyz, float* __restrict__ newxyz,
    const float* __restrict__ points,
    const float* __restrict__ wk, const float* __restrict__ wv,
    const float* __restrict__ wq, const float* __restrict__ dw2,
    const float* __restrict__ gw1, const float* __restrict__ gw2,
    const float* __restrict__ lw,
    const float* __restrict__ dw1, const float* __restrict__ db1)
{
    const int bid = blockIdx.x;
    const int tid = threadIdx.x;

    if (bid < 8) {
        // ------------------------- FPS -------------------------------------
        extern __shared__ char smtop[];
        float* sx = (float*)smtop;
        float* sy = sx + NN;
        float* sz = sy + NN;
        unsigned long long* swk = (unsigned long long*)(smtop + 3*NN*4); // [2][8]

        int b = bid;
        int lane = tid & 31, wid = tid >> 5;
        const float* base = xyz + (size_t)b * NN * 3;

        for (int i = tid; i < NN; i += 256) {
            sx[i] = base[i*3+0];
            sy[i] = base[i*3+1];
            sz[i] = base[i*3+2];
        }
        __syncthreads();

        float px[16], py[16], pz[16], dist[16];
#pragma unroll
        for (int j = 0; j < 16; j++) {
            int i = tid * 16 + j;
            px[j] = sx[i]; py[j] = sy[i]; pz[j] = sz[i];
            dist[j] = 1e10f;
        }

        int far = 0;
        for (int s = 0; s < SS; s++) {
            float cx = sx[far], cy = sy[far], cz = sz[far];
            if (tid == 0) {
                g_fps[b*SS + s] = b*NN + far;
                newxyz[((size_t)b*SS + s)*3 + 0] = cx;
                newxyz[((size_t)b*SS + s)*3 + 1] = cy;
                newxyz[((size_t)b*SS + s)*3 + 2] = cz;
                if ((s & 31) == 31) {
                    __threadfence();
                    atomicExch(&g_prog[b], s + 1);
                }
            }
#pragma unroll
            for (int j = 0; j < 16; j++) {
                float dx = __fsub_rn(px[j], cx);
                float dy = __fsub_rn(py[j], cy);
                float dz = __fsub_rn(pz[j], cz);
                float d  = __fadd_rn(__fadd_rn(__fmul_rn(dx,dx), __fmul_rn(dy,dy)),
                                     __fmul_rn(dz,dz));
                dist[j] = fminf(dist[j], d);
            }
            float m8[8];
#pragma unroll
            for (int j = 0; j < 8; j++) m8[j] = fmaxf(dist[j], dist[j+8]);
#pragma unroll
            for (int j = 0; j < 4; j++) m8[j] = fmaxf(m8[j], m8[j+4]);
            float bv = fmaxf(fmaxf(m8[0], m8[1]), fmaxf(m8[2], m8[3]));
            unsigned match = 0;
#pragma unroll
            for (int j = 0; j < 16; j++) match |= (dist[j] == bv) ? (1u << j) : 0u;
            int bi = tid*16 + (__ffs(match) - 1);

            unsigned key  = __float_as_uint(bv);
            unsigned wmax = __reduce_max_sync(0xffffffffu, key);
            unsigned ball = __ballot_sync(0xffffffffu, key == wmax);
            int src  = __ffs(ball) - 1;
            int wbi  = __shfl_sync(0xffffffffu, bi, src);
            if (lane == 0)
                swk[(s & 1)*8 + wid] = ((unsigned long long)wmax << 32)
                                     | (unsigned)(NN - 1 - wbi);
            __syncthreads();
            unsigned long long best = swk[(s & 1)*8 + 0];
#pragma unroll
            for (int w = 1; w < 8; w++) {
                unsigned long long c = swk[(s & 1)*8 + w];
                if (c > best) best = c;
            }
            far = NN - 1 - (int)(best & 0xffffffffu);
        }
        return;
    }

    if (bid < B_KV) {
        // ------------- pre-cvts (points, wk, wv) + release counter ----------
        int cb = bid - B_CVTPRE;
        if (cb < CVT_PTS_B)               cvt_block_wide(points, g_ph, g_pl, cb, tid);
        else if (cb < CVT_PTS_B + CVT_WSM_B)
            cvt_block_wide(wk, g_wkh, g_wkl, cb - CVT_PTS_B, tid);
        else
            cvt_block_wide(wv, g_wvh, g_wvl, cb - CVT_PTS_B - CVT_WSM_B, tid);
        __syncthreads();
        if (tid == 0) { __threadfence(); atomicAdd(&g_cvtcnt, 1); }
        return;
    }

    if (bid < B_CVTPOST) {
        // -------------------- merged k/v GEMM (polls cvtcnt) ----------------
        if (tid == 0) { while (ld_acquire(&g_cvtcnt) < CVT_PRE_TOT) { } }
        const int idx = bid - B_KV;
        const int bx  = idx & 7;           // 0..3 -> wk, 4..7 -> wv
        const int m0  = (idx >> 3) * 128;
        const int n0  = (bx & 3) * 64;
        const bf16* WhiS = (bx < 4) ? g_wkh : g_wvh;
        const bf16* WloS = (bx < 4) ? g_wkl : g_wvl;
        float* CS = (bx < 4) ? g_kall : g_vall;
        const int Kd = CIN;
        const int* rowmap = nullptr;

        GEMM_MAINLOOP(g_ph, g_pl, rowmap, WhiS, WloS)

        const int quad = lane >> 2, tq = lane & 3;
#pragma unroll
        for (int mt = 0; mt < 2; mt++) {
            int r0 = m0 + wm*32 + mt*16 + quad;
            int r1 = r0 + 8;
#pragma unroll
            for (int nt = 0; nt < 4; nt++) {
                int col = n0 + wn*32 + nt*8 + tq*2;
                *(float2*)(CS + (size_t)r0*COUT + col) =
                    make_float2(acc[mt][nt][0], acc[mt][nt][1]);
                *(float2*)(CS + (size_t)r1*COUT + col) =
                    make_float2(acc[mt][nt][2], acc[mt][nt][3]);
            }
        }
        return;
    }

    if (bid < B_KNN) {
        // ------------------------ post weight cvts ---------------------------
        int cb = bid - B_CVTPOST;
        if (cb < CVT_WSM_B) { cvt_block_wide(wq, g_wqh, g_wql, cb, tid); return; }
        cb -= CVT_WSM_B;
        if (cb < CVT_WBG_B) { cvt_block_wide(dw2, g_dw2h, g_dw2l, cb, tid); return; }
        cb -= CVT_WBG_B;
        if (cb < CVT_WBG_B) { cvt_block_wide(gw1, g_gw1h, g_gw1l, cb, tid); return; }
        cb -= CVT_WBG_B;
        if (cb < CVT_WBG_B) { cvt_block_wide(gw2, g_gw2h, g_gw2l, cb, tid); return; }
        cb -= CVT_WBG_B;
        cvt_block_wide(lw, g_lwh, g_lwl, cb, tid);
        return;
    }

    if (bid < B_Q) {
        // ------------- KNN (polls FPS progress, commits kprog) ---------------
        extern __shared__ char smk[];
        float (*smd)[512] = (float(*)[512])smk;
        int   (*smi)[512] = (int(*)[512])(smk + 8*512*4);

        const int kb   = bid - B_KNN;
        const int lane = tid & 31;
        const int wloc = tid >> 5;
        const int b    = kb & 7;
        const int s0   = (kb >> 3) * 8;
        const int s    = s0 + wloc;
        const int warp = b * SS + s;
        const float* base = xyz + (size_t)b * NN * 3;

        if (lane == 0) {
            while (ld_acquire(&g_prog[b]) <= s) { }
        }
        __syncwarp();

        float nx = __ldcg(newxyz + (size_t)warp*3 + 0);
        float ny = __ldcg(newxyz + (size_t)warp*3 + 1);
        float nz = __ldcg(newxyz + (size_t)warp*3 + 2);
        float ns = fmaf(nz, nz, fmaf(ny, ny, __fmul_rn(nx, nx)));

        float v[16]; int id[16];
#pragma unroll
        for (int t = 0; t < 16; t++) { v[t] = 3.4e38f; id[t] = 0x7fffffff; }

        for (int j = lane; j < NN; j += 32) {
            float x = base[j*3+0], y = base[j*3+1], z = base[j*3+2];
            float dot = fmaf(z, nz, fmaf(y, ny, __fmul_rn(x, nx)));
            float nq  = fmaf(z, z,  fmaf(y, y,  __fmul_rn(x, x)));
            float d   = __fadd_rn(__fsub_rn(ns, __fmul_rn(2.0f, dot)), nq);
            if (d < v[15]) {
                v[15] = d; id[15] = j;
#pragma unroll
                for (int t = 15; t > 0; t--) {
                    if (v[t] < v[t-1] || (v[t] == v[t-1] && id[t] < id[t-1])) {
                        float tv = v[t]; v[t] = v[t-1]; v[t-1] = tv;
                        int   ti = id[t]; id[t] = id[t-1]; id[t-1] = ti;
                    } else break;
                }
            }
        }

#pragma unroll
        for (int t = 0; t < 16; t++) {
            smd[wloc][lane*16 + t] = v[t];
            smi[wloc][lane*16 + t] = id[t];
        }
        __syncwarp();

        int p = 0;
        for (int t = 0; t < 16; t++) {
            float cv = (p < 16) ? smd[wloc][lane*16 + p] : 3.4e38f;
            int   ci = (p < 16) ? smi[wloc][lane*16 + p] : 0x7fffffff;
            float mv = cv; int mi = ci;
#pragma unroll
            for (int off = 16; off; off >>= 1) {
                float ov = __shfl_xor_sync(0xffffffffu, mv, off);
                int   oi = __shfl_xor_sync(0xffffffffu, mi, off);
                if (ov < mv || (ov == mv && oi < mi)) { mv = ov; mi = oi; }
            }
            if (cv == mv && ci == mi) p++;
            if (lane == 0) g_knn[(size_t)warp*16 + t] = b*NN + mi;
            __syncwarp();
        }

        // in-order commit of per-batch KNN progress
        __syncthreads();
        if (tid == 0) {
            while (ld_acquire(&g_kprog[b]) != s0) { }
            __threadfence();
            atomicExch(&g_kprog[b], s0 + 8);
        }
        return;
    }

    if (bid < B_H1) {
        // -------------- q GEMM = gather(points, fps) @ wq (polls prog) -------
        const int idx = bid - B_Q;
        const int n0  = (idx & 3) * 64;
        const int m0  = (idx >> 2) * 128;
        const int b   = m0 >> 10;
        const int s_need = (m0 & 1023) + 128;
        if (tid == 0) { while (ld_acquire(&g_prog[b]) < s_need) { } }
        const int Kd = CIN;
        const int* fps_ptr = g_fps;

        GEMM_MAINLOOP(g_ph, g_pl, fps_ptr, g_wqh, g_wql)

        const int quad = lane >> 2, tq = lane & 3;
#pragma unroll
        for (int mt = 0; mt < 2; mt++) {
            int r0 = m0 + wm*32 + mt*16 + quad;
            int r1 = r0 + 8;
#pragma unroll
            for (int nt = 0; nt < 4; nt++) {
                int col = n0 + wn*32 + nt*8 + tq*2;
                *(float2*)(g_q + (size_t)r0*COUT + col) =
                    make_float2(acc[mt][nt][0], acc[mt][nt][1]);
                *(float2*)(g_q + (size_t)r1*COUT + col) =
                    make_float2(acc[mt][nt][2], acc[mt][nt][3]);
            }
        }
        return;
    }

    // ----------------- h1 pos-enc layer 1 (polls kprog) ----------------------
    {
        const int hb = bid - B_H1;           // 0..1023, rows [hb*128, +128)
        const int b  = hb >> 7;
        const int s_need = ((hb * 8) & 1023) + 8;
        if (tid == 0) { while (ld_acquire(&g_kprog[b]) < s_need) { } }
        __syncthreads();

        const int col    = (tid & 127) * 2;
        const int rowsel = tid >> 7;
        const float w0a = dw1[col],        w0b = dw1[col+1];
        const float w1a = dw1[COUT+col],   w1b = dw1[COUT+col+1];
        const float w2a = dw1[2*COUT+col], w2b = dw1[2*COUT+col+1];
        const float b0  = db1[col],        b1  = db1[col+1];

        for (int rr = 0; rr < 64; rr++) {
            int r  = hb*128 + rr*2 + rowsel;
            int g  = __ldcg(&g_knn[r]);
            int bs = r >> 4;
            float cx = __ldcg(&xyz[(size_t)g*3+0]) - __ldcg(&newxyz[(size_t)bs*3+0]);
            float cy = __ldcg(&xyz[(size_t)g*3+1]) - __ldcg(&newxyz[(size_t)bs*3+1]);
            float cz = __ldcg(&xyz[(size_t)g*3+2]) - __ldcg(&newxyz[(size_t)bs*3+2]);
            float h0 = b0, h1v = b1;
            h0  = fmaf(cx, w0a, h0);  h0  = fmaf(cy, w1a, h0);  h0  = fmaf(cz, w2a, h0);
            h1v = fmaf(cx, w0b, h1v); h1v = fmaf(cy, w1b, h1v); h1v = fmaf(cz, w2b, h1v);
            h0  = fmaxf(h0, 0.0f);
            h1v = fmaxf(h1v, 0.0f);
            uint32_t h, l;
            split2(h0, h1v, h, l);
            *(uint32_t*)&g_x1h[(size_t)r*COUT + col] = h;
            *(uint32_t*)&g_x1l[(size_t)r*COUT + col] = l;
        }
    }
}

// --------- generic GEMM (fp32 out / bf16-split out / fused a1 dual write) ---
__global__ __launch_bounds__(256, 2) void tgemm_bf(
    const bf16* __restrict__ Ahi, const bf16* __restrict__ Alo,
    const int* __restrict__ rowmap,
    const bf16* __restrict__ Whi, const bf16* __restrict__ Wlo,
    const float* __restrict__ bias, int Kd, int relu,
    float* __restrict__ C, bf16* __restrict__ Chi, bf16* __restrict__ Clo,
    const float* __restrict__ qv, const float* __restrict__ kall,
    const int* __restrict__ knn,
    bf16* __restrict__ A1hi, bf16* __restrict__ A1lo)
{
    const int tid = threadIdx.x;
    const int m0  = blockIdx.y * 128;
    const int n0  = blockIdx.x * 64;

    GEMM_MAINLOOP(Ahi, Alo, rowmap, Whi, Wlo)

    const int quad = lane >> 2, tq = lane & 3;
#pragma unroll
    for (int mt = 0; mt < 2; mt++) {
        int r0 = m0 + wm*32 + mt*16 + quad;
        int r1 = r0 + 8;
        const float *q0 = nullptr, *k0p = nullptr, *q1 = nullptr, *k1p = nullptr;
        if (A1hi) {
            q0 = qv + (size_t)(r0 >> 4) * COUT;  k0p = kall + (size_t)knn[r0] * COUT;
            q1 = qv + (size_t)(r1 >> 4) * COUT;  k1p = kall + (size_t)knn[r1] * COUT;
        }
#pragma unroll
        for (int nt = 0; nt < 4; nt++) {
            int col = n0 + wn*32 + nt*8 + tq*2;
            float o0 = acc[mt][nt][0], o1 = acc[mt][nt][1];
            float o2 = acc[mt][nt][2], o3 = acc[mt][nt][3];
            if (bias) { float bb0 = bias[col], bb1 = bias[col+1];
                        o0 += bb0; o1 += bb1; o2 += bb0; o3 += bb1; }
            if (relu) { o0 = fmaxf(o0,0.f); o1 = fmaxf(o1,0.f);
                        o2 = fmaxf(o2,0.f); o3 = fmaxf(o3,0.f); }
            if (C) {
                *(float2*)(C + (size_t)r0*COUT + col) = make_float2(o0, o1);
                *(float2*)(C + (size_t)r1*COUT + col) = make_float2(o2, o3);
            }
            if (Chi) {
                uint32_t h, l;
                split2(o0, o1, h, l);
                *(uint32_t*)&Chi[(size_t)r0*COUT + col] = h;
                *(uint32_t*)&Clo[(size_t)r0*COUT + col] = l;
                split2(o2, o3, h, l);
                *(uint32_t*)&Chi[(size_t)r1*COUT + col] = h;
                *(uint32_t*)&Clo[(size_t)r1*COUT + col] = l;
            }
            if (A1hi) {
                float w0 = __fadd_rn(__fsub_rn(q0[col],   k0p[col]),   o0);
                float w1 = __fadd_rn(__fsub_rn(q0[col+1], k0p[col+1]), o1);
                float w2 = __fadd_rn(__fsub_rn(q1[col],   k1p[col]),   o2);
                float w3 = __fadd_rn(__fsub_rn(q1[col+1], k1p[col+1]), o3);
                uint32_t h, l;
                split2(w0, w1, h, l);
                *(uint32_t*)&A1hi[(size_t)r0*COUT + col] = h;
                *(uint32_t*)&A1lo[(size_t)r0*COUT + col] = l;
                split2(w2, w3, h, l);
                *(uint32_t*)&A1hi[(size_t)r1*COUT + col] = h;
                *(uint32_t*)&A1lo[(size_t)r1*COUT + col] = l;
            }
        }
    }
}

// --------- att GEMM with fused per-group softmax + weighted sum -------------
// att = A@gw2 + gb2, then per 16-row group (one sampled point), per channel:
//   p = softmax(att/16 over group rows); r0 = sum_i p_i * (vall[knn_i] + pos_i)
__global__ __launch_bounds__(256, 2) void tgemm_att(
    const bf16* __restrict__ Ahi, const bf16* __restrict__ Alo,
    const bf16* __restrict__ Whi, const bf16* __restrict__ Wlo,
    const float* __restrict__ bias, int Kd,
    const int* __restrict__ knn,
    const float* __restrict__ pos, const float* __restrict__ vall,
    bf16* __restrict__ R0hi, bf16* __restrict__ R0lo)
{
    const int tid = threadIdx.x;
    const int m0  = blockIdx.y * 128;
    const int n0  = blockIdx.x * 64;
    const int* rowmap = nullptr;

    GEMM_MAINLOOP(Ahi, Alo, rowmap, Whi, Wlo)

    const int quad = lane >> 2;
    const unsigned FULL = 0xffffffffu;
#pragma unroll
    for (int mt = 0; mt < 2; mt++) {
        int gr  = m0 + wm*32 + mt*16;      // 16-aligned group base
        int bs  = gr >> 4;
        int ra  = gr + quad;
        int rb  = ra + 8;
        int kna = knn[ra], knb = knn[rb];
#pragma unroll
        for (int nt = 0; nt < 4; nt++) {
            int col = n0 + wn*32 + nt*8 + (lane & 3)*2;
            float b0 = bias[col], b1 = bias[col+1];
            float v00 = (acc[mt][nt][0] + b0) * 0.0625f;   // row ra, col
            float v01 = (acc[mt][nt][1] + b1) * 0.0625f;   // row ra, col+1
            float v10 = (acc[mt][nt][2] + b0) * 0.0625f;   // row rb, col
            float v11 = (acc[mt][nt][3] + b1) * 0.0625f;   // row rb, col+1
            float m0c = fmaxf(v00, v10);
            float m1c = fmaxf(v01, v11);
#pragma unroll
            for (int off = 4; off <= 16; off <<= 1) {
                m0c = fmaxf(m0c, __shfl_xor_sync(FULL, m0c, off));
                m1c = fmaxf(m1c, __shfl_xor_sync(FULL, m1c, off));
            }
            float e00 = expf(v00 - m0c), e10 = expf(v10 - m0c);
            float e01 = expf(v01 - m1c), e11 = expf(v11 - m1c);
            float s0 = e00 + e10, s1 = e01 + e11;
#pragma unroll
            for (int off = 4; off <= 16; off <<= 1) {
                s0 += __shfl_xor_sync(FULL, s0, off);
                s1 += __shfl_xor_sync(FULL, s1, off);
            }
            float2 pa = *(const float2*)(pos  + (size_t)ra*COUT + col);
            float2 pb = *(const float2*)(pos  + (size_t)rb*COUT + col);
            float2 va = *(const float2*)(vall + (size_t)kna*COUT + col);
            float2 vb = *(const float2*)(vall + (size_t)knb*COUT + col);
            float w0 = e00*(va.x + pa.x) + e10*(vb.x + pb.x);
            float w1 = e01*(va.y + pa.y) + e11*(vb.y + pb.y);
#pragma unroll
            for (int off = 4; off <= 16; off <<= 1) {
                w0 += __shfl_xor_sync(FULL, w0, off);
                w1 += __shfl_xor_sync(FULL, w1, off);
            }
            if (quad == 0) {
                float o0 = w0 / s0, o1 = w1 / s1;
                uint32_t h, l;
                split2(o0, o1, h, l);
                *(uint32_t*)&R0hi[(size_t)bs*COUT + col] = h;
                *(uint32_t*)&R0lo[(size_t)bs*COUT + col] = l;
            }
        }
    }
}

// ---------------------------- BatchNorm ------------------------------------
__global__ void bn_partial_kernel()
{
    int blk = blockIdx.x;
    int c   = threadIdx.x;
    float s = 0.0f, q = 0.0f;
    for (int r = blk*128; r < blk*128 + 128; r++) {
        float x = g_res1[(size_t)r*COUT + c];
        s += x; q = fmaf(x, x, q);
    }
    g_psum[blk*COUT + c] = s;
    g_psq [blk*COUT + c] = q;
}

__global__ void bn_final_kernel(const float* __restrict__ bng, const float* __restrict__ bnb)
{
    int c = threadIdx.x;
    float s = 0.0f, q = 0.0f;
    for (int i = 0; i < 64; i++) { s += g_psum[i*COUT + c]; q += g_psq[i*COUT + c]; }
    float mean = s * (1.0f/(float)BSR);
    float var  = fmaxf(q * (1.0f/(float)BSR) - mean*mean, 0.0f);
    float sc   = bng[c] * rsqrtf(var + 1e-5f);
    g_scale[c] = sc;
    g_shift[c] = bnb[c] - mean * sc;
}

__global__ void bn_apply_kernel(float* __restrict__ out)
{
    size_t e = (size_t)blockIdx.x * blockDim.x + threadIdx.x;
    int c = (int)(e & 255);
    out[e] = fmaxf(fmaf(g_res1[e], g_scale[c], g_shift[c]), 0.0f);
}

// ------------------------------ launch --------------------------------------
extern "C" void kernel_launch(void* const* d_in, const int* in_sizes, int n_in,
                              void* d_out, int out_size)
{
    const float* xyz    = (const float*)d_in[0];
    const float* points = (const float*)d_in[1];
    const float* wq     = (const float*)d_in[2];
    const float* wk     = (const float*)d_in[3];
    const float* wv     = (const float*)d_in[4];
    const float* dw1    = (const float*)d_in[5];
    const float* db1    = (const float*)d_in[6];
    const float* dw2    = (const float*)d_in[7];
    const float* db2    = (const float*)d_in[8];
    const float* gw1    = (const float*)d_in[9];
    const float* gb1    = (const float*)d_in[10];
    const float* gw2    = (const float*)d_in[11];
    const float* gb2    = (const float*)d_in[12];
    const float* lw     = (const float*)d_in[13];
    const float* lb     = (const float*)d_in[14];
    const float* bng    = (const float*)d_in[15];
    const float* bnb    = (const float*)d_in[16];

    float* out     = (float*)d_out;
    float* newxyz  = out;
    float* res_out = out + (size_t)BSR*3;

    static bool attr_set = false;
    if (!attr_set) {
        cudaFuncSetAttribute(tgemm_bf,  cudaFuncAttributeMaxDynamicSharedMemorySize, TG_SMEM);
        cudaFuncSetAttribute(tgemm_att, cudaFuncAttributeMaxDynamicSharedMemorySize, TG_SMEM);
        cudaFuncSetAttribute(fused_all, cudaFuncAttributeMaxDynamicSharedMemorySize, TG_SMEM);
        attr_set = true;
    }

#define SYM(p, s) void* p; cudaGetSymbolAddress(&p, s)
    SYM(ppos, g_pos);
    SYM(pa1h, g_a1h);  SYM(pa1l, g_a1l);
    SYM(px1h, g_x1h);  SYM(px1l, g_x1l);
    SYM(pph,  g_ph);   SYM(ppl,  g_pl);
    SYM(pk,   g_kall); SYM(pv,   g_vall);
    SYM(pq,   g_q);
    SYM(pr0h, g_r0h);  SYM(pr0l, g_r0l);
    SYM(pr1,  g_res1);
    SYM(pknn, g_knn);
    SYM(pdw2h, g_dw2h); SYM(pdw2l, g_dw2l);
    SYM(pgw1h, g_gw1h); SYM(pgw1l, g_gw1l);
    SYM(pgw2h, g_gw2h); SYM(pgw2l, g_gw2l);
    SYM(plwh, g_lwh);   SYM(plwl, g_lwl);
#undef SYM

    // 1: reset progress counters (graph-replay safe)
    reset_prog_kernel<<<1, 64>>>();
    // 2: FPS || pre-cvts || kv GEMM || post-cvts || KNN || q GEMM || h1
    fused_all<<<FUSED_GRID, 256, TG_SMEM>>>(xyz, newxyz, points, wk, wv,
                                            wq, dw2, gw1, gw2, lw, dw1, db1);
    // 3: pos = h1 @ dw2 + db2 (fp32) + fused a1 = q - k_gather + pos (bf16 split)
    tgemm_bf<<<dim3(4, MROWS/128), 256, TG_SMEM>>>(
        (const bf16*)px1h, (const bf16*)px1l, nullptr,
        (const bf16*)pdw2h, (const bf16*)pdw2l, db2, COUT, 0,
        (float*)ppos, nullptr, nullptr,
        (const float*)pq, (const float*)pk, (const int*)pknn,
        (bf16*)pa1h, (bf16*)pa1l);
    // 4: h2 = relu(a1 @ gw1 + gb1) -> x1 (bf16 split)
    tgemm_bf<<<dim3(4, MROWS/128), 256, TG_SMEM>>>(
        (const bf16*)pa1h, (const bf16*)pa1l, nullptr,
        (const bf16*)pgw1h, (const bf16*)pgw1l, gb1, COUT, 1,
        nullptr, (bf16*)px1h, (bf16*)px1l,
        nullptr, nullptr, nullptr, nullptr, nullptr);
    // 5: att GEMM + fused softmax/weighted-sum -> r0 (bf16 split)
    tgemm_att<<<dim3(4, MROWS/128), 256, TG_SMEM>>>(
        (const bf16*)px1h, (const bf16*)px1l,
        (const bf16*)pgw2h, (const bf16*)pgw2l,
        gb2, COUT, (const int*)pknn,
        (const float*)ppos, (const float*)pv,
        (bf16*)pr0h, (bf16*)pr0l);
    // 6: res1 = res0 @ lw + lb
    tgemm_bf<<<dim3(4, BSR/128), 256, TG_SMEM>>>(
        (const bf16*)pr0h, (const bf16*)pr0l, nullptr,
        (const bf16*)plwh, (const bf16*)plwl, lb, COUT, 0,
        (float*)pr1, nullptr, nullptr,
        nullptr, nullptr, nullptr, nullptr, nullptr);
    // 7: BatchNorm (training stats) + ReLU -> output
    bn_partial_kernel<<<64, 256>>>();
    bn_final_kernel<<<1, 256>>>(bng, bnb);
    bn_apply_kernel<<<(BSR*COUT)/1024, 1024>>>(res_out);
}

// round 15
// speedup vs baseline: 1.1157x; 1.0040x over previous
#include <cuda_runtime.h>
#include <cuda_bf16.h>
#include <math.h>
#include <stdint.h>

#define BB   8
#define NN   4096
#define SS   1024
#define KNBR 16
#define CIN  128
#define COUT 256
#define MROWS (BB*SS*KNBR)   /* 131072 */
#define BSR   (BB*SS)        /* 8192  */
#define NPTS  (BB*NN)        /* 32768 */

typedef __nv_bfloat16 bf16;

// ---------------- static device scratch (no allocs allowed) ----------------
__device__ float g_pos [(size_t)MROWS*COUT];
__device__ bf16  g_a1h [(size_t)MROWS*COUT];
__device__ bf16  g_a1l [(size_t)MROWS*COUT];
__device__ bf16  g_x1h [(size_t)MROWS*COUT];   // h1 then h2
__device__ bf16  g_x1l [(size_t)MROWS*COUT];
__device__ bf16  g_ph  [(size_t)NPTS*CIN];
__device__ bf16  g_pl  [(size_t)NPTS*CIN];
__device__ float g_kall[(size_t)NPTS*COUT];
__device__ float g_vall[(size_t)NPTS*COUT];
__device__ float g_q   [(size_t)BSR*COUT];
__device__ bf16  g_r0h [(size_t)BSR*COUT];
__device__ bf16  g_r0l [(size_t)BSR*COUT];
__device__ float g_res1[(size_t)BSR*COUT];
__device__ int   g_fps [BSR];
__device__ int   g_knn [MROWS];
__device__ int   g_prog[BB];
__device__ int   g_kprog[BB];
__device__ int   g_cvtcnt;
__device__ int   g_c1[MROWS/128];
__device__ int   g_c2[MROWS/128];
__device__ int   g_c3[BSR/128];
__device__ int   g_c4a[BSR/128];
__device__ int   g_c5;
__device__ float g_psum[64*COUT];
__device__ float g_psq [64*COUT];
// pre-split weights
__device__ bf16  g_wkh[CIN*COUT],  g_wkl[CIN*COUT];
__device__ bf16  g_wvh[CIN*COUT],  g_wvl[CIN*COUT];
__device__ bf16  g_wqh[CIN*COUT],  g_wql[CIN*COUT];
__device__ bf16  g_dw2h[COUT*COUT], g_dw2l[COUT*COUT];
__device__ bf16  g_gw1h[COUT*COUT], g_gw1l[COUT*COUT];
__device__ bf16  g_gw2h[COUT*COUT], g_gw2l[COUT*COUT];
__device__ bf16  g_lwh[COUT*COUT],  g_lwl[COUT*COUT];

// -------------------- bf16 split helper ------------------------------------
__device__ __forceinline__ void split2(float x0, float x1, uint32_t& hi, uint32_t& lo)
{
    bf16 h0 = __float2bfloat16(x0);
    bf16 h1 = __float2bfloat16(x1);
    float r0 = __fsub_rn(x0, __bfloat162float(h0));
    float r1 = __fsub_rn(x1, __bfloat162float(h1));
    bf16 l0 = __float2bfloat16(r0);
    bf16 l1 = __float2bfloat16(r1);
    hi = (uint32_t)__bfloat16_as_ushort(h0) | ((uint32_t)__bfloat16_as_ushort(h1) << 16);
    lo = (uint32_t)__bfloat16_as_ushort(l0) | ((uint32_t)__bfloat16_as_ushort(l1) << 16);
}

__device__ __forceinline__ int ld_acquire(const int* p)
{
    int v;
    asm volatile("ld.acquire.gpu.global.b32 %0, [%1];" : "=r"(v) : "l"(p));
    return v;
}

// ---------------- wide fp32 -> bf16 hi/lo conversion (8 elems/thread) -------
__device__ __forceinline__ void cvt_block_wide(const float* __restrict__ src,
                                               bf16* __restrict__ hi, bf16* __restrict__ lo,
                                               int local_bid, int tid)
{
    int e = (local_bid * 256 + tid) * 8;
    float4 a = *(const float4*)(src + e);
    float4 c = *(const float4*)(src + e + 4);
    uint32_t h0,l0,h1,l1,h2,l2,h3,l3;
    split2(a.x, a.y, h0, l0); split2(a.z, a.w, h1, l1);
    split2(c.x, c.y, h2, l2); split2(c.z, c.w, h3, l3);
    uint4 H; H.x = h0; H.y = h1; H.z = h2; H.w = h3;
    uint4 L; L.x = l0; L.y = l1; L.z = l2; L.w = l3;
    *(uint4*)&hi[e] = H;
    *(uint4*)&lo[e] = L;
}

__global__ void reset_prog_kernel()
{
    int t = blockIdx.x * 256 + threadIdx.x;   // <<<8,256>>> -> 2048
    if (t < 1024) { g_c1[t] = 0; g_c2[t] = 0; }
    int u = t - 1024;
    if (u >= 0) {
        if (u < 64)              g_c3[u] = 0;
        else if (u < 128)        g_c4a[u-64] = 0;
        else if (u == 128)       g_c5 = 0;
        else if (u >= 192 && u < 200) g_prog[u-192] = 0;
        else if (u >= 200 && u < 208) g_kprog[u-200] = 0;
        else if (u == 208)       g_cvtcnt = 0;
    }
}

// ------------------------- mma helpers --------------------------------------
__device__ __forceinline__ void cp16(void* s, const void* g)
{
    unsigned sa = (unsigned)__cvta_generic_to_shared(s);
    asm volatile("cp.async.ca.shared.global [%0], [%1], 16;\n" :: "r"(sa), "l"(g));
}
#define CP_COMMIT() asm volatile("cp.async.commit_group;\n")

__device__ __forceinline__ void ldsm_x4(uint32_t* r, const void* p)
{
    uint32_t a = (uint32_t)__cvta_generic_to_shared(p);
    asm volatile("ldmatrix.sync.aligned.m8n8.x4.shared.b16 {%0,%1,%2,%3}, [%4];"
                 : "=r"(r[0]), "=r"(r[1]), "=r"(r[2]), "=r"(r[3]) : "r"(a));
}

__device__ __forceinline__ void ldsm_x4_t(uint32_t* r, const void* p)
{
    uint32_t a = (uint32_t)__cvta_generic_to_shared(p);
    asm volatile("ldmatrix.sync.aligned.m8n8.x4.trans.shared.b16 {%0,%1,%2,%3}, [%4];"
                 : "=r"(r[0]), "=r"(r[1]), "=r"(r[2]), "=r"(r[3]) : "r"(a));
}

__device__ __forceinline__ void mma16816(float* c, const uint32_t* a, const uint32_t* b)
{
    asm volatile("mma.sync.aligned.m16n8k16.row.col.f32.bf16.bf16.f32 "
                 "{%0,%1,%2,%3}, {%4,%5,%6,%7}, {%8,%9}, {%0,%1,%2,%3};"
                 : "+f"(c[0]), "+f"(c[1]), "+f"(c[2]), "+f"(c[3])
                 : "r"(a[0]), "r"(a[1]), "r"(a[2]), "r"(a[3]),
                   "r"(b[0]), "r"(b[1]));
}

// ----------------------- shared GEMM mainloop macro (128x64, 4-stage) -------
#define KCH    16
#define NSTG   4
#define ASTR2  24
#define BSTR2  72
#define AS_BYTES  (NSTG*2*128*ASTR2*2)
#define BS_BYTES  (NSTG*2*KCH*BSTR2*2)
#define TG_SMEM   (AS_BYTES + BS_BYTES + 512)

#define GEMM_MAINLOOP(AHI, ALO, ROWMAP, WHI, WLO)                               \
    extern __shared__ char smraw[];                                            \
    typedef bf16 (*AsT)[2][128][ASTR2];                                        \
    typedef bf16 (*BsT)[2][KCH][BSTR2];                                        \
    AsT As = (AsT)smraw;                                                       \
    BsT Bs = (BsT)(smraw + AS_BYTES);                                          \
    int* rmap = (int*)(smraw + AS_BYTES + BS_BYTES);                           \
    if (tid < 128) rmap[tid] = (ROWMAP) ? __ldcg((ROWMAP) + m0 + tid) : (m0 + tid); \
    __syncthreads();                                                           \
    const int arow = tid >> 1;                                                 \
    const int ach  = (tid & 1) * 8;                                            \
    const bf16* aSrcH = (AHI) + (size_t)rmap[arow] * Kd + ach;                 \
    const bf16* aSrcL = (ALO) + (size_t)rmap[arow] * Kd + ach;                 \
    const int bpl = tid >> 7;                                                  \
    const int bk  = (tid >> 3) & 15;                                           \
    const int bch = (tid & 7) * 8;                                             \
    const bf16* bSrc = (bpl ? (WLO) : (WHI)) + (size_t)bk * COUT + n0 + bch;   \
    const int lane = tid & 31;                                                 \
    const int wm = (tid >> 5) >> 1;                                            \
    const int wn = (tid >> 5) & 1;                                             \
    const int aFrow = wm * 32 + (lane & 15);                                   \
    const int aFk   = (lane >> 4) * 8;                                         \
    const int bFk   = (lane & 7) + ((lane >> 3) & 1) * 8;                      \
    const int bFn   = (lane >> 4) * 8;                                         \
    float acc[2][4][4];                                                        \
    _Pragma("unroll")                                                          \
    for (int i = 0; i < 2; i++)                                                \
        _Pragma("unroll")                                                      \
        for (int j = 0; j < 4; j++)                                            \
            _Pragma("unroll")                                                  \
            for (int l = 0; l < 4; l++) acc[i][j][l] = 0.0f;                   \
    const int nk = Kd >> 4;                                                    \
    _Pragma("unroll")                                                          \
    for (int s = 0; s < NSTG - 1; s++) {                                       \
        if (s < nk) {                                                          \
            int k0 = s * KCH;                                                  \
            cp16(&As[s][0][arow][ach], aSrcH + k0);                            \
            cp16(&As[s][1][arow][ach], aSrcL + k0);                            \
            cp16(&Bs[s][bpl][bk][bch], bSrc + (size_t)k0 * COUT);              \
        }                                                                      \
        CP_COMMIT();                                                           \
    }                                                                          \
    for (int t = 0; t < nk; t++) {                                             \
        const int cur = t & (NSTG - 1);                                        \
        if (t + NSTG - 1 < nk) {                                               \
            asm volatile("cp.async.wait_group 2;\n" ::: "memory");             \
        } else {                                                               \
            asm volatile("cp.async.wait_group 0;\n" ::: "memory");             \
        }                                                                      \
        __syncthreads();                                                       \
        if (t + NSTG - 1 < nk) {                                               \
            const int stg = (t + NSTG - 1) & (NSTG - 1);                       \
            const int k0  = (t + NSTG - 1) * KCH;                              \
            cp16(&As[stg][0][arow][ach], aSrcH + k0);                          \
            cp16(&As[stg][1][arow][ach], aSrcL + k0);                          \
            cp16(&Bs[stg][bpl][bk][bch], bSrc + (size_t)k0 * COUT);            \
            CP_COMMIT();                                                       \
        }                                                                      \
        uint32_t ah[2][4], al[2][4], bh[4][2], bl[4][2];                       \
        _Pragma("unroll")                                                      \
        for (int mt = 0; mt < 2; mt++) {                                       \
            ldsm_x4(ah[mt], &As[cur][0][aFrow + mt*16][aFk]);                  \
            ldsm_x4(al[mt], &As[cur][1][aFrow + mt*16][aFk]);                  \
        }                                                                      \
        _Pragma("unroll")                                                      \
        for (int g = 0; g < 2; g++) {                                          \
            uint32_t tmp[4];                                                   \
            ldsm_x4_t(tmp, &Bs[cur][0][bFk][wn*32 + g*16 + bFn]);              \
            bh[g*2][0]   = tmp[0]; bh[g*2][1]   = tmp[1];                      \
            bh[g*2+1][0] = tmp[2]; bh[g*2+1][1] = tmp[3];                      \
            ldsm_x4_t(tmp, &Bs[cur][1][bFk][wn*32 + g*16 + bFn]);              \
            bl[g*2][0]   = tmp[0]; bl[g*2][1]   = tmp[1];                      \
            bl[g*2+1][0] = tmp[2]; bl[g*2+1][1] = tmp[3];                      \
        }                                                                      \
        _Pragma("unroll")                                                      \
        for (int mt = 0; mt < 2; mt++)                                         \
            _Pragma("unroll")                                                  \
            for (int nt = 0; nt < 4; nt++) {                                   \
                mma16816(acc[mt][nt], ah[mt], bh[nt]);                         \
                mma16816(acc[mt][nt], al[mt], bh[nt]);                         \
                mma16816(acc[mt][nt], ah[mt], bl[nt]);                         \
            }                                                                  \
    }

// --------- GEMM body as device function (fp32 / bf16-split / a1 dual) -------
__device__ __forceinline__ void gemm_body(
    int tid, int m0, int n0, int Kd,
    const bf16* __restrict__ Ahi, const bf16* __restrict__ Alo,
    const int* __restrict__ rowmap,
    const bf16* __restrict__ Whi, const bf16* __restrict__ Wlo,
    const float* __restrict__ bias, int relu,
    float* __restrict__ C, bf16* __restrict__ Chi, bf16* __restrict__ Clo,
    const float* __restrict__ qv, const float* __restrict__ kall,
    const int* __restrict__ knn,
    bf16* __restrict__ A1hi, bf16* __restrict__ A1lo)
{
    GEMM_MAINLOOP(Ahi, Alo, rowmap, Whi, Wlo)

    const int quad = lane >> 2, tq = lane & 3;
#pragma unroll
    for (int mt = 0; mt < 2; mt++) {
        int r0 = m0 + wm*32 + mt*16 + quad;
        int r1 = r0 + 8;
        const float *q0 = nullptr, *k0p = nullptr, *q1 = nullptr, *k1p = nullptr;
        if (A1hi) {
            q0 = qv + (size_t)(r0 >> 4) * COUT;  k0p = kall + (size_t)knn[r0] * COUT;
            q1 = qv + (size_t)(r1 >> 4) * COUT;  k1p = kall + (size_t)knn[r1] * COUT;
        }
#pragma unroll
        for (int nt = 0; nt < 4; nt++) {
            int col = n0 + wn*32 + nt*8 + tq*2;
            float o0 = acc[mt][nt][0], o1 = acc[mt][nt][1];
            float o2 = acc[mt][nt][2], o3 = acc[mt][nt][3];
            if (bias) { float bb0 = bias[col], bb1 = bias[col+1];
                        o0 += bb0; o1 += bb1; o2 += bb0; o3 += bb1; }
            if (relu) { o0 = fmaxf(o0,0.f); o1 = fmaxf(o1,0.f);
                        o2 = fmaxf(o2,0.f); o3 = fmaxf(o3,0.f); }
            if (C) {
                *(float2*)(C + (size_t)r0*COUT + col) = make_float2(o0, o1);
                *(float2*)(C + (size_t)r1*COUT + col) = make_float2(o2, o3);
            }
            if (Chi) {
                uint32_t h, l;
                split2(o0, o1, h, l);
                *(uint32_t*)&Chi[(size_t)r0*COUT + col] = h;
                *(uint32_t*)&Clo[(size_t)r0*COUT + col] = l;
                split2(o2, o3, h, l);
                *(uint32_t*)&Chi[(size_t)r1*COUT + col] = h;
                *(uint32_t*)&Clo[(size_t)r1*COUT + col] = l;
            }
            if (A1hi) {
                float w0 = __fadd_rn(__fsub_rn(q0[col],   k0p[col]),   o0);
                float w1 = __fadd_rn(__fsub_rn(q0[col+1], k0p[col+1]), o1);
                float w2 = __fadd_rn(__fsub_rn(q1[col],   k1p[col]),   o2);
                float w3 = __fadd_rn(__fsub_rn(q1[col+1], k1p[col+1]), o3);
                uint32_t h, l;
                split2(w0, w1, h, l);
                *(uint32_t*)&A1hi[(size_t)r0*COUT + col] = h;
                *(uint32_t*)&A1lo[(size_t)r0*COUT + col] = l;
                split2(w2, w3, h, l);
                *(uint32_t*)&A1hi[(size_t)r1*COUT + col] = h;
                *(uint32_t*)&A1lo[(size_t)r1*COUT + col] = l;
            }
        }
    }
}

// --------- att GEMM body: fused per-group softmax + weighted sum ------------
__device__ __forceinline__ void gemm_att_body(
    int tid, int m0, int n0, int Kd,
    const bf16* __restrict__ Ahi, const bf16* __restrict__ Alo,
    const bf16* __restrict__ Whi, const bf16* __restrict__ Wlo,
    const float* __restrict__ bias,
    const int* __restrict__ knn,
    const float* __restrict__ pos, const float* __restrict__ vall,
    bf16* __restrict__ R0hi, bf16* __restrict__ R0lo)
{
    const int* rowmap = nullptr;
    GEMM_MAINLOOP(Ahi, Alo, rowmap, Whi, Wlo)

    const int quad = lane >> 2;
    const unsigned FULL = 0xffffffffu;
#pragma unroll
    for (int mt = 0; mt < 2; mt++) {
        int gr  = m0 + wm*32 + mt*16;
        int bs  = gr >> 4;
        int ra  = gr + quad;
        int rb  = ra + 8;
        int kna = knn[ra], knb = knn[rb];
#pragma unroll
        for (int nt = 0; nt < 4; nt++) {
            int col = n0 + wn*32 + nt*8 + (lane & 3)*2;
            float b0 = bias[col], b1 = bias[col+1];
            float v00 = (acc[mt][nt][0] + b0) * 0.0625f;
            float v01 = (acc[mt][nt][1] + b1) * 0.0625f;
            float v10 = (acc[mt][nt][2] + b0) * 0.0625f;
            float v11 = (acc[mt][nt][3] + b1) * 0.0625f;
            float m0c = fmaxf(v00, v10);
            float m1c = fmaxf(v01, v11);
#pragma unroll
            for (int off = 4; off <= 16; off <<= 1) {
                m0c = fmaxf(m0c, __shfl_xor_sync(FULL, m0c, off));
                m1c = fmaxf(m1c, __shfl_xor_sync(FULL, m1c, off));
            }
            float e00 = expf(v00 - m0c), e10 = expf(v10 - m0c);
            float e01 = expf(v01 - m1c), e11 = expf(v11 - m1c);
            float s0 = e00 + e10, s1 = e01 + e11;
#pragma unroll
            for (int off = 4; off <= 16; off <<= 1) {
                s0 += __shfl_xor_sync(FULL, s0, off);
                s1 += __shfl_xor_sync(FULL, s1, off);
            }
            float2 pa = *(const float2*)(pos  + (size_t)ra*COUT + col);
            float2 pb = *(const float2*)(pos  + (size_t)rb*COUT + col);
            float2 va = *(const float2*)(vall + (size_t)kna*COUT + col);
            float2 vb = *(const float2*)(vall + (size_t)knb*COUT + col);
            float w0 = e00*(va.x + pa.x) + e10*(vb.x + pb.x);
            float w1 = e01*(va.y + pa.y) + e11*(vb.y + pb.y);
#pragma unroll
            for (int off = 4; off <= 16; off <<= 1) {
                w0 += __shfl_xor_sync(FULL, w0, off);
                w1 += __shfl_xor_sync(FULL, w1, off);
            }
            if (quad == 0) {
                float o0 = w0 / s0, o1 = w1 / s1;
                uint32_t h, l;
                split2(o0, o1, h, l);
                *(uint32_t*)&R0hi[(size_t)bs*COUT + col] = h;
                *(uint32_t*)&R0lo[(size_t)bs*COUT + col] = l;
            }
        }
    }
}

// ------ FUSED kernel 1 block ranges ------------------------------------------
#define CVT_PTS_B    (NPTS*CIN/2048)
#define CVT_WSM_B    (CIN*COUT/2048)
#define CVT_WBG_B    (COUT*COUT/2048)
#define CVT_PRE_TOT  (CVT_PTS_B + 2*CVT_WSM_B)
#define KV_BLOCKS    (8 * (NPTS/128))
#define CVT_POST_TOT (CVT_WSM_B + 4*CVT_WBG_B)
#define KNN_BLOCKS   (BSR/8)
#define Q_BLOCKS     (4 * (BSR/128))
#define H1_BLOCKS    (MROWS/128)

#define B_CVTPRE   8
#define B_KV       (B_CVTPRE + CVT_PRE_TOT)
#define B_CVTPOST  (B_KV + KV_BLOCKS)
#define B_KNN      (B_CVTPOST + CVT_POST_TOT)
#define B_Q        (B_KNN + KNN_BLOCKS)
#define B_H1       (B_Q + Q_BLOCKS)
#define FUSED_GRID (B_H1 + H1_BLOCKS)

__global__ __launch_bounds__(256, 2) void fused_all(
    const float* __restrict__ xyz, float* __restrict__ newxyz,
    const float* __restrict__ points,
    const float* __restrict__ wk, const float* __restrict__ wv,
    const float* __restrict__ wq, const float* __restrict__ dw2,
    const float* __restrict__ gw1, const float* __restrict__ gw2,
    const float* __restrict__ lw,
    const float* __restrict__ dw1, const float* __restrict__ db1)
{
    const int bid = blockIdx.x;
    const int tid = threadIdx.x;

    if (bid < 8) {
        // ------------------------- FPS -------------------------------------
        extern __shared__ char smtop[];
        float* sx = (float*)smtop;
        float* sy = sx + NN;
        float* sz = sy + NN;
        unsigned long long* swk = (unsigned long long*)(smtop + 3*NN*4);

        int b = bid;
        int lane = tid & 31, wid = tid >> 5;
        const float* base = xyz + (size_t)b * NN * 3;

        for (int i = tid; i < NN; i += 256) {
            sx[i] = base[i*3+0];
            sy[i] = base[i*3+1];
            sz[i] = base[i*3+2];
        }
        __syncthreads();

        float px[16], py[16], pz[16], dist[16];
#pragma unroll
        for (int j = 0; j < 16; j++) {
            int i = tid * 16 + j;
            px[j] = sx[i]; py[j] = sy[i]; pz[j] = sz[i];
            dist[j] = 1e10f;
        }

        int far = 0;
        for (int s = 0; s < SS; s++) {
            float cx = sx[far], cy = sy[far], cz = sz[far];
            if (tid == 0) {
                g_fps[b*SS + s] = b*NN + far;
                newxyz[((size_t)b*SS + s)*3 + 0] = cx;
                newxyz[((size_t)b*SS + s)*3 + 1] = cy;
                newxyz[((size_t)b*SS + s)*3 + 2] = cz;
                if ((s & 31) == 31) {
                    __threadfence();
                    atomicExch(&g_prog[b], s + 1);
                }
            }
#pragma unroll
            for (int j = 0; j < 16; j++) {
                float dx = __fsub_rn(px[j], cx);
                float dy = __fsub_rn(py[j], cy);
                float dz = __fsub_rn(pz[j], cz);
                float d  = __fadd_rn(__fadd_rn(__fmul_rn(dx,dx), __fmul_rn(dy,dy)),
                                     __fmul_rn(dz,dz));
                dist[j] = fminf(dist[j], d);
            }
            float m8[8];
#pragma unroll
            for (int j = 0; j < 8; j++) m8[j] = fmaxf(dist[j], dist[j+8]);
#pragma unroll
            for (int j = 0; j < 4; j++) m8[j] = fmaxf(m8[j], m8[j+4]);
            float bv = fmaxf(fmaxf(m8[0], m8[1]), fmaxf(m8[2], m8[3]));
            unsigned match = 0;
#pragma unroll
            for (int j = 0; j < 16; j++) match |= (dist[j] == bv) ? (1u << j) : 0u;
            int bi = tid*16 + (__ffs(match) - 1);

            unsigned key  = __float_as_uint(bv);
            unsigned wmax = __reduce_max_sync(0xffffffffu, key);
            unsigned ball = __ballot_sync(0xffffffffu, key == wmax);
            int src  = __ffs(ball) - 1;
            int wbi  = __shfl_sync(0xffffffffu, bi, src);
            if (lane == 0)
                swk[(s & 1)*8 + wid] = ((unsigned long long)wmax << 32)
                                     | (unsigned)(NN - 1 - wbi);
            __syncthreads();
            unsigned long long best = swk[(s & 1)*8 + 0];
#pragma unroll
            for (int w = 1; w < 8; w++) {
                unsigned long long c = swk[(s & 1)*8 + w];
                if (c > best) best = c;
            }
            far = NN - 1 - (int)(best & 0xffffffffu);
        }
        return;
    }

    if (bid < B_KV) {
        int cb = bid - B_CVTPRE;
        if (cb < CVT_PTS_B)               cvt_block_wide(points, g_ph, g_pl, cb, tid);
        else if (cb < CVT_PTS_B + CVT_WSM_B)
            cvt_block_wide(wk, g_wkh, g_wkl, cb - CVT_PTS_B, tid);
        else
            cvt_block_wide(wv, g_wvh, g_wvl, cb - CVT_PTS_B - CVT_WSM_B, tid);
        __syncthreads();
        if (tid == 0) { __threadfence(); atomicAdd(&g_cvtcnt, 1); }
        return;
    }

    if (bid < B_CVTPOST) {
        // -------------------- merged k/v GEMM (polls cvtcnt) ----------------
        if (tid == 0) { while (ld_acquire(&g_cvtcnt) < CVT_PRE_TOT) { } }
        const int idx = bid - B_KV;
        const int bx  = idx & 7;
        const int m0  = (idx >> 3) * 128;
        const int n0  = (bx & 3) * 64;
        const bf16* WhiS = (bx < 4) ? g_wkh : g_wvh;
        const bf16* WloS = (bx < 4) ? g_wkl : g_wvl;
        float* CS = (bx < 4) ? g_kall : g_vall;
        const int Kd = CIN;
        const int* rowmap = nullptr;

        GEMM_MAINLOOP(g_ph, g_pl, rowmap, WhiS, WloS)

        const int quad = lane >> 2, tq = lane & 3;
#pragma unroll
        for (int mt = 0; mt < 2; mt++) {
            int r0 = m0 + wm*32 + mt*16 + quad;
            int r1 = r0 + 8;
#pragma unroll
            for (int nt = 0; nt < 4; nt++) {
                int col = n0 + wn*32 + nt*8 + tq*2;
                *(float2*)(CS + (size_t)r0*COUT + col) =
                    make_float2(acc[mt][nt][0], acc[mt][nt][1]);
                *(float2*)(CS + (size_t)r1*COUT + col) =
                    make_float2(acc[mt][nt][2], acc[mt][nt][3]);
            }
        }
        return;
    }

    if (bid < B_KNN) {
        int cb = bid - B_CVTPOST;
        if (cb < CVT_WSM_B) { cvt_block_wide(wq, g_wqh, g_wql, cb, tid); return; }
        cb -= CVT_WSM_B;
        if (cb < CVT_WBG_B) { cvt_block_wide(dw2, g_dw2h, g_dw2l, cb, tid); return; }
        cb -= CVT_WBG_B;
        if (cb < CVT_WBG_B) { cvt_block_wide(gw1, g_gw1h, g_gw1l, cb, tid); return; }
        cb -= CVT_WBG_B;
        if (cb < CVT_WBG_B) { cvt_block_wide(gw2, g_gw2h, g_gw2l, cb, tid); return; }
        cb -= CVT_WBG_B;
        cvt_block_wide(lw, g_lwh, g_lwl, cb, tid);
        return;
    }

    if (bid < B_Q) {
        // ------------- KNN (polls FPS progress, commits kprog) ---------------
        extern __shared__ char smk[];
        float (*smd)[512] = (float(*)[512])smk;
        int   (*smi)[512] = (int(*)[512])(smk + 8*512*4);

        const int kb   = bid - B_KNN;
        const int lane = tid & 31;
        const int wloc = tid >> 5;
        const int b    = kb & 7;
        const int s0   = (kb >> 3) * 8;
        const int s    = s0 + wloc;
        const int warp = b * SS + s;
        const float* base = xyz + (size_t)b * NN * 3;

        if (lane == 0) {
            while (ld_acquire(&g_prog[b]) <= s) { }
        }
        __syncwarp();

        float nx = __ldcg(newxyz + (size_t)warp*3 + 0);
        float ny = __ldcg(newxyz + (size_t)warp*3 + 1);
        float nz = __ldcg(newxyz + (size_t)warp*3 + 2);
        float ns = fmaf(nz, nz, fmaf(ny, ny, __fmul_rn(nx, nx)));

        float v[16]; int id[16];
#pragma unroll
        for (int t = 0; t < 16; t++) { v[t] = 3.4e38f; id[t] = 0x7fffffff; }

        for (int j = lane; j < NN; j += 32) {
            float x = base[j*3+0], y = base[j*3+1], z = base[j*3+2];
            float dot = fmaf(z, nz, fmaf(y, ny, __fmul_rn(x, nx)));
            float nq  = fmaf(z, z,  fmaf(y, y,  __fmul_rn(x, x)));
            float d   = __fadd_rn(__fsub_rn(ns, __fmul_rn(2.0f, dot)), nq);
            if (d < v[15]) {
                v[15] = d; id[15] = j;
#pragma unroll
                for (int t = 15; t > 0; t--) {
                    if (v[t] < v[t-1] || (v[t] == v[t-1] && id[t] < id[t-1])) {
                        float tv = v[t]; v[t] = v[t-1]; v[t-1] = tv;
                        int   ti = id[t]; id[t] = id[t-1]; id[t-1] = ti;
                    } else break;
                }
            }
        }

#pragma unroll
        for (int t = 0; t < 16; t++) {
            smd[wloc][lane*16 + t] = v[t];
            smi[wloc][lane*16 + t] = id[t];
        }
        __syncwarp();

        int p = 0;
        for (int t = 0; t < 16; t++) {
            float cv = (p < 16) ? smd[wloc][lane*16 + p] : 3.4e38f;
            int   ci = (p < 16) ? smi[wloc][lane*16 + p] : 0x7fffffff;
            float mv = cv; int mi = ci;
#pragma unroll
            for (int off = 16; off; off >>= 1) {
                float ov = __shfl_xor_sync(0xffffffffu, mv, off);
                int   oi = __shfl_xor_sync(0xffffffffu, mi, off);
                if (ov < mv || (ov == mv && oi < mi)) { mv = ov; mi = oi; }
            }
            if (cv == mv && ci == mi) p++;
            if (lane == 0) g_knn[(size_t)warp*16 + t] = b*NN + mi;
            __syncwarp();
        }

        __syncthreads();
        if (tid == 0) {
            while (ld_acquire(&g_kprog[b]) != s0) { }
            __threadfence();
            atomicExch(&g_kprog[b], s0 + 8);
        }
        return;
    }

    if (bid < B_H1) {
        // -------------- q GEMM = gather(points, fps) @ wq (polls prog) -------
        const int idx = bid - B_Q;
        const int n0  = (idx & 3) * 64;
        const int m0  = (idx >> 2) * 128;
        const int b   = m0 >> 10;
        const int s_need = (m0 & 1023) + 128;
        if (tid == 0) { while (ld_acquire(&g_prog[b]) < s_need) { } }
        const int Kd = CIN;
        const int* fps_ptr = g_fps;

        GEMM_MAINLOOP(g_ph, g_pl, fps_ptr, g_wqh, g_wql)

        const int quad = lane >> 2, tq = lane & 3;
#pragma unroll
        for (int mt = 0; mt < 2; mt++) {
            int r0 = m0 + wm*32 + mt*16 + quad;
            int r1 = r0 + 8;
#pragma unroll
            for (int nt = 0; nt < 4; nt++) {
                int col = n0 + wn*32 + nt*8 + tq*2;
                *(float2*)(g_q + (size_t)r0*COUT + col) =
                    make_float2(acc[mt][nt][0], acc[mt][nt][1]);
                *(float2*)(g_q + (size_t)r1*COUT + col) =
                    make_float2(acc[mt][nt][2], acc[mt][nt][3]);
            }
        }
        return;
    }

    // ----------------- h1 pos-enc layer 1 (polls kprog) ----------------------
    {
        const int hb = bid - B_H1;
        const int b  = hb >> 7;
        const int s_need = ((hb * 8) & 1023) + 8;
        if (tid == 0) { while (ld_acquire(&g_kprog[b]) < s_need) { } }
        __syncthreads();

        const int col    = (tid & 127) * 2;
        const int rowsel = tid >> 7;
        const float w0a = dw1[col],        w0b = dw1[col+1];
        const float w1a = dw1[COUT+col],   w1b = dw1[COUT+col+1];
        const float w2a = dw1[2*COUT+col], w2b = dw1[2*COUT+col+1];
        const float b0  = db1[col],        b1  = db1[col+1];

        for (int rr = 0; rr < 64; rr++) {
            int r  = hb*128 + rr*2 + rowsel;
            int g  = __ldcg(&g_knn[r]);
            int bs = r >> 4;
            float cx = __ldcg(&xyz[(size_t)g*3+0]) - __ldcg(&newxyz[(size_t)bs*3+0]);
            float cy = __ldcg(&xyz[(size_t)g*3+1]) - __ldcg(&newxyz[(size_t)bs*3+1]);
            float cz = __ldcg(&xyz[(size_t)g*3+2]) - __ldcg(&newxyz[(size_t)bs*3+2]);
            float h0 = b0, h1v = b1;
            h0  = fmaf(cx, w0a, h0);  h0  = fmaf(cy, w1a, h0);  h0  = fmaf(cz, w2a, h0);
            h1v = fmaf(cx, w0b, h1v); h1v = fmaf(cy, w1b, h1v); h1v = fmaf(cz, w2b, h1v);
            h0  = fmaxf(h0, 0.0f);
            h1v = fmaxf(h1v, 0.0f);
            uint32_t h, l;
            split2(h0, h1v, h, l);
            *(uint32_t*)&g_x1h[(size_t)r*COUT + col] = h;
            *(uint32_t*)&g_x1l[(size_t)r*COUT + col] = l;
        }
    }
}

// ------ FUSED kernel 2: a1 -> h2 -> att -> lw -> BN (poll-chained) ----------
#define M2_H2   4096
#define M2_ATT  8192
#define M2_LW   12288
#define M2_BNP  (M2_LW + 256)
#define M2_BNA  (M2_BNP + 64)
#define M2_GRID (M2_BNA + 16)

__global__ __launch_bounds__(256, 2) void mega_mlp(
    const float* __restrict__ db2, const float* __restrict__ gb1,
    const float* __restrict__ gb2, const float* __restrict__ lb,
    const float* __restrict__ bng, const float* __restrict__ bnb,
    float* __restrict__ res_out)
{
    const int bid = blockIdx.x;
    const int tid = threadIdx.x;

    if (bid < M2_H2) {
        // a1 GEMM: pos = h1@dw2+db2 (fp32) + fused a1 = q - k_gather + pos
        const int idx = bid;
        const int n0  = (idx & 3) * 64;
        const int m0  = (idx >> 2) * 128;
        gemm_body(tid, m0, n0, COUT, g_x1h, g_x1l, nullptr,
                  g_dw2h, g_dw2l, db2, 0,
                  g_pos, nullptr, nullptr,
                  g_q, g_kall, g_knn, g_a1h, g_a1l);
        __syncthreads();
        if (tid == 0) { __threadfence(); atomicAdd(&g_c1[m0 >> 7], 1); }
        return;
    }

    if (bid < M2_ATT) {
        // h2 = relu(a1@gw1+gb1) -> x1 (bf16 split)
        const int idx = bid - M2_H2;
        const int n0  = (idx & 3) * 64;
        const int m0  = (idx >> 2) * 128;
        if (tid == 0) { while (ld_acquire(&g_c1[m0 >> 7]) < 4) { } }
        gemm_body(tid, m0, n0, COUT, g_a1h, g_a1l, nullptr,
                  g_gw1h, g_gw1l, gb1, 1,
                  nullptr, g_x1h, g_x1l,
                  nullptr, nullptr, nullptr, nullptr, nullptr);
        __syncthreads();
        if (tid == 0) { __threadfence(); atomicAdd(&g_c2[m0 >> 7], 1); }
        return;
    }

    if (bid < M2_LW) {
        // att GEMM + fused softmax/weighted sum -> r0 (bf16 split)
        const int idx = bid - M2_ATT;
        const int n0  = (idx & 3) * 64;
        const int m0  = (idx >> 2) * 128;
        if (tid == 0) { while (ld_acquire(&g_c2[m0 >> 7]) < 4) { } }
        gemm_att_body(tid, m0, n0, COUT, g_x1h, g_x1l,
                      g_gw2h, g_gw2l, gb2, g_knn, g_pos, g_vall,
                      g_r0h, g_r0l);
        __syncthreads();
        if (tid == 0) { __threadfence(); atomicAdd(&g_c3[m0 >> 11], 1); }
        return;
    }

    if (bid < M2_BNP) {
        // lw GEMM: res1 = r0@lw + lb
        const int idx = bid - M2_LW;
        const int n0  = (idx & 3) * 64;
        const int m0  = (idx >> 2) * 128;
        if (tid == 0) { while (ld_acquire(&g_c3[m0 >> 7]) < 64) { } }
        gemm_body(tid, m0, n0, COUT, g_r0h, g_r0l, nullptr,
                  g_lwh, g_lwl, lb, 0,
                  g_res1, nullptr, nullptr,
                  nullptr, nullptr, nullptr, nullptr, nullptr);
        __syncthreads();
        if (tid == 0) { __threadfence(); atomicAdd(&g_c4a[m0 >> 7], 1); }
        return;
    }

    if (bid < M2_BNA) {
        // BN partial sums over 128-row slab
        const int blk = bid - M2_BNP;
        if (tid == 0) { while (ld_acquire(&g_c4a[blk]) < 4) { } }
        __syncthreads();
        const int c = tid;
        float s = 0.0f, q = 0.0f;
        for (int r = blk*128; r < blk*128 + 128; r++) {
            float x = g_res1[(size_t)r*COUT + c];
            s += x; q = fmaf(x, x, q);
        }
        g_psum[blk*COUT + c] = s;
        g_psq [blk*COUT + c] = q;
        __syncthreads();
        if (tid == 0) { __threadfence(); atomicAdd(&g_c5, 1); }
        return;
    }

    // BN finalize + apply (each block recomputes scale/shift, applies a slab)
    {
        const int kb = bid - M2_BNA;           // 0..15
        if (tid == 0) { while (ld_acquire(&g_c5) < 64) { } }
        __syncthreads();
        extern __shared__ char smraw[];
        float* ssc = (float*)smraw;            // [256]
        float* ssh = ssc + 256;                // [256]
        {
            float s = 0.0f, q = 0.0f;
            for (int i = 0; i < 64; i++) {
                s += g_psum[i*COUT + tid];
                q += g_psq [i*COUT + tid];
            }
            float mean = s * (1.0f/(float)BSR);
            float var  = fmaxf(q * (1.0f/(float)BSR) - mean*mean, 0.0f);
            float sc   = bng[tid] * rsqrtf(var + 1e-5f);
            ssc[tid] = sc;
            ssh[tid] = bnb[tid] - mean * sc;
        }
        __syncthreads();
        const int c4i = tid & 63;
        float4 sc4 = ((const float4*)ssc)[c4i];
        float4 sh4 = ((const float4*)ssh)[c4i];
        const float4* in4  = (const float4*)g_res1;
        float4*       out4 = (float4*)res_out;
        size_t base = (size_t)kb * 32768;      // float4 units: 524288/16
        for (int i = 0; i < 128; i++) {
            size_t f = base + (size_t)i*256 + tid;
            float4 x = in4[f];
            float4 o;
            o.x = fmaxf(fmaf(x.x, sc4.x, sh4.x), 0.0f);
            o.y = fmaxf(fmaf(x.y, sc4.y, sh4.y), 0.0f);
            o.z = fmaxf(fmaf(x.z, sc4.z, sh4.z), 0.0f);
            o.w = fmaxf(fmaf(x.w, sc4.w, sh4.w), 0.0f);
            out4[f] = o;
        }
    }
}

// ------------------------------ launch --------------------------------------
extern "C" void kernel_launch(void* const* d_in, const int* in_sizes, int n_in,
                              void* d_out, int out_size)
{
    const float* xyz    = (const float*)d_in[0];
    const float* points = (const float*)d_in[1];
    const float* wq     = (const float*)d_in[2];
    const float* wk     = (const float*)d_in[3];
    const float* wv     = (const float*)d_in[4];
    const float* dw1    = (const float*)d_in[5];
    const float* db1    = (const float*)d_in[6];
    const float* dw2    = (const float*)d_in[7];
    const float* db2    = (const float*)d_in[8];
    const float* gw1    = (const float*)d_in[9];
    const float* gb1    = (const float*)d_in[10];
    const float* gw2    = (const float*)d_in[11];
    const float* gb2    = (const float*)d_in[12];
    const float* lw     = (const float*)d_in[13];
    const float* lb     = (const float*)d_in[14];
    const float* bng    = (const float*)d_in[15];
    const float* bnb    = (const float*)d_in[16];

    float* out     = (float*)d_out;
    float* newxyz  = out;
    float* res_out = out + (size_t)BSR*3;

    static bool attr_set = false;
    if (!attr_set) {
        cudaFuncSetAttribute(fused_all, cudaFuncAttributeMaxDynamicSharedMemorySize, TG_SMEM);
        cudaFuncSetAttribute(mega_mlp,  cudaFuncAttributeMaxDynamicSharedMemorySize, TG_SMEM);
        attr_set = true;
    }

    // 1: reset progress counters (graph-replay safe)
    reset_prog_kernel<<<8, 256>>>();
    // 2: FPS || pre-cvts || kv GEMM || post-cvts || KNN || q GEMM || h1
    fused_all<<<FUSED_GRID, 256, TG_SMEM>>>(xyz, newxyz, points, wk, wv,
                                            wq, dw2, gw1, gw2, lw, dw1, db1);
    // 3: a1 -> h2 -> att(+softmax) -> lw -> BN, poll-chained in one launch
    mega_mlp<<<M2_GRID, 256, TG_SMEM>>>(db2, gb1, gb2, lb, bng, bnb, res_out);
}

// round 16
// speedup vs baseline: 1.1202x; 1.0040x over previous
#include <cuda_runtime.h>
#include <cuda_bf16.h>
#include <math.h>
#include <stdint.h>

#define BB   8
#define NN   4096
#define SS   1024
#define KNBR 16
#define CIN  128
#define COUT 256
#define MROWS (BB*SS*KNBR)   /* 131072 */
#define BSR   (BB*SS)        /* 8192  */
#define NPTS  (BB*NN)        /* 32768 */

typedef __nv_bfloat16 bf16;

// ---------------- static device scratch (no allocs allowed) ----------------
__device__ float g_pos [(size_t)MROWS*COUT];
__device__ bf16  g_a1h [(size_t)MROWS*COUT];
__device__ bf16  g_a1l [(size_t)MROWS*COUT];
__device__ bf16  g_x1h [(size_t)MROWS*COUT];   // h1 then h2
__device__ bf16  g_x1l [(size_t)MROWS*COUT];
__device__ bf16  g_ph  [(size_t)NPTS*CIN];
__device__ bf16  g_pl  [(size_t)NPTS*CIN];
__device__ float g_kall[(size_t)NPTS*COUT];
__device__ float g_vall[(size_t)NPTS*COUT];
__device__ float g_q   [(size_t)BSR*COUT];
__device__ bf16  g_r0h [(size_t)BSR*COUT];
__device__ bf16  g_r0l [(size_t)BSR*COUT];
__device__ float g_res1[(size_t)BSR*COUT];
__device__ int   g_fps [BSR];
__device__ int   g_knn [MROWS];
__device__ int   g_prog[BB];
__device__ int   g_kprog[BB];
__device__ int   g_cvtcnt;
__device__ int   g_kwc[BB];            // kall per-batch block count (128 each)
__device__ int   g_vwc[BB];            // vall per-batch block count (128 each)
__device__ int   g_qc [BSR/128];       // q per-m-tile n-block count (4 each)
__device__ int   g_hc [MROWS/128];     // h1 per-tile done flag
__device__ int   g_c1[MROWS/128];
__device__ int   g_c2[MROWS/128];
__device__ int   g_c3[BSR/128];
__device__ int   g_c4a[BSR/128];
__device__ int   g_c5;
__device__ float g_psum[64*COUT];
__device__ float g_psq [64*COUT];
// pre-split weights
__device__ bf16  g_wkh[CIN*COUT],  g_wkl[CIN*COUT];
__device__ bf16  g_wvh[CIN*COUT],  g_wvl[CIN*COUT];
__device__ bf16  g_wqh[CIN*COUT],  g_wql[CIN*COUT];
__device__ bf16  g_dw2h[COUT*COUT], g_dw2l[COUT*COUT];
__device__ bf16  g_gw1h[COUT*COUT], g_gw1l[COUT*COUT];
__device__ bf16  g_gw2h[COUT*COUT], g_gw2l[COUT*COUT];
__device__ bf16  g_lwh[COUT*COUT],  g_lwl[COUT*COUT];

// -------------------- bf16 split helper ------------------------------------
__device__ __forceinline__ void split2(float x0, float x1, uint32_t& hi, uint32_t& lo)
{
    bf16 h0 = __float2bfloat16(x0);
    bf16 h1 = __float2bfloat16(x1);
    float r0 = __fsub_rn(x0, __bfloat162float(h0));
    float r1 = __fsub_rn(x1, __bfloat162float(h1));
    bf16 l0 = __float2bfloat16(r0);
    bf16 l1 = __float2bfloat16(r1);
    hi = (uint32_t)__bfloat16_as_ushort(h0) | ((uint32_t)__bfloat16_as_ushort(h1) << 16);
    lo = (uint32_t)__bfloat16_as_ushort(l0) | ((uint32_t)__bfloat16_as_ushort(l1) << 16);
}

__device__ __forceinline__ int ld_acquire(const int* p)
{
    int v;
    asm volatile("ld.acquire.gpu.global.b32 %0, [%1];" : "=r"(v) : "l"(p));
    return v;
}

// ---------------- wide fp32 -> bf16 hi/lo conversion (8 elems/thread) -------
__device__ __forceinline__ void cvt_block_wide(const float* __restrict__ src,
                                               bf16* __restrict__ hi, bf16* __restrict__ lo,
                                               int local_bid, int tid)
{
    int e = (local_bid * 256 + tid) * 8;
    float4 a = *(const float4*)(src + e);
    float4 c = *(const float4*)(src + e + 4);
    uint32_t h0,l0,h1,l1,h2,l2,h3,l3;
    split2(a.x, a.y, h0, l0); split2(a.z, a.w, h1, l1);
    split2(c.x, c.y, h2, l2); split2(c.z, c.w, h3, l3);
    uint4 H; H.x = h0; H.y = h1; H.z = h2; H.w = h3;
    uint4 L; L.x = l0; L.y = l1; L.z = l2; L.w = l3;
    *(uint4*)&hi[e] = H;
    *(uint4*)&lo[e] = L;
}

__global__ void reset_prog_kernel()
{
    int t = blockIdx.x * 256 + threadIdx.x;   // <<<16,256>>> = 4096
    if (t < 1024) { g_c1[t] = 0; g_c2[t] = 0; g_hc[t] = 0; }
    int u = t - 1024;
    if (u >= 0) {
        if (u < 64)                   g_c3[u] = 0;
        else if (u < 128)             g_c4a[u-64] = 0;
        else if (u < 192)             g_qc[u-128] = 0;
        else if (u == 192)            g_c5 = 0;
        else if (u >= 200 && u < 208) g_prog[u-200] = 0;
        else if (u >= 208 && u < 216) g_kprog[u-208] = 0;
        else if (u >= 216 && u < 224) g_kwc[u-216] = 0;
        else if (u >= 224 && u < 232) g_vwc[u-224] = 0;
        else if (u == 232)            g_cvtcnt = 0;
    }
}

// ------------------------- mma helpers --------------------------------------
__device__ __forceinline__ void cp16(void* s, const void* g)
{
    unsigned sa = (unsigned)__cvta_generic_to_shared(s);
    asm volatile("cp.async.ca.shared.global [%0], [%1], 16;\n" :: "r"(sa), "l"(g));
}
#define CP_COMMIT() asm volatile("cp.async.commit_group;\n")

__device__ __forceinline__ void ldsm_x4(uint32_t* r, const void* p)
{
    uint32_t a = (uint32_t)__cvta_generic_to_shared(p);
    asm volatile("ldmatrix.sync.aligned.m8n8.x4.shared.b16 {%0,%1,%2,%3}, [%4];"
                 : "=r"(r[0]), "=r"(r[1]), "=r"(r[2]), "=r"(r[3]) : "r"(a));
}

__device__ __forceinline__ void ldsm_x4_t(uint32_t* r, const void* p)
{
    uint32_t a = (uint32_t)__cvta_generic_to_shared(p);
    asm volatile("ldmatrix.sync.aligned.m8n8.x4.trans.shared.b16 {%0,%1,%2,%3}, [%4];"
                 : "=r"(r[0]), "=r"(r[1]), "=r"(r[2]), "=r"(r[3]) : "r"(a));
}

__device__ __forceinline__ void mma16816(float* c, const uint32_t* a, const uint32_t* b)
{
    asm volatile("mma.sync.aligned.m16n8k16.row.col.f32.bf16.bf16.f32 "
                 "{%0,%1,%2,%3}, {%4,%5,%6,%7}, {%8,%9}, {%0,%1,%2,%3};"
                 : "+f"(c[0]), "+f"(c[1]), "+f"(c[2]), "+f"(c[3])
                 : "r"(a[0]), "r"(a[1]), "r"(a[2]), "r"(a[3]),
                   "r"(b[0]), "r"(b[1]));
}

// ----------------------- shared GEMM mainloop macro (128x64, 4-stage) -------
#define KCH    16
#define NSTG   4
#define ASTR2  24
#define BSTR2  72
#define AS_BYTES  (NSTG*2*128*ASTR2*2)
#define BS_BYTES  (NSTG*2*KCH*BSTR2*2)
#define TG_SMEM   (AS_BYTES + BS_BYTES + 512)

#define GEMM_MAINLOOP(AHI, ALO, ROWMAP, WHI, WLO)                               \
    extern __shared__ char smraw[];                                            \
    typedef bf16 (*AsT)[2][128][ASTR2];                                        \
    typedef bf16 (*BsT)[2][KCH][BSTR2];                                        \
    AsT As = (AsT)smraw;                                                       \
    BsT Bs = (BsT)(smraw + AS_BYTES);                                          \
    int* rmap = (int*)(smraw + AS_BYTES + BS_BYTES);                           \
    if (tid < 128) rmap[tid] = (ROWMAP) ? __ldcg((ROWMAP) + m0 + tid) : (m0 + tid); \
    __syncthreads();                                                           \
    const int arow = tid >> 1;                                                 \
    const int ach  = (tid & 1) * 8;                                            \
    const bf16* aSrcH = (AHI) + (size_t)rmap[arow] * Kd + ach;                 \
    const bf16* aSrcL = (ALO) + (size_t)rmap[arow] * Kd + ach;                 \
    const int bpl = tid >> 7;                                                  \
    const int bk  = (tid >> 3) & 15;                                           \
    const int bch = (tid & 7) * 8;                                             \
    const bf16* bSrc = (bpl ? (WLO) : (WHI)) + (size_t)bk * COUT + n0 + bch;   \
    const int lane = tid & 31;                                                 \
    const int wm = (tid >> 5) >> 1;                                            \
    const int wn = (tid >> 5) & 1;                                             \
    const int aFrow = wm * 32 + (lane & 15);                                   \
    const int aFk   = (lane >> 4) * 8;                                         \
    const int bFk   = (lane & 7) + ((lane >> 3) & 1) * 8;                      \
    const int bFn   = (lane >> 4) * 8;                                         \
    float acc[2][4][4];                                                        \
    _Pragma("unroll")                                                          \
    for (int i = 0; i < 2; i++)                                                \
        _Pragma("unroll")                                                      \
        for (int j = 0; j < 4; j++)                                            \
            _Pragma("unroll")                                                  \
            for (int l = 0; l < 4; l++) acc[i][j][l] = 0.0f;                   \
    const int nk = Kd >> 4;                                                    \
    _Pragma("unroll")                                                          \
    for (int s = 0; s < NSTG - 1; s++) {                                       \
        if (s < nk) {                                                          \
            int k0 = s * KCH;                                                  \
            cp16(&As[s][0][arow][ach], aSrcH + k0);                            \
            cp16(&As[s][1][arow][ach], aSrcL + k0);                            \
            cp16(&Bs[s][bpl][bk][bch], bSrc + (size_t)k0 * COUT);              \
        }                                                                      \
        CP_COMMIT();                                                           \
    }                                                                          \
    for (int t = 0; t < nk; t++) {                                             \
        const int cur = t & (NSTG - 1);                                        \
        if (t + NSTG - 1 < nk) {                                               \
            asm volatile("cp.async.wait_group 2;\n" ::: "memory");             \
        } else {                                                               \
            asm volatile("cp.async.wait_group 0;\n" ::: "memory");             \
        }                                                                      \
        __syncthreads();                                                       \
        if (t + NSTG - 1 < nk) {                                               \
            const int stg = (t + NSTG - 1) & (NSTG - 1);                       \
            const int k0  = (t + NSTG - 1) * KCH;                              \
            cp16(&As[stg][0][arow][ach], aSrcH + k0);                          \
            cp16(&As[stg][1][arow][ach], aSrcL + k0);                          \
            cp16(&Bs[stg][bpl][bk][bch], bSrc + (size_t)k0 * COUT);            \
            CP_COMMIT();                                                       \
        }                                                                      \
        uint32_t ah[2][4], al[2][4], bh[4][2], bl[4][2];                       \
        _Pragma("unroll")                                                      \
        for (int mt = 0; mt < 2; mt++) {                                       \
            ldsm_x4(ah[mt], &As[cur][0][aFrow + mt*16][aFk]);                  \
            ldsm_x4(al[mt], &As[cur][1][aFrow + mt*16][aFk]);                  \
        }                                                                      \
        _Pragma("unroll")                                                      \
        for (int g = 0; g < 2; g++) {                                          \
            uint32_t tmp[4];                                                   \
            ldsm_x4_t(tmp, &Bs[cur][0][bFk][wn*32 + g*16 + bFn]);              \
            bh[g*2][0]   = tmp[0]; bh[g*2][1]   = tmp[1];                      \
            bh[g*2+1][0] = tmp[2]; bh[g*2+1][1] = tmp[3];                      \
            ldsm_x4_t(tmp, &Bs[cur][1][bFk][wn*32 + g*16 + bFn]);              \
            bl[g*2][0]   = tmp[0]; bl[g*2][1]   = tmp[1];                      \
            bl[g*2+1][0] = tmp[2]; bl[g*2+1][1] = tmp[3];                      \
        }                                                                      \
        _Pragma("unroll")                                                      \
        for (int mt = 0; mt < 2; mt++)                                         \
            _Pragma("unroll")                                                  \
            for (int nt = 0; nt < 4; nt++) {                                   \
                mma16816(acc[mt][nt], ah[mt], bh[nt]);                         \
                mma16816(acc[mt][nt], al[mt], bh[nt]);                         \
                mma16816(acc[mt][nt], ah[mt], bl[nt]);                         \
            }                                                                  \
    }

// --------- GEMM body as device function (fp32 / bf16-split / a1 dual) -------
__device__ __forceinline__ void gemm_body(
    int tid, int m0, int n0, int Kd,
    const bf16* __restrict__ Ahi, const bf16* __restrict__ Alo,
    const int* __restrict__ rowmap,
    const bf16* __restrict__ Whi, const bf16* __restrict__ Wlo,
    const float* __restrict__ bias, int relu,
    float* __restrict__ C, bf16* __restrict__ Chi, bf16* __restrict__ Clo,
    const float* __restrict__ qv, const float* __restrict__ kall,
    const int* __restrict__ knn,
    bf16* __restrict__ A1hi, bf16* __restrict__ A1lo)
{
    GEMM_MAINLOOP(Ahi, Alo, rowmap, Whi, Wlo)

    const int quad = lane >> 2, tq = lane & 3;
#pragma unroll
    for (int mt = 0; mt < 2; mt++) {
        int r0 = m0 + wm*32 + mt*16 + quad;
        int r1 = r0 + 8;
        const float *q0 = nullptr, *k0p = nullptr, *q1 = nullptr, *k1p = nullptr;
        if (A1hi) {
            q0 = qv + (size_t)(r0 >> 4) * COUT;  k0p = kall + (size_t)knn[r0] * COUT;
            q1 = qv + (size_t)(r1 >> 4) * COUT;  k1p = kall + (size_t)knn[r1] * COUT;
        }
#pragma unroll
        for (int nt = 0; nt < 4; nt++) {
            int col = n0 + wn*32 + nt*8 + tq*2;
            float o0 = acc[mt][nt][0], o1 = acc[mt][nt][1];
            float o2 = acc[mt][nt][2], o3 = acc[mt][nt][3];
            if (bias) { float bb0 = bias[col], bb1 = bias[col+1];
                        o0 += bb0; o1 += bb1; o2 += bb0; o3 += bb1; }
            if (relu) { o0 = fmaxf(o0,0.f); o1 = fmaxf(o1,0.f);
                        o2 = fmaxf(o2,0.f); o3 = fmaxf(o3,0.f); }
            if (C) {
                *(float2*)(C + (size_t)r0*COUT + col) = make_float2(o0, o1);
                *(float2*)(C + (size_t)r1*COUT + col) = make_float2(o2, o3);
            }
            if (Chi) {
                uint32_t h, l;
                split2(o0, o1, h, l);
                *(uint32_t*)&Chi[(size_t)r0*COUT + col] = h;
                *(uint32_t*)&Clo[(size_t)r0*COUT + col] = l;
                split2(o2, o3, h, l);
                *(uint32_t*)&Chi[(size_t)r1*COUT + col] = h;
                *(uint32_t*)&Clo[(size_t)r1*COUT + col] = l;
            }
            if (A1hi) {
                float w0 = __fadd_rn(__fsub_rn(q0[col],   k0p[col]),   o0);
                float w1 = __fadd_rn(__fsub_rn(q0[col+1], k0p[col+1]), o1);
                float w2 = __fadd_rn(__fsub_rn(q1[col],   k1p[col]),   o2);
                float w3 = __fadd_rn(__fsub_rn(q1[col+1], k1p[col+1]), o3);
                uint32_t h, l;
                split2(w0, w1, h, l);
                *(uint32_t*)&A1hi[(size_t)r0*COUT + col] = h;
                *(uint32_t*)&A1lo[(size_t)r0*COUT + col] = l;
                split2(w2, w3, h, l);
                *(uint32_t*)&A1hi[(size_t)r1*COUT + col] = h;
                *(uint32_t*)&A1lo[(size_t)r1*COUT + col] = l;
            }
        }
    }
}

// --------- att GEMM body: fused per-group softmax + weighted sum ------------
__device__ __forceinline__ void gemm_att_body(
    int tid, int m0, int n0, int Kd,
    const bf16* __restrict__ Ahi, const bf16* __restrict__ Alo,
    const bf16* __restrict__ Whi, const bf16* __restrict__ Wlo,
    const float* __restrict__ bias,
    const int* __restrict__ knn,
    const float* __restrict__ pos, const float* __restrict__ vall,
    bf16* __restrict__ R0hi, bf16* __restrict__ R0lo)
{
    const int* rowmap = nullptr;
    GEMM_MAINLOOP(Ahi, Alo, rowmap, Whi, Wlo)

    const int quad = lane >> 2;
    const unsigned FULL = 0xffffffffu;
#pragma unroll
    for (int mt = 0; mt < 2; mt++) {
        int gr  = m0 + wm*32 + mt*16;
        int bs  = gr >> 4;
        int ra  = gr + quad;
        int rb  = ra + 8;
        int kna = knn[ra], knb = knn[rb];
#pragma unroll
        for (int nt = 0; nt < 4; nt++) {
            int col = n0 + wn*32 + nt*8 + (lane & 3)*2;
            float b0 = bias[col], b1 = bias[col+1];
            float v00 = (acc[mt][nt][0] + b0) * 0.0625f;
            float v01 = (acc[mt][nt][1] + b1) * 0.0625f;
            float v10 = (acc[mt][nt][2] + b0) * 0.0625f;
            float v11 = (acc[mt][nt][3] + b1) * 0.0625f;
            float m0c = fmaxf(v00, v10);
            float m1c = fmaxf(v01, v11);
#pragma unroll
            for (int off = 4; off <= 16; off <<= 1) {
                m0c = fmaxf(m0c, __shfl_xor_sync(FULL, m0c, off));
                m1c = fmaxf(m1c, __shfl_xor_sync(FULL, m1c, off));
            }
            float e00 = expf(v00 - m0c), e10 = expf(v10 - m0c);
            float e01 = expf(v01 - m1c), e11 = expf(v11 - m1c);
            float s0 = e00 + e10, s1 = e01 + e11;
#pragma unroll
            for (int off = 4; off <= 16; off <<= 1) {
                s0 += __shfl_xor_sync(FULL, s0, off);
                s1 += __shfl_xor_sync(FULL, s1, off);
            }
            float2 pa = *(const float2*)(pos  + (size_t)ra*COUT + col);
            float2 pb = *(const float2*)(pos  + (size_t)rb*COUT + col);
            float2 va = *(const float2*)(vall + (size_t)kna*COUT + col);
            float2 vb = *(const float2*)(vall + (size_t)knb*COUT + col);
            float w0 = e00*(va.x + pa.x) + e10*(vb.x + pb.x);
            float w1 = e01*(va.y + pa.y) + e11*(vb.y + pb.y);
#pragma unroll
            for (int off = 4; off <= 16; off <<= 1) {
                w0 += __shfl_xor_sync(FULL, w0, off);
                w1 += __shfl_xor_sync(FULL, w1, off);
            }
            if (quad == 0) {
                float o0 = w0 / s0, o1 = w1 / s1;
                uint32_t h, l;
                split2(o0, o1, h, l);
                *(uint32_t*)&R0hi[(size_t)bs*COUT + col] = h;
                *(uint32_t*)&R0lo[(size_t)bs*COUT + col] = l;
            }
        }
    }
}

// ------ UBER kernel block ranges ---------------------------------------------
#define CVT_PTS_B    (NPTS*CIN/2048)          /* 2048 */
#define CVT_WSM_B    (CIN*COUT/2048)          /* 16   */
#define CVT_WBG_B    (COUT*COUT/2048)         /* 32   */
#define CVT_PRE_TOT  (CVT_PTS_B + 2*CVT_WSM_B)
#define KV_BLOCKS    (8 * (NPTS/128))                     /* 2048 */
#define CVT_POST_TOT (CVT_WSM_B + 4*CVT_WBG_B)            /* 144  */
#define KNN_BLOCKS   (BSR/8)                              /* 1024 */
#define Q_BLOCKS     (4 * (BSR/128))                      /* 256  */
#define H1_BLOCKS    (MROWS/128)                          /* 1024 */
#define G_BLOCKS     (4 * (MROWS/128))                    /* 4096 */

#define B_CVTPRE   8
#define B_KV       (B_CVTPRE + CVT_PRE_TOT)
#define B_CVTPOST  (B_KV + KV_BLOCKS)
#define B_KNN      (B_CVTPOST + CVT_POST_TOT)
#define B_Q        (B_KNN + KNN_BLOCKS)
#define B_H1       (B_Q + Q_BLOCKS)
#define B_A1       (B_H1 + H1_BLOCKS)
#define B_H2       (B_A1 + G_BLOCKS)
#define B_ATT      (B_H2 + G_BLOCKS)
#define B_LW       (B_ATT + G_BLOCKS)
#define B_BNP      (B_LW + 256)
#define B_BNA      (B_BNP + 64)
#define UBER_GRID  (B_BNA + 16)

__global__ __launch_bounds__(256, 2) void uber(
    const float* __restrict__ xyz, float* __restrict__ newxyz,
    const float* __restrict__ points,
    const float* __restrict__ wk, const float* __restrict__ wv,
    const float* __restrict__ wq, const float* __restrict__ dw2,
    const float* __restrict__ gw1, const float* __restrict__ gw2,
    const float* __restrict__ lw,
    const float* __restrict__ dw1, const float* __restrict__ db1,
    const float* __restrict__ db2, const float* __restrict__ gb1,
    const float* __restrict__ gb2, const float* __restrict__ lb,
    const float* __restrict__ bng, const float* __restrict__ bnb,
    float* __restrict__ res_out)
{
    const int bid = blockIdx.x;
    const int tid = threadIdx.x;

    if (bid < 8) {
        // ------------------------- FPS -------------------------------------
        extern __shared__ char smtop[];
        float* sx = (float*)smtop;
        float* sy = sx + NN;
        float* sz = sy + NN;
        unsigned long long* swk = (unsigned long long*)(smtop + 3*NN*4);

        int b = bid;
        int lane = tid & 31, wid = tid >> 5;
        const float* base = xyz + (size_t)b * NN * 3;

        for (int i = tid; i < NN; i += 256) {
            sx[i] = base[i*3+0];
            sy[i] = base[i*3+1];
            sz[i] = base[i*3+2];
        }
        __syncthreads();

        float px[16], py[16], pz[16], dist[16];
#pragma unroll
        for (int j = 0; j < 16; j++) {
            int i = tid * 16 + j;
            px[j] = sx[i]; py[j] = sy[i]; pz[j] = sz[i];
            dist[j] = 1e10f;
        }

        int far = 0;
        for (int s = 0; s < SS; s++) {
            float cx = sx[far], cy = sy[far], cz = sz[far];
            if (tid == 0) {
                g_fps[b*SS + s] = b*NN + far;
                newxyz[((size_t)b*SS + s)*3 + 0] = cx;
                newxyz[((size_t)b*SS + s)*3 + 1] = cy;
                newxyz[((size_t)b*SS + s)*3 + 2] = cz;
                if ((s & 31) == 31) {
                    __threadfence();
                    atomicExch(&g_prog[b], s + 1);
                }
            }
#pragma unroll
            for (int j = 0; j < 16; j++) {
                float dx = __fsub_rn(px[j], cx);
                float dy = __fsub_rn(py[j], cy);
                float dz = __fsub_rn(pz[j], cz);
                float d  = __fadd_rn(__fadd_rn(__fmul_rn(dx,dx), __fmul_rn(dy,dy)),
                                     __fmul_rn(dz,dz));
                dist[j] = fminf(dist[j], d);
            }
            float m8[8];
#pragma unroll
            for (int j = 0; j < 8; j++) m8[j] = fmaxf(dist[j], dist[j+8]);
#pragma unroll
            for (int j = 0; j < 4; j++) m8[j] = fmaxf(m8[j], m8[j+4]);
            float bv = fmaxf(fmaxf(m8[0], m8[1]), fmaxf(m8[2], m8[3]));
            unsigned match = 0;
#pragma unroll
            for (int j = 0; j < 16; j++) match |= (dist[j] == bv) ? (1u << j) : 0u;
            int bi = tid*16 + (__ffs(match) - 1);

            unsigned key  = __float_as_uint(bv);
            unsigned wmax = __reduce_max_sync(0xffffffffu, key);
            unsigned ball = __ballot_sync(0xffffffffu, key == wmax);
            int src  = __ffs(ball) - 1;
            int wbi  = __shfl_sync(0xffffffffu, bi, src);
            if (lane == 0)
                swk[(s & 1)*8 + wid] = ((unsigned long long)wmax << 32)
                                     | (unsigned)(NN - 1 - wbi);
            __syncthreads();
            unsigned long long best = swk[(s & 1)*8 + 0];
#pragma unroll
            for (int w = 1; w < 8; w++) {
                unsigned long long c = swk[(s & 1)*8 + w];
                if (c > best) best = c;
            }
            far = NN - 1 - (int)(best & 0xffffffffu);
        }
        return;
    }

    if (bid < B_KV) {
        int cb = bid - B_CVTPRE;
        if (cb < CVT_PTS_B)               cvt_block_wide(points, g_ph, g_pl, cb, tid);
        else if (cb < CVT_PTS_B + CVT_WSM_B)
            cvt_block_wide(wk, g_wkh, g_wkl, cb - CVT_PTS_B, tid);
        else
            cvt_block_wide(wv, g_wvh, g_wvl, cb - CVT_PTS_B - CVT_WSM_B, tid);
        __syncthreads();
        if (tid == 0) { __threadfence(); atomicAdd(&g_cvtcnt, 1); }
        return;
    }

    if (bid < B_CVTPOST) {
        // -------------------- merged k/v GEMM (polls cvtcnt) ----------------
        if (tid == 0) { while (ld_acquire(&g_cvtcnt) < CVT_PRE_TOT) { } }
        const int idx = bid - B_KV;
        const int bx  = idx & 7;
        const int m0  = (idx >> 3) * 128;
        const int n0  = (bx & 3) * 64;
        const bf16* WhiS = (bx < 4) ? g_wkh : g_wvh;
        const bf16* WloS = (bx < 4) ? g_wkl : g_wvl;
        float* CS = (bx < 4) ? g_kall : g_vall;
        const int Kd = CIN;
        const int* rowmap = nullptr;

        GEMM_MAINLOOP(g_ph, g_pl, rowmap, WhiS, WloS)

        const int quad = lane >> 2, tq = lane & 3;
#pragma unroll
        for (int mt = 0; mt < 2; mt++) {
            int r0 = m0 + wm*32 + mt*16 + quad;
            int r1 = r0 + 8;
#pragma unroll
            for (int nt = 0; nt < 4; nt++) {
                int col = n0 + wn*32 + nt*8 + tq*2;
                *(float2*)(CS + (size_t)r0*COUT + col) =
                    make_float2(acc[mt][nt][0], acc[mt][nt][1]);
                *(float2*)(CS + (size_t)r1*COUT + col) =
                    make_float2(acc[mt][nt][2], acc[mt][nt][3]);
            }
        }
        __syncthreads();
        if (tid == 0) {
            __threadfence();
            atomicAdd((bx < 4) ? &g_kwc[m0 >> 12] : &g_vwc[m0 >> 12], 1);
        }
        return;
    }

    if (bid < B_KNN) {
        int cb = bid - B_CVTPOST;
        if (cb < CVT_WSM_B) { cvt_block_wide(wq, g_wqh, g_wql, cb, tid); return; }
        cb -= CVT_WSM_B;
        if (cb < CVT_WBG_B) { cvt_block_wide(dw2, g_dw2h, g_dw2l, cb, tid); return; }
        cb -= CVT_WBG_B;
        if (cb < CVT_WBG_B) { cvt_block_wide(gw1, g_gw1h, g_gw1l, cb, tid); return; }
        cb -= CVT_WBG_B;
        if (cb < CVT_WBG_B) { cvt_block_wide(gw2, g_gw2h, g_gw2l, cb, tid); return; }
        cb -= CVT_WBG_B;
        cvt_block_wide(lw, g_lwh, g_lwl, cb, tid);
        return;
    }

    if (bid < B_Q) {
        // ------------- KNN (polls FPS progress, commits kprog) ---------------
        extern __shared__ char smk[];
        float (*smd)[512] = (float(*)[512])smk;
        int   (*smi)[512] = (int(*)[512])(smk + 8*512*4);

        const int kb   = bid - B_KNN;
        const int lane = tid & 31;
        const int wloc = tid >> 5;
        const int b    = kb & 7;
        const int s0   = (kb >> 3) * 8;
        const int s    = s0 + wloc;
        const int warp = b * SS + s;
        const float* base = xyz + (size_t)b * NN * 3;

        if (lane == 0) {
            while (ld_acquire(&g_prog[b]) <= s) { }
        }
        __syncwarp();

        float nx = __ldcg(newxyz + (size_t)warp*3 + 0);
        float ny = __ldcg(newxyz + (size_t)warp*3 + 1);
        float nz = __ldcg(newxyz + (size_t)warp*3 + 2);
        float ns = fmaf(nz, nz, fmaf(ny, ny, __fmul_rn(nx, nx)));

        float v[16]; int id[16];
#pragma unroll
        for (int t = 0; t < 16; t++) { v[t] = 3.4e38f; id[t] = 0x7fffffff; }

        for (int j = lane; j < NN; j += 32) {
            float x = base[j*3+0], y = base[j*3+1], z = base[j*3+2];
            float dot = fmaf(z, nz, fmaf(y, ny, __fmul_rn(x, nx)));
            float nq  = fmaf(z, z,  fmaf(y, y,  __fmul_rn(x, x)));
            float d   = __fadd_rn(__fsub_rn(ns, __fmul_rn(2.0f, dot)), nq);
            if (d < v[15]) {
                v[15] = d; id[15] = j;
#pragma unroll
                for (int t = 15; t > 0; t--) {
                    if (v[t] < v[t-1] || (v[t] == v[t-1] && id[t] < id[t-1])) {
                        float tv = v[t]; v[t] = v[t-1]; v[t-1] = tv;
                        int   ti = id[t]; id[t] = id[t-1]; id[t-1] = ti;
                    } else break;
                }
            }
        }

#pragma unroll
        for (int t = 0; t < 16; t++) {
            smd[wloc][lane*16 + t] = v[t];
            smi[wloc][lane*16 + t] = id[t];
        }
        __syncwarp();

        int p = 0;
        for (int t = 0; t < 16; t++) {
            float cv = (p < 16) ? smd[wloc][lane*16 + p] : 3.4e38f;
            int   ci = (p < 16) ? smi[wloc][lane*16 + p] : 0x7fffffff;
            float mv = cv; int mi = ci;
#pragma unroll
            for (int off = 16; off; off >>= 1) {
                float ov = __shfl_xor_sync(0xffffffffu, mv, off);
                int   oi = __shfl_xor_sync(0xffffffffu, mi, off);
                if (ov < mv || (ov == mv && oi < mi)) { mv = ov; mi = oi; }
            }
            if (cv == mv && ci == mi) p++;
            if (lane == 0) g_knn[(size_t)warp*16 + t] = b*NN + mi;
            __syncwarp();
        }

        __syncthreads();
        if (tid == 0) {
            while (ld_acquire(&g_kprog[b]) != s0) { }
            __threadfence();
            atomicExch(&g_kprog[b], s0 + 8);
        }
        return;
    }

    if (bid < B_H1) {
        // -------------- q GEMM = gather(points, fps) @ wq (polls prog) -------
        const int idx = bid - B_Q;
        const int n0  = (idx & 3) * 64;
        const int m0  = (idx >> 2) * 128;
        const int b   = m0 >> 10;
        const int s_need = (m0 & 1023) + 128;
        if (tid == 0) { while (ld_acquire(&g_prog[b]) < s_need) { } }
        const int Kd = CIN;
        const int* fps_ptr = g_fps;

        GEMM_MAINLOOP(g_ph, g_pl, fps_ptr, g_wqh, g_wql)

        const int quad = lane >> 2, tq = lane & 3;
#pragma unroll
        for (int mt = 0; mt < 2; mt++) {
            int r0 = m0 + wm*32 + mt*16 + quad;
            int r1 = r0 + 8;
#pragma unroll
            for (int nt = 0; nt < 4; nt++) {
                int col = n0 + wn*32 + nt*8 + tq*2;
                *(float2*)(g_q + (size_t)r0*COUT + col) =
                    make_float2(acc[mt][nt][0], acc[mt][nt][1]);
                *(float2*)(g_q + (size_t)r1*COUT + col) =
                    make_float2(acc[mt][nt][2], acc[mt][nt][3]);
            }
        }
        __syncthreads();
        if (tid == 0) { __threadfence(); atomicAdd(&g_qc[m0 >> 7], 1); }
        return;
    }

    if (bid < B_A1) {
        // ----------------- h1 pos-enc layer 1 (polls kprog) ------------------
        const int hb = bid - B_H1;
        const int b  = hb >> 7;
        const int s_need = ((hb * 8) & 1023) + 8;
        if (tid == 0) { while (ld_acquire(&g_kprog[b]) < s_need) { } }
        __syncthreads();

        const int col    = (tid & 127) * 2;
        const int rowsel = tid >> 7;
        const float w0a = dw1[col],        w0b = dw1[col+1];
        const float w1a = dw1[COUT+col],   w1b = dw1[COUT+col+1];
        const float w2a = dw1[2*COUT+col], w2b = dw1[2*COUT+col+1];
        const float b0  = db1[col],        b1  = db1[col+1];

        for (int rr = 0; rr < 64; rr++) {
            int r  = hb*128 + rr*2 + rowsel;
            int g  = __ldcg(&g_knn[r]);
            int bs = r >> 4;
            float cx = __ldcg(&xyz[(size_t)g*3+0]) - __ldcg(&newxyz[(size_t)bs*3+0]);
            float cy = __ldcg(&xyz[(size_t)g*3+1]) - __ldcg(&newxyz[(size_t)bs*3+1]);
            float cz = __ldcg(&xyz[(size_t)g*3+2]) - __ldcg(&newxyz[(size_t)bs*3+2]);
            float h0 = b0, h1v = b1;
            h0  = fmaf(cx, w0a, h0);  h0  = fmaf(cy, w1a, h0);  h0  = fmaf(cz, w2a, h0);
            h1v = fmaf(cx, w0b, h1v); h1v = fmaf(cy, w1b, h1v); h1v = fmaf(cz, w2b, h1v);
            h0  = fmaxf(h0, 0.0f);
            h1v = fmaxf(h1v, 0.0f);
            uint32_t h, l;
            split2(h0, h1v, h, l);
            *(uint32_t*)&g_x1h[(size_t)r*COUT + col] = h;
            *(uint32_t*)&g_x1l[(size_t)r*COUT + col] = l;
        }
        __syncthreads();
        if (tid == 0) { __threadfence(); atomicExch(&g_hc[hb], 1); }
        return;
    }

    if (bid < B_H2) {
        // a1 GEMM: pos = h1@dw2+db2 (fp32) + fused a1 = q - k_gather + pos
        const int idx = bid - B_A1;
        const int n0  = (idx & 3) * 64;
        const int m0  = (idx >> 2) * 128;
        if (tid == 0) {
            while (ld_acquire(&g_hc[m0 >> 7]) == 0) { }
            while (ld_acquire(&g_qc[m0 >> 11]) < 4) { }
            while (ld_acquire(&g_kwc[m0 >> 14]) < 128) { }
        }
        gemm_body(tid, m0, n0, COUT, g_x1h, g_x1l, nullptr,
                  g_dw2h, g_dw2l, db2, 0,
                  g_pos, nullptr, nullptr,
                  g_q, g_kall, g_knn, g_a1h, g_a1l);
        __syncthreads();
        if (tid == 0) { __threadfence(); atomicAdd(&g_c1[m0 >> 7], 1); }
        return;
    }

    if (bid < B_ATT) {
        // h2 = relu(a1@gw1+gb1) -> x1 (bf16 split)
        const int idx = bid - B_H2;
        const int n0  = (idx & 3) * 64;
        const int m0  = (idx >> 2) * 128;
        if (tid == 0) { while (ld_acquire(&g_c1[m0 >> 7]) < 4) { } }
        gemm_body(tid, m0, n0, COUT, g_a1h, g_a1l, nullptr,
                  g_gw1h, g_gw1l, gb1, 1,
                  nullptr, g_x1h, g_x1l,
                  nullptr, nullptr, nullptr, nullptr, nullptr);
        __syncthreads();
        if (tid == 0) { __threadfence(); atomicAdd(&g_c2[m0 >> 7], 1); }
        return;
    }

    if (bid < B_LW) {
        // att GEMM + fused softmax/weighted sum -> r0 (bf16 split)
        const int idx = bid - B_ATT;
        const int n0  = (idx & 3) * 64;
        const int m0  = (idx >> 2) * 128;
        if (tid == 0) {
            while (ld_acquire(&g_c2[m0 >> 7]) < 4) { }
            while (ld_acquire(&g_vwc[m0 >> 14]) < 128) { }
        }
        gemm_att_body(tid, m0, n0, COUT, g_x1h, g_x1l,
                      g_gw2h, g_gw2l, gb2, g_knn, g_pos, g_vall,
                      g_r0h, g_r0l);
        __syncthreads();
        if (tid == 0) { __threadfence(); atomicAdd(&g_c3[m0 >> 11], 1); }
        return;
    }

    if (bid < B_BNP) {
        // lw GEMM: res1 = r0@lw + lb
        const int idx = bid - B_LW;
        const int n0  = (idx & 3) * 64;
        const int m0  = (idx >> 2) * 128;
        if (tid == 0) { while (ld_acquire(&g_c3[m0 >> 7]) < 64) { } }
        gemm_body(tid, m0, n0, COUT, g_r0h, g_r0l, nullptr,
                  g_lwh, g_lwl, lb, 0,
                  g_res1, nullptr, nullptr,
                  nullptr, nullptr, nullptr, nullptr, nullptr);
        __syncthreads();
        if (tid == 0) { __threadfence(); atomicAdd(&g_c4a[m0 >> 7], 1); }
        return;
    }

    if (bid < B_BNA) {
        // BN partial sums over 128-row slab
        const int blk = bid - B_BNP;
        if (tid == 0) { while (ld_acquire(&g_c4a[blk]) < 4) { } }
        __syncthreads();
        const int c = tid;
        float s = 0.0f, q = 0.0f;
        for (int r = blk*128; r < blk*128 + 128; r++) {
            float x = g_res1[(size_t)r*COUT + c];
            s += x; q = fmaf(x, x, q);
        }
        g_psum[blk*COUT + c] = s;
        g_psq [blk*COUT + c] = q;
        __syncthreads();
        if (tid == 0) { __threadfence(); atomicAdd(&g_c5, 1); }
        return;
    }

    // BN finalize + apply (each block recomputes scale/shift, applies a slab)
    {
        const int kb = bid - B_BNA;           // 0..15
        if (tid == 0) { while (ld_acquire(&g_c5) < 64) { } }
        __syncthreads();
        extern __shared__ char smraw[];
        float* ssc = (float*)smraw;
        float* ssh = ssc + 256;
        {
            float s = 0.0f, q = 0.0f;
            for (int i = 0; i < 64; i++) {
                s += g_psum[i*COUT + tid];
                q += g_psq [i*COUT + tid];
            }
            float mean = s * (1.0f/(float)BSR);
            float var  = fmaxf(q * (1.0f/(float)BSR) - mean*mean, 0.0f);
            float sc   = bng[tid] * rsqrtf(var + 1e-5f);
            ssc[tid] = sc;
            ssh[tid] = bnb[tid] - mean * sc;
        }
        __syncthreads();
        const int c4i = tid & 63;
        float4 sc4 = ((const float4*)ssc)[c4i];
        float4 sh4 = ((const float4*)ssh)[c4i];
        const float4* in4  = (const float4*)g_res1;
        float4*       out4 = (float4*)res_out;
        size_t base = (size_t)kb * 32768;
        for (int i = 0; i < 128; i++) {
            size_t f = base + (size_t)i*256 + tid;
            float4 x = in4[f];
            float4 o;
            o.x = fmaxf(fmaf(x.x, sc4.x, sh4.x), 0.0f);
            o.y = fmaxf(fmaf(x.y, sc4.y, sh4.y), 0.0f);
            o.z = fmaxf(fmaf(x.z, sc4.z, sh4.z), 0.0f);
            o.w = fmaxf(fmaf(x.w, sc4.w, sh4.w), 0.0f);
            out4[f] = o;
        }
    }
}

// ------------------------------ launch --------------------------------------
extern "C" void kernel_launch(void* const* d_in, const int* in_sizes, int n_in,
                              void* d_out, int out_size)
{
    const float* xyz    = (const float*)d_in[0];
    const float* points = (const float*)d_in[1];
    const float* wq     = (const float*)d_in[2];
    const float* wk     = (const float*)d_in[3];
    const float* wv     = (const float*)d_in[4];
    const float* dw1    = (const float*)d_in[5];
    const float* db1    = (const float*)d_in[6];
    const float* dw2    = (const float*)d_in[7];
    const float* db2    = (const float*)d_in[8];
    const float* gw1    = (const float*)d_in[9];
    const float* gb1    = (const float*)d_in[10];
    const float* gw2    = (const float*)d_in[11];
    const float* gb2    = (const float*)d_in[12];
    const float* lw     = (const float*)d_in[13];
    const float* lb     = (const float*)d_in[14];
    const float* bng    = (const float*)d_in[15];
    const float* bnb    = (const float*)d_in[16];

    float* out     = (float*)d_out;
    float* newxyz  = out;
    float* res_out = out + (size_t)BSR*3;

    static bool attr_set = false;
    if (!attr_set) {
        cudaFuncSetAttribute(uber, cudaFuncAttributeMaxDynamicSharedMemorySize, TG_SMEM);
        attr_set = true;
    }

    // 1: reset progress counters (graph-replay safe)
    reset_prog_kernel<<<16, 256>>>();
    // 2: the entire network, one launch, poll-chained per-tile
    uber<<<UBER_GRID, 256, TG_SMEM>>>(xyz, newxyz, points, wk, wv,
                                      wq, dw2, gw1, gw2, lw, dw1, db1,
                                      db2, gb1, gb2, lb, bng, bnb, res_out);
}

// round 17
// speedup vs baseline: 1.1258x; 1.0050x over previous
#include <cuda_runtime.h>
#include <cuda_bf16.h>
#include <math.h>
#include <stdint.h>

#define BB   8
#define NN   4096
#define SS   1024
#define KNBR 16
#define CIN  128
#define COUT 256
#define MROWS (BB*SS*KNBR)   /* 131072 */
#define BSR   (BB*SS)        /* 8192  */
#define NPTS  (BB*NN)        /* 32768 */

typedef __nv_bfloat16 bf16;

// ---------------- static device scratch (no allocs allowed) ----------------
__device__ float g_pos [(size_t)MROWS*COUT];
__device__ bf16  g_a1h [(size_t)MROWS*COUT];
__device__ bf16  g_a1l [(size_t)MROWS*COUT];
__device__ bf16  g_x1h [(size_t)MROWS*COUT];   // h1 then h2
__device__ bf16  g_x1l [(size_t)MROWS*COUT];
__device__ bf16  g_ph  [(size_t)NPTS*CIN];
__device__ bf16  g_pl  [(size_t)NPTS*CIN];
__device__ float g_kall[(size_t)NPTS*COUT];
__device__ float g_vall[(size_t)NPTS*COUT];
__device__ float g_q   [(size_t)BSR*COUT];
__device__ bf16  g_r0h [(size_t)BSR*COUT];
__device__ bf16  g_r0l [(size_t)BSR*COUT];
__device__ float g_res1[(size_t)BSR*COUT];
__device__ int   g_fps [BSR];
__device__ int   g_knn [MROWS];
__device__ int   g_prog[BB];
__device__ int   g_kprog[BB];
__device__ int   g_cvtcnt;
__device__ int   g_kwc[BB];
__device__ int   g_vwc[BB];
__device__ int   g_qc [BSR/128];
__device__ int   g_hc [MROWS/128];
__device__ int   g_c1[MROWS/128];
__device__ int   g_c2[MROWS/128];
__device__ int   g_c3[BSR/128];
__device__ int   g_c4a[BSR/128];
__device__ int   g_c5;
__device__ float g_psum[64*COUT];
__device__ float g_psq [64*COUT];
// pre-split weights
__device__ bf16  g_wkh[CIN*COUT],  g_wkl[CIN*COUT];
__device__ bf16  g_wvh[CIN*COUT],  g_wvl[CIN*COUT];
__device__ bf16  g_wqh[CIN*COUT],  g_wql[CIN*COUT];
__device__ bf16  g_dw2h[COUT*COUT], g_dw2l[COUT*COUT];
__device__ bf16  g_gw1h[COUT*COUT], g_gw1l[COUT*COUT];
__device__ bf16  g_gw2h[COUT*COUT], g_gw2l[COUT*COUT];
__device__ bf16  g_lwh[COUT*COUT],  g_lwl[COUT*COUT];

// -------------------- bf16 split helper ------------------------------------
__device__ __forceinline__ void split2(float x0, float x1, uint32_t& hi, uint32_t& lo)
{
    bf16 h0 = __float2bfloat16(x0);
    bf16 h1 = __float2bfloat16(x1);
    float r0 = __fsub_rn(x0, __bfloat162float(h0));
    float r1 = __fsub_rn(x1, __bfloat162float(h1));
    bf16 l0 = __float2bfloat16(r0);
    bf16 l1 = __float2bfloat16(r1);
    hi = (uint32_t)__bfloat16_as_ushort(h0) | ((uint32_t)__bfloat16_as_ushort(h1) << 16);
    lo = (uint32_t)__bfloat16_as_ushort(l0) | ((uint32_t)__bfloat16_as_ushort(l1) << 16);
}

__device__ __forceinline__ int ld_acquire(const int* p)
{
    int v;
    asm volatile("ld.acquire.gpu.global.b32 %0, [%1];" : "=r"(v) : "l"(p));
    return v;
}

// ---------------- wide fp32 -> bf16 hi/lo conversion (8 elems/thread) -------
__device__ __forceinline__ void cvt_block_wide(const float* __restrict__ src,
                                               bf16* __restrict__ hi, bf16* __restrict__ lo,
                                               int local_bid, int tid)
{
    int e = (local_bid * 256 + tid) * 8;
    float4 a = *(const float4*)(src + e);
    float4 c = *(const float4*)(src + e + 4);
    uint32_t h0,l0,h1,l1,h2,l2,h3,l3;
    split2(a.x, a.y, h0, l0); split2(a.z, a.w, h1, l1);
    split2(c.x, c.y, h2, l2); split2(c.z, c.w, h3, l3);
    uint4 H; H.x = h0; H.y = h1; H.z = h2; H.w = h3;
    uint4 L; L.x = l0; L.y = l1; L.z = l2; L.w = l3;
    *(uint4*)&hi[e] = H;
    *(uint4*)&lo[e] = L;
}

__global__ void reset_prog_kernel()
{
    int t = blockIdx.x * 256 + threadIdx.x;   // <<<16,256>>> = 4096
    if (t < 1024) { g_c1[t] = 0; g_c2[t] = 0; g_hc[t] = 0; }
    int u = t - 1024;
    if (u >= 0) {
        if (u < 64)                   g_c3[u] = 0;
        else if (u < 128)             g_c4a[u-64] = 0;
        else if (u < 192)             g_qc[u-128] = 0;
        else if (u == 192)            g_c5 = 0;
        else if (u >= 200 && u < 208) g_prog[u-200] = 0;
        else if (u >= 208 && u < 216) g_kprog[u-208] = 0;
        else if (u >= 216 && u < 224) g_kwc[u-216] = 0;
        else if (u >= 224 && u < 232) g_vwc[u-224] = 0;
        else if (u == 232)            g_cvtcnt = 0;
    }
}

// ------------------------- mma helpers --------------------------------------
__device__ __forceinline__ void cp16(void* s, const void* g)
{
    unsigned sa = (unsigned)__cvta_generic_to_shared(s);
    asm volatile("cp.async.ca.shared.global [%0], [%1], 16;\n" :: "r"(sa), "l"(g));
}
#define CP_COMMIT() asm volatile("cp.async.commit_group;\n")

__device__ __forceinline__ void ldsm_x4(uint32_t* r, const void* p)
{
    uint32_t a = (uint32_t)__cvta_generic_to_shared(p);
    asm volatile("ldmatrix.sync.aligned.m8n8.x4.shared.b16 {%0,%1,%2,%3}, [%4];"
                 : "=r"(r[0]), "=r"(r[1]), "=r"(r[2]), "=r"(r[3]) : "r"(a));
}

__device__ __forceinline__ void ldsm_x4_t(uint32_t* r, const void* p)
{
    uint32_t a = (uint32_t)__cvta_generic_to_shared(p);
    asm volatile("ldmatrix.sync.aligned.m8n8.x4.trans.shared.b16 {%0,%1,%2,%3}, [%4];"
                 : "=r"(r[0]), "=r"(r[1]), "=r"(r[2]), "=r"(r[3]) : "r"(a));
}

__device__ __forceinline__ void mma16816(float* c, const uint32_t* a, const uint32_t* b)
{
    asm volatile("mma.sync.aligned.m16n8k16.row.col.f32.bf16.bf16.f32 "
                 "{%0,%1,%2,%3}, {%4,%5,%6,%7}, {%8,%9}, {%0,%1,%2,%3};"
                 : "+f"(c[0]), "+f"(c[1]), "+f"(c[2]), "+f"(c[3])
                 : "r"(a[0]), "r"(a[1]), "r"(a[2]), "r"(a[3]),
                   "r"(b[0]), "r"(b[1]));
}

// ----------------------- shared GEMM mainloop macro (128x64, 4-stage) -------
#define KCH    16
#define NSTG   4
#define ASTR2  24
#define BSTR2  72
#define AS_BYTES  (NSTG*2*128*ASTR2*2)
#define BS_BYTES  (NSTG*2*KCH*BSTR2*2)
#define TG_SMEM   (AS_BYTES + BS_BYTES + 512)

#define GEMM_MAINLOOP(AHI, ALO, ROWMAP, WHI, WLO)                               \
    extern __shared__ char smraw[];                                            \
    typedef bf16 (*AsT)[2][128][ASTR2];                                        \
    typedef bf16 (*BsT)[2][KCH][BSTR2];                                        \
    AsT As = (AsT)smraw;                                                       \
    BsT Bs = (BsT)(smraw + AS_BYTES);                                          \
    int* rmap = (int*)(smraw + AS_BYTES + BS_BYTES);                           \
    if (tid < 128) rmap[tid] = (ROWMAP) ? __ldcg((ROWMAP) + m0 + tid) : (m0 + tid); \
    __syncthreads();                                                           \
    const int arow = tid >> 1;                                                 \
    const int ach  = (tid & 1) * 8;                                            \
    const bf16* aSrcH = (AHI) + (size_t)rmap[arow] * Kd + ach;                 \
    const bf16* aSrcL = (ALO) + (size_t)rmap[arow] * Kd + ach;                 \
    const int bpl = tid >> 7;                                                  \
    const int bk  = (tid >> 3) & 15;                                           \
    const int bch = (tid & 7) * 8;                                             \
    const bf16* bSrc = (bpl ? (WLO) : (WHI)) + (size_t)bk * COUT + n0 + bch;   \
    const int lane = tid & 31;                                                 \
    const int wm = (tid >> 5) >> 1;                                            \
    const int wn = (tid >> 5) & 1;                                             \
    const int aFrow = wm * 32 + (lane & 15);                                   \
    const int aFk   = (lane >> 4) * 8;                                         \
    const int bFk   = (lane & 7) + ((lane >> 3) & 1) * 8;                      \
    const int bFn   = (lane >> 4) * 8;                                         \
    float acc[2][4][4];                                                        \
    _Pragma("unroll")                                                          \
    for (int i = 0; i < 2; i++)                                                \
        _Pragma("unroll")                                                      \
        for (int j = 0; j < 4; j++)                                            \
            _Pragma("unroll")                                                  \
            for (int l = 0; l < 4; l++) acc[i][j][l] = 0.0f;                   \
    const int nk = Kd >> 4;                                                    \
    _Pragma("unroll")                                                          \
    for (int s = 0; s < NSTG - 1; s++) {                                       \
        if (s < nk) {                                                          \
            int k0 = s * KCH;                                                  \
            cp16(&As[s][0][arow][ach], aSrcH + k0);                            \
            cp16(&As[s][1][arow][ach], aSrcL + k0);                            \
            cp16(&Bs[s][bpl][bk][bch], bSrc + (size_t)k0 * COUT);              \
        }                                                                      \
        CP_COMMIT();                                                           \
    }                                                                          \
    for (int t = 0; t < nk; t++) {                                             \
        const int cur = t & (NSTG - 1);                                        \
        if (t + NSTG - 1 < nk) {                                               \
            asm volatile("cp.async.wait_group 2;\n" ::: "memory");             \
        } else {                                                               \
            asm volatile("cp.async.wait_group 0;\n" ::: "memory");             \
        }                                                                      \
        __syncthreads();                                                       \
        if (t + NSTG - 1 < nk) {                                               \
            const int stg = (t + NSTG - 1) & (NSTG - 1);                       \
            const int k0  = (t + NSTG - 1) * KCH;                              \
            cp16(&As[stg][0][arow][ach], aSrcH + k0);                          \
            cp16(&As[stg][1][arow][ach], aSrcL + k0);                          \
            cp16(&Bs[stg][bpl][bk][bch], bSrc + (size_t)k0 * COUT);            \
            CP_COMMIT();                                                       \
        }                                                                      \
        uint32_t ah[2][4], al[2][4], bh[4][2], bl[4][2];                       \
        _Pragma("unroll")                                                      \
        for (int mt = 0; mt < 2; mt++) {                                       \
            ldsm_x4(ah[mt], &As[cur][0][aFrow + mt*16][aFk]);                  \
            ldsm_x4(al[mt], &As[cur][1][aFrow + mt*16][aFk]);                  \
        }                                                                      \
        _Pragma("unroll")                                                      \
        for (int g = 0; g < 2; g++) {                                          \
            uint32_t tmp[4];                                                   \
            ldsm_x4_t(tmp, &Bs[cur][0][bFk][wn*32 + g*16 + bFn]);              \
            bh[g*2][0]   = tmp[0]; bh[g*2][1]   = tmp[1];                      \
            bh[g*2+1][0] = tmp[2]; bh[g*2+1][1] = tmp[3];                      \
            ldsm_x4_t(tmp, &Bs[cur][1][bFk][wn*32 + g*16 + bFn]);              \
            bl[g*2][0]   = tmp[0]; bl[g*2][1]   = tmp[1];                      \
            bl[g*2+1][0] = tmp[2]; bl[g*2+1][1] = tmp[3];                      \
        }                                                                      \
        _Pragma("unroll")                                                      \
        for (int mt = 0; mt < 2; mt++)                                         \
            _Pragma("unroll")                                                  \
            for (int nt = 0; nt < 4; nt++) {                                   \
                mma16816(acc[mt][nt], ah[mt], bh[nt]);                         \
                mma16816(acc[mt][nt], al[mt], bh[nt]);                         \
                mma16816(acc[mt][nt], ah[mt], bl[nt]);                         \
            }                                                                  \
    }

// --------- GEMM body as device function (fp32 / bf16-split / a1 dual) -------
__device__ __forceinline__ void gemm_body(
    int tid, int m0, int n0, int Kd,
    const bf16* __restrict__ Ahi, const bf16* __restrict__ Alo,
    const int* __restrict__ rowmap,
    const bf16* __restrict__ Whi, const bf16* __restrict__ Wlo,
    const float* __restrict__ bias, int relu,
    float* __restrict__ C, bf16* __restrict__ Chi, bf16* __restrict__ Clo,
    const float* __restrict__ qv, const float* __restrict__ kall,
    const int* __restrict__ knn,
    bf16* __restrict__ A1hi, bf16* __restrict__ A1lo)
{
    GEMM_MAINLOOP(Ahi, Alo, rowmap, Whi, Wlo)

    const int quad = lane >> 2, tq = lane & 3;
#pragma unroll
    for (int mt = 0; mt < 2; mt++) {
        int r0 = m0 + wm*32 + mt*16 + quad;
        int r1 = r0 + 8;
        const float *q0 = nullptr, *k0p = nullptr, *q1 = nullptr, *k1p = nullptr;
        if (A1hi) {
            q0 = qv + (size_t)(r0 >> 4) * COUT;  k0p = kall + (size_t)knn[r0] * COUT;
            q1 = qv + (size_t)(r1 >> 4) * COUT;  k1p = kall + (size_t)knn[r1] * COUT;
        }
#pragma unroll
        for (int nt = 0; nt < 4; nt++) {
            int col = n0 + wn*32 + nt*8 + tq*2;
            float o0 = acc[mt][nt][0], o1 = acc[mt][nt][1];
            float o2 = acc[mt][nt][2], o3 = acc[mt][nt][3];
            if (bias) { float bb0 = bias[col], bb1 = bias[col+1];
                        o0 += bb0; o1 += bb1; o2 += bb0; o3 += bb1; }
            if (relu) { o0 = fmaxf(o0,0.f); o1 = fmaxf(o1,0.f);
                        o2 = fmaxf(o2,0.f); o3 = fmaxf(o3,0.f); }
            if (C) {
                *(float2*)(C + (size_t)r0*COUT + col) = make_float2(o0, o1);
                *(float2*)(C + (size_t)r1*COUT + col) = make_float2(o2, o3);
            }
            if (Chi) {
                uint32_t h, l;
                split2(o0, o1, h, l);
                *(uint32_t*)&Chi[(size_t)r0*COUT + col] = h;
                *(uint32_t*)&Clo[(size_t)r0*COUT + col] = l;
                split2(o2, o3, h, l);
                *(uint32_t*)&Chi[(size_t)r1*COUT + col] = h;
                *(uint32_t*)&Clo[(size_t)r1*COUT + col] = l;
            }
            if (A1hi) {
                float w0 = __fadd_rn(__fsub_rn(q0[col],   k0p[col]),   o0);
                float w1 = __fadd_rn(__fsub_rn(q0[col+1], k0p[col+1]), o1);
                float w2 = __fadd_rn(__fsub_rn(q1[col],   k1p[col]),   o2);
                float w3 = __fadd_rn(__fsub_rn(q1[col+1], k1p[col+1]), o3);
                uint32_t h, l;
                split2(w0, w1, h, l);
                *(uint32_t*)&A1hi[(size_t)r0*COUT + col] = h;
                *(uint32_t*)&A1lo[(size_t)r0*COUT + col] = l;
                split2(w2, w3, h, l);
                *(uint32_t*)&A1hi[(size_t)r1*COUT + col] = h;
                *(uint32_t*)&A1lo[(size_t)r1*COUT + col] = l;
            }
        }
    }
}

// --------- att GEMM body: fused per-group softmax + weighted sum ------------
__device__ __forceinline__ void gemm_att_body(
    int tid, int m0, int n0, int Kd,
    const bf16* __restrict__ Ahi, const bf16* __restrict__ Alo,
    const bf16* __restrict__ Whi, const bf16* __restrict__ Wlo,
    const float* __restrict__ bias,
    const int* __restrict__ knn,
    const float* __restrict__ pos, const float* __restrict__ vall,
    bf16* __restrict__ R0hi, bf16* __restrict__ R0lo)
{
    const int* rowmap = nullptr;
    GEMM_MAINLOOP(Ahi, Alo, rowmap, Whi, Wlo)

    const int quad = lane >> 2;
    const unsigned FULL = 0xffffffffu;
#pragma unroll
    for (int mt = 0; mt < 2; mt++) {
        int gr  = m0 + wm*32 + mt*16;
        int bs  = gr >> 4;
        int ra  = gr + quad;
        int rb  = ra + 8;
        int kna = knn[ra], knb = knn[rb];
#pragma unroll
        for (int nt = 0; nt < 4; nt++) {
            int col = n0 + wn*32 + nt*8 + (lane & 3)*2;
            float b0 = bias[col], b1 = bias[col+1];
            float v00 = (acc[mt][nt][0] + b0) * 0.0625f;
            float v01 = (acc[mt][nt][1] + b1) * 0.0625f;
            float v10 = (acc[mt][nt][2] + b0) * 0.0625f;
            float v11 = (acc[mt][nt][3] + b1) * 0.0625f;
            float m0c = fmaxf(v00, v10);
            float m1c = fmaxf(v01, v11);
#pragma unroll
            for (int off = 4; off <= 16; off <<= 1) {
                m0c = fmaxf(m0c, __shfl_xor_sync(FULL, m0c, off));
                m1c = fmaxf(m1c, __shfl_xor_sync(FULL, m1c, off));
            }
            float e00 = expf(v00 - m0c), e10 = expf(v10 - m0c);
            float e01 = expf(v01 - m1c), e11 = expf(v11 - m1c);
            float s0 = e00 + e10, s1 = e01 + e11;
#pragma unroll
            for (int off = 4; off <= 16; off <<= 1) {
                s0 += __shfl_xor_sync(FULL, s0, off);
                s1 += __shfl_xor_sync(FULL, s1, off);
            }
            float2 pa = *(const float2*)(pos  + (size_t)ra*COUT + col);
            float2 pb = *(const float2*)(pos  + (size_t)rb*COUT + col);
            float2 va = *(const float2*)(vall + (size_t)kna*COUT + col);
            float2 vb = *(const float2*)(vall + (size_t)knb*COUT + col);
            float w0 = e00*(va.x + pa.x) + e10*(vb.x + pb.x);
            float w1 = e01*(va.y + pa.y) + e11*(vb.y + pb.y);
#pragma unroll
            for (int off = 4; off <= 16; off <<= 1) {
                w0 += __shfl_xor_sync(FULL, w0, off);
                w1 += __shfl_xor_sync(FULL, w1, off);
            }
            if (quad == 0) {
                float o0 = w0 / s0, o1 = w1 / s1;
                uint32_t h, l;
                split2(o0, o1, h, l);
                *(uint32_t*)&R0hi[(size_t)bs*COUT + col] = h;
                *(uint32_t*)&R0lo[(size_t)bs*COUT + col] = l;
            }
        }
    }
}

// ------ UBER kernel block ranges ---------------------------------------------
#define CVT_PTS_B    (NPTS*CIN/2048)
#define CVT_WSM_B    (CIN*COUT/2048)
#define CVT_WBG_B    (COUT*COUT/2048)
#define CVT_PRE_TOT  (CVT_PTS_B + 2*CVT_WSM_B)
#define KV_BLOCKS    (8 * (NPTS/128))
#define CVT_POST_TOT (CVT_WSM_B + 4*CVT_WBG_B)
#define KNN_BLOCKS   (BSR/8)
#define Q_BLOCKS     (4 * (BSR/128))
#define H1_BLOCKS    (MROWS/128)

#define B_CVTPRE   8
#define B_KV       (B_CVTPRE + CVT_PRE_TOT)
#define B_CVTPOST  (B_KV + KV_BLOCKS)
#define B_KNN      (B_CVTPOST + CVT_POST_TOT)
#define B_Q        (B_KNN + KNN_BLOCKS)
#define B_H1       (B_Q + Q_BLOCKS)
#define B_MLP      (B_H1 + H1_BLOCKS)

// skewed pipeline: 19 rounds x [a1 chunk r | h2 r-1 | att r-2 | lw r-3]
#define ROUND_SZ   784
#define NROUNDS    19
#define NCHUNK     16
#define B_BNP      (B_MLP + NROUNDS*ROUND_SZ)
#define B_BNA      (B_BNP + 64)
#define UBER_GRID  (B_BNA + 16)

__global__ __launch_bounds__(256, 2) void uber(
    const float* __restrict__ xyz, float* __restrict__ newxyz,
    const float* __restrict__ points,
    const float* __restrict__ wk, const float* __restrict__ wv,
    const float* __restrict__ wq, const float* __restrict__ dw2,
    const float* __restrict__ gw1, const float* __restrict__ gw2,
    const float* __restrict__ lw,
    const float* __restrict__ dw1, const float* __restrict__ db1,
    const float* __restrict__ db2, const float* __restrict__ gb1,
    const float* __restrict__ gb2, const float* __restrict__ lb,
    const float* __restrict__ bng, const float* __restrict__ bnb,
    float* __restrict__ res_out)
{
    const int bid = blockIdx.x;
    const int tid = threadIdx.x;

    if (bid < 8) {
        // ------------------------- FPS -------------------------------------
        extern __shared__ char smtop[];
        float* sx = (float*)smtop;
        float* sy = sx + NN;
        float* sz = sy + NN;
        unsigned long long* swk = (unsigned long long*)(smtop + 3*NN*4);

        int b = bid;
        int lane = tid & 31, wid = tid >> 5;
        const float* base = xyz + (size_t)b * NN * 3;

        for (int i = tid; i < NN; i += 256) {
            sx[i] = base[i*3+0];
            sy[i] = base[i*3+1];
            sz[i] = base[i*3+2];
        }
        __syncthreads();

        float px[16], py[16], pz[16], dist[16];
#pragma unroll
        for (int j = 0; j < 16; j++) {
            int i = tid * 16 + j;
            px[j] = sx[i]; py[j] = sy[i]; pz[j] = sz[i];
            dist[j] = 1e10f;
        }

        int far = 0;
        for (int s = 0; s < SS; s++) {
            float cx = sx[far], cy = sy[far], cz = sz[far];
            if (tid == 0) {
                g_fps[b*SS + s] = b*NN + far;
                newxyz[((size_t)b*SS + s)*3 + 0] = cx;
                newxyz[((size_t)b*SS + s)*3 + 1] = cy;
                newxyz[((size_t)b*SS + s)*3 + 2] = cz;
                if ((s & 31) == 31) {
                    __threadfence();
                    atomicExch(&g_prog[b], s + 1);
                }
            }
#pragma unroll
            for (int j = 0; j < 16; j++) {
                float dx = __fsub_rn(px[j], cx);
                float dy = __fsub_rn(py[j], cy);
                float dz = __fsub_rn(pz[j], cz);
                float d  = __fadd_rn(__fadd_rn(__fmul_rn(dx,dx), __fmul_rn(dy,dy)),
                                     __fmul_rn(dz,dz));
                dist[j] = fminf(dist[j], d);
            }
            float m8[8];
#pragma unroll
            for (int j = 0; j < 8; j++) m8[j] = fmaxf(dist[j], dist[j+8]);
#pragma unroll
            for (int j = 0; j < 4; j++) m8[j] = fmaxf(m8[j], m8[j+4]);
            float bv = fmaxf(fmaxf(m8[0], m8[1]), fmaxf(m8[2], m8[3]));
            unsigned match = 0;
#pragma unroll
            for (int j = 0; j < 16; j++) match |= (dist[j] == bv) ? (1u << j) : 0u;
            int bi = tid*16 + (__ffs(match) - 1);

            unsigned key  = __float_as_uint(bv);
            unsigned wmax = __reduce_max_sync(0xffffffffu, key);
            unsigned ball = __ballot_sync(0xffffffffu, key == wmax);
            int src  = __ffs(ball) - 1;
            int wbi  = __shfl_sync(0xffffffffu, bi, src);
            if (lane == 0)
                swk[(s & 1)*8 + wid] = ((unsigned long long)wmax << 32)
                                     | (unsigned)(NN - 1 - wbi);
            __syncthreads();
            unsigned long long best = swk[(s & 1)*8 + 0];
#pragma unroll
            for (int w = 1; w < 8; w++) {
                unsigned long long c = swk[(s & 1)*8 + w];
                if (c > best) best = c;
            }
            far = NN - 1 - (int)(best & 0xffffffffu);
        }
        return;
    }

    if (bid < B_KV) {
        int cb = bid - B_CVTPRE;
        if (cb < CVT_PTS_B)               cvt_block_wide(points, g_ph, g_pl, cb, tid);
        else if (cb < CVT_PTS_B + CVT_WSM_B)
            cvt_block_wide(wk, g_wkh, g_wkl, cb - CVT_PTS_B, tid);
        else
            cvt_block_wide(wv, g_wvh, g_wvl, cb - CVT_PTS_B - CVT_WSM_B, tid);
        __syncthreads();
        if (tid == 0) { __threadfence(); atomicAdd(&g_cvtcnt, 1); }
        return;
    }

    if (bid < B_CVTPOST) {
        // -------------------- merged k/v GEMM (polls cvtcnt) ----------------
        if (tid == 0) { while (ld_acquire(&g_cvtcnt) < CVT_PRE_TOT) { } }
        const int idx = bid - B_KV;
        const int bx  = idx & 7;
        const int m0  = (idx >> 3) * 128;
        const int n0  = (bx & 3) * 64;
        const bf16* WhiS = (bx < 4) ? g_wkh : g_wvh;
        const bf16* WloS = (bx < 4) ? g_wkl : g_wvl;
        float* CS = (bx < 4) ? g_kall : g_vall;
        const int Kd = CIN;
        const int* rowmap = nullptr;

        GEMM_MAINLOOP(g_ph, g_pl, rowmap, WhiS, WloS)

        const int quad = lane >> 2, tq = lane & 3;
#pragma unroll
        for (int mt = 0; mt < 2; mt++) {
            int r0 = m0 + wm*32 + mt*16 + quad;
            int r1 = r0 + 8;
#pragma unroll
            for (int nt = 0; nt < 4; nt++) {
                int col = n0 + wn*32 + nt*8 + tq*2;
                *(float2*)(CS + (size_t)r0*COUT + col) =
                    make_float2(acc[mt][nt][0], acc[mt][nt][1]);
                *(float2*)(CS + (size_t)r1*COUT + col) =
                    make_float2(acc[mt][nt][2], acc[mt][nt][3]);
            }
        }
        __syncthreads();
        if (tid == 0) {
            __threadfence();
            atomicAdd((bx < 4) ? &g_kwc[m0 >> 12] : &g_vwc[m0 >> 12], 1);
        }
        return;
    }

    if (bid < B_KNN) {
        int cb = bid - B_CVTPOST;
        if (cb < CVT_WSM_B) { cvt_block_wide(wq, g_wqh, g_wql, cb, tid); return; }
        cb -= CVT_WSM_B;
        if (cb < CVT_WBG_B) { cvt_block_wide(dw2, g_dw2h, g_dw2l, cb, tid); return; }
        cb -= CVT_WBG_B;
        if (cb < CVT_WBG_B) { cvt_block_wide(gw1, g_gw1h, g_gw1l, cb, tid); return; }
        cb -= CVT_WBG_B;
        if (cb < CVT_WBG_B) { cvt_block_wide(gw2, g_gw2h, g_gw2l, cb, tid); return; }
        cb -= CVT_WBG_B;
        cvt_block_wide(lw, g_lwh, g_lwl, cb, tid);
        return;
    }

    if (bid < B_Q) {
        // ------------- KNN (polls FPS progress, commits kprog) ---------------
        extern __shared__ char smk[];
        float (*smd)[512] = (float(*)[512])smk;
        int   (*smi)[512] = (int(*)[512])(smk + 8*512*4);

        const int kb   = bid - B_KNN;
        const int lane = tid & 31;
        const int wloc = tid >> 5;
        const int b    = kb & 7;
        const int s0   = (kb >> 3) * 8;
        const int s    = s0 + wloc;
        const int warp = b * SS + s;
        const float* base = xyz + (size_t)b * NN * 3;

        if (lane == 0) {
            while (ld_acquire(&g_prog[b]) <= s) { }
        }
        __syncwarp();

        float nx = __ldcg(newxyz + (size_t)warp*3 + 0);
        float ny = __ldcg(newxyz + (size_t)warp*3 + 1);
        float nz = __ldcg(newxyz + (size_t)warp*3 + 2);
        float ns = fmaf(nz, nz, fmaf(ny, ny, __fmul_rn(nx, nx)));

        float v[16]; int id[16];
#pragma unroll
        for (int t = 0; t < 16; t++) { v[t] = 3.4e38f; id[t] = 0x7fffffff; }

        for (int j = lane; j < NN; j += 32) {
            float x = base[j*3+0], y = base[j*3+1], z = base[j*3+2];
            float dot = fmaf(z, nz, fmaf(y, ny, __fmul_rn(x, nx)));
            float nq  = fmaf(z, z,  fmaf(y, y,  __fmul_rn(x, x)));
            float d   = __fadd_rn(__fsub_rn(ns, __fmul_rn(2.0f, dot)), nq);
            if (d < v[15]) {
                v[15] = d; id[15] = j;
#pragma unroll
                for (int t = 15; t > 0; t--) {
                    if (v[t] < v[t-1] || (v[t] == v[t-1] && id[t] < id[t-1])) {
                        float tv = v[t]; v[t] = v[t-1]; v[t-1] = tv;
                        int   ti = id[t]; id[t] = id[t-1]; id[t-1] = ti;
                    } else break;
                }
            }
        }

#pragma unroll
        for (int t = 0; t < 16; t++) {
            smd[wloc][lane*16 + t] = v[t];
            smi[wloc][lane*16 + t] = id[t];
        }
        __syncwarp();

        int p = 0;
        for (int t = 0; t < 16; t++) {
            float cv = (p < 16) ? smd[wloc][lane*16 + p] : 3.4e38f;
            int   ci = (p < 16) ? smi[wloc][lane*16 + p] : 0x7fffffff;
            float mv = cv; int mi = ci;
#pragma unroll
            for (int off = 16; off; off >>= 1) {
                float ov = __shfl_xor_sync(0xffffffffu, mv, off);
                int   oi = __shfl_xor_sync(0xffffffffu, mi, off);
                if (ov < mv || (ov == mv && oi < mi)) { mv = ov; mi = oi; }
            }
            if (cv == mv && ci == mi) p++;
            if (lane == 0) g_knn[(size_t)warp*16 + t] = b*NN + mi;
            __syncwarp();
        }

        __syncthreads();
        if (tid == 0) {
            while (ld_acquire(&g_kprog[b]) != s0) { }
            __threadfence();
            atomicExch(&g_kprog[b], s0 + 8);
        }
        return;
    }

    if (bid < B_H1) {
        // -------------- q GEMM = gather(points, fps) @ wq (polls prog) -------
        const int idx = bid - B_Q;
        const int n0  = (idx & 3) * 64;
        const int m0  = (idx >> 2) * 128;
        const int b   = m0 >> 10;
        const int s_need = (m0 & 1023) + 128;
        if (tid == 0) { while (ld_acquire(&g_prog[b]) < s_need) { } }
        const int Kd = CIN;
        const int* fps_ptr = g_fps;

        GEMM_MAINLOOP(g_ph, g_pl, fps_ptr, g_wqh, g_wql)

        const int quad = lane >> 2, tq = lane & 3;
#pragma unroll
        for (int mt = 0; mt < 2; mt++) {
            int r0 = m0 + wm*32 + mt*16 + quad;
            int r1 = r0 + 8;
#pragma unroll
            for (int nt = 0; nt < 4; nt++) {
                int col = n0 + wn*32 + nt*8 + tq*2;
                *(float2*)(g_q + (size_t)r0*COUT + col) =
                    make_float2(acc[mt][nt][0], acc[mt][nt][1]);
                *(float2*)(g_q + (size_t)r1*COUT + col) =
                    make_float2(acc[mt][nt][2], acc[mt][nt][3]);
            }
        }
        __syncthreads();
        if (tid == 0) { __threadfence(); atomicAdd(&g_qc[m0 >> 7], 1); }
        return;
    }

    if (bid < B_MLP) {
        // ----------------- h1 pos-enc layer 1 (polls kprog) ------------------
        const int hb = bid - B_H1;
        const int b  = hb >> 7;
        const int s_need = ((hb * 8) & 1023) + 8;
        if (tid == 0) { while (ld_acquire(&g_kprog[b]) < s_need) { } }
        __syncthreads();

        const int col    = (tid & 127) * 2;
        const int rowsel = tid >> 7;
        const float w0a = dw1[col],        w0b = dw1[col+1];
        const float w1a = dw1[COUT+col],   w1b = dw1[COUT+col+1];
        const float w2a = dw1[2*COUT+col], w2b = dw1[2*COUT+col+1];
        const float b0  = db1[col],        b1  = db1[col+1];

        for (int rr = 0; rr < 64; rr++) {
            int r  = hb*128 + rr*2 + rowsel;
            int g  = __ldcg(&g_knn[r]);
            int bs = r >> 4;
            float cx = __ldcg(&xyz[(size_t)g*3+0]) - __ldcg(&newxyz[(size_t)bs*3+0]);
            float cy = __ldcg(&xyz[(size_t)g*3+1]) - __ldcg(&newxyz[(size_t)bs*3+1]);
            float cz = __ldcg(&xyz[(size_t)g*3+2]) - __ldcg(&newxyz[(size_t)bs*3+2]);
            float h0 = b0, h1v = b1;
            h0  = fmaf(cx, w0a, h0);  h0  = fmaf(cy, w1a, h0);  h0  = fmaf(cz, w2a, h0);
            h1v = fmaf(cx, w0b, h1v); h1v = fmaf(cy, w1b, h1v); h1v = fmaf(cz, w2b, h1v);
            h0  = fmaxf(h0, 0.0f);
            h1v = fmaxf(h1v, 0.0f);
            uint32_t h, l;
            split2(h0, h1v, h, l);
            *(uint32_t*)&g_x1h[(size_t)r*COUT + col] = h;
            *(uint32_t*)&g_x1l[(size_t)r*COUT + col] = l;
        }
        __syncthreads();
        if (tid == 0) { __threadfence(); atomicExch(&g_hc[hb], 1); }
        return;
    }

    if (bid < B_BNP) {
        // ---------- skewed-pipeline MLP region: a1 / h2 / att / lw ----------
        const int g    = bid - B_MLP;
        const int r    = g / ROUND_SZ;
        const int slot = g % ROUND_SZ;
        int stage, chunk, s2;
        if (slot < 256)      { stage = 0; chunk = r;     s2 = slot;       }
        else if (slot < 512) { stage = 1; chunk = r - 1; s2 = slot - 256; }
        else if (slot < 768) { stage = 2; chunk = r - 2; s2 = slot - 512; }
        else                 { stage = 3; chunk = r - 3; s2 = slot - 768; }
        if (chunk < 0 || chunk >= NCHUNK) return;   // ghost block

        if (stage == 0) {
            // a1: pos = h1@dw2+db2 (fp32) + fused a1 = q - k_gather + pos
            const int mtile = chunk*64 + (s2 >> 2);
            const int m0 = mtile * 128;
            const int n0 = (s2 & 3) * 64;
            if (tid == 0) {
                while (ld_acquire(&g_hc[mtile]) == 0) { }
                while (ld_acquire(&g_qc[m0 >> 11]) < 4) { }
                while (ld_acquire(&g_kwc[m0 >> 14]) < 128) { }
            }
            gemm_body(tid, m0, n0, COUT, g_x1h, g_x1l, nullptr,
                      g_dw2h, g_dw2l, db2, 0,
                      g_pos, nullptr, nullptr,
                      g_q, g_kall, g_knn, g_a1h, g_a1l);
            __syncthreads();
            if (tid == 0) { __threadfence(); atomicAdd(&g_c1[mtile], 1); }
            return;
        }
        if (stage == 1) {
            // h2 = relu(a1@gw1+gb1) -> x1 (bf16 split)
            const int mtile = chunk*64 + (s2 >> 2);
            const int m0 = mtile * 128;
            const int n0 = (s2 & 3) * 64;
            if (tid == 0) { while (ld_acquire(&g_c1[mtile]) < 4) { } }
            gemm_body(tid, m0, n0, COUT, g_a1h, g_a1l, nullptr,
                      g_gw1h, g_gw1l, gb1, 1,
                      nullptr, g_x1h, g_x1l,
                      nullptr, nullptr, nullptr, nullptr, nullptr);
            __syncthreads();
            if (tid == 0) { __threadfence(); atomicAdd(&g_c2[mtile], 1); }
            return;
        }
        if (stage == 2) {
            // att GEMM + fused softmax/weighted sum -> r0 (bf16 split)
            const int mtile = chunk*64 + (s2 >> 2);
            const int m0 = mtile * 128;
            const int n0 = (s2 & 3) * 64;
            if (tid == 0) {
                while (ld_acquire(&g_c2[mtile]) < 4) { }
                while (ld_acquire(&g_vwc[m0 >> 14]) < 128) { }
            }
            gemm_att_body(tid, m0, n0, COUT, g_x1h, g_x1l,
                          g_gw2h, g_gw2l, gb2, g_knn, g_pos, g_vall,
                          g_r0h, g_r0l);
            __syncthreads();
            if (tid == 0) { __threadfence(); atomicAdd(&g_c3[m0 >> 11], 1); }
            return;
        }
        // stage 3: lw GEMM: res1 = r0@lw + lb (m in BSR rows)
        {
            const int mtile = chunk*4 + (s2 >> 2);
            const int m0 = mtile * 128;
            const int n0 = (s2 & 3) * 64;
            if (tid == 0) { while (ld_acquire(&g_c3[mtile]) < 64) { } }
            gemm_body(tid, m0, n0, COUT, g_r0h, g_r0l, nullptr,
                      g_lwh, g_lwl, lb, 0,
                      g_res1, nullptr, nullptr,
                      nullptr, nullptr, nullptr, nullptr, nullptr);
            __syncthreads();
            if (tid == 0) { __threadfence(); atomicAdd(&g_c4a[mtile], 1); }
            return;
        }
    }

    if (bid < B_BNA) {
        // BN partial sums over 128-row slab
        const int blk = bid - B_BNP;
        if (tid == 0) { while (ld_acquire(&g_c4a[blk]) < 4) { } }
        __syncthreads();
        const int c = tid;
        float s = 0.0f, q = 0.0f;
        for (int r = blk*128; r < blk*128 + 128; r++) {
            float x = g_res1[(size_t)r*COUT + c];
            s += x; q = fmaf(x, x, q);
        }
        g_psum[blk*COUT + c] = s;
        g_psq [blk*COUT + c] = q;
        __syncthreads();
        if (tid == 0) { __threadfence(); atomicAdd(&g_c5, 1); }
        return;
    }

    // BN finalize + apply (each block recomputes scale/shift, applies a slab)
    {
        const int kb = bid - B_BNA;           // 0..15
        if (tid == 0) { while (ld_acquire(&g_c5) < 64) { } }
        __syncthreads();
        extern __shared__ char smraw[];
        float* ssc = (float*)smraw;
        float* ssh = ssc + 256;
        {
            float s = 0.0f, q = 0.0f;
            for (int i = 0; i < 64; i++) {
                s += g_psum[i*COUT + tid];
                q += g_psq [i*COUT + tid];
            }
            float mean = s * (1.0f/(float)BSR);
            float var  = fmaxf(q * (1.0f/(float)BSR) - mean*mean, 0.0f);
            float sc   = bng[tid] * rsqrtf(var + 1e-5f);
            ssc[tid] = sc;
            ssh[tid] = bnb[tid] - mean * sc;
        }
        __syncthreads();
        const int c4i = tid & 63;
        float4 sc4 = ((const float4*)ssc)[c4i];
        float4 sh4 = ((const float4*)ssh)[c4i];
        const float4* in4  = (const float4*)g_res1;
        float4*       out4 = (float4*)res_out;
        size_t base = (size_t)kb * 32768;
        for (int i = 0; i < 128; i++) {
            size_t f = base + (size_t)i*256 + tid;
            float4 x = in4[f];
            float4 o;
            o.x = fmaxf(fmaf(x.x, sc4.x, sh4.x), 0.0f);
            o.y = fmaxf(fmaf(x.y, sc4.y, sh4.y), 0.0f);
            o.z = fmaxf(fmaf(x.z, sc4.z, sh4.z), 0.0f);
            o.w = fmaxf(fmaf(x.w, sc4.w, sh4.w), 0.0f);
            out4[f] = o;
        }
    }
}

// ------------------------------ launch --------------------------------------
extern "C" void kernel_launch(void* const* d_in, const int* in_sizes, int n_in,
                              void* d_out, int out_size)
{
    const float* xyz    = (const float*)d_in[0];
    const float* points = (const float*)d_in[1];
    const float* wq     = (const float*)d_in[2];
    const float* wk     = (const float*)d_in[3];
    const float* wv     = (const float*)d_in[4];
    const float* dw1    = (const float*)d_in[5];
    const float* db1    = (const float*)d_in[6];
    const float* dw2    = (const float*)d_in[7];
    const float* db2    = (const float*)d_in[8];
    const float* gw1    = (const float*)d_in[9];
    const float* gb1    = (const float*)d_in[10];
    const float* gw2    = (const float*)d_in[11];
    const float* gb2    = (const float*)d_in[12];
    const float* lw     = (const float*)d_in[13];
    const float* lb     = (const float*)d_in[14];
    const float* bng    = (const float*)d_in[15];
    const float* bnb    = (const float*)d_in[16];

    float* out     = (float*)d_out;
    float* newxyz  = out;
    float* res_out = out + (size_t)BSR*3;

    static bool attr_set = false;
    if (!attr_set) {
        cudaFuncSetAttribute(uber, cudaFuncAttributeMaxDynamicSharedMemorySize, TG_SMEM);
        attr_set = true;
    }

    // 1: reset progress counters (graph-replay safe)
    reset_prog_kernel<<<16, 256>>>();
    // 2: the entire network, one launch, skew-pipelined per-chunk
    uber<<<UBER_GRID, 256, TG_SMEM>>>(xyz, newxyz, points, wk, wv,
                                      wq, dw2, gw1, gw2, lw, dw1, db1,
                                      db2, gb1, gb2, lb, bng, bnb, res_out);
}